// round 5
// baseline (speedup 1.0000x reference)
#include <cuda_runtime.h>
#include <cuda_bf16.h>
#include <math.h>
#include <stdint.h>

#define NN 20000
#define MPAD 20096          // 157 * 128
#define NE 320000
#define NB 64
#define HID 128
#define DEPTH 4
#define NFREQ 8
#define KFK (NFREQ * HID)   // 1024
#define TWO_PI_F 6.283185307179586f

typedef __nv_bfloat16 bf16;

// ==================== scratch (static device allocations) ====================
__device__ float g_h[MPAD * HID];
__device__ float g_p1[NN * HID];
__device__ float g_p2[NN * HID];
__device__ float g_hconv[NN * HID];
__device__ bf16 g_hhi[MPAD * HID];
__device__ bf16 g_hlo[MPAD * HID];
__device__ bf16 g_Shi[(size_t)MPAD * KFK];
__device__ bf16 g_Slo[(size_t)MPAD * KFK];
__device__ bf16 g_Wfk_hi[DEPTH * HID * KFK];      // [l][n][k]
__device__ bf16 g_Wfk_lo[DEPTH * HID * KFK];
__device__ bf16 g_Wlin_hi[DEPTH * 2 * HID * HID]; // [l][part][n][k]
__device__ bf16 g_Wlin_lo[DEPTH * 2 * HID * HID];
__device__ float g_q1[NN];
__device__ float g_q2[NN];
__device__ float g_logits[NN];
__device__ float g_stats[2 * HID];
__device__ float g_pooled[NB * HID];
__device__ unsigned g_umax;
__device__ float g_sumexp;

// ==================== mma.sync helpers ====================
__device__ __forceinline__ uint32_t smem_to_u32(const void* p) {
    uint32_t a;
    asm("{ .reg .u64 t; cvta.to.shared.u64 t, %1; cvt.u32.u64 %0, t; }" : "=r"(a) : "l"(p));
    return a;
}

#define LDSM4(r, addr) \
    asm volatile("ldmatrix.sync.aligned.m8n8.x4.shared.b16 {%0,%1,%2,%3}, [%4];" \
        : "=r"((r)[0]), "=r"((r)[1]), "=r"((r)[2]), "=r"((r)[3]) : "r"(addr))

#define MMA_BF16(c, a, b0, b1) \
    asm volatile("mma.sync.aligned.m16n8k16.row.col.f32.bf16.bf16.f32 " \
        "{%0,%1,%2,%3}, {%4,%5,%6,%7}, {%8,%9}, {%0,%1,%2,%3};" \
        : "+f"((c)[0]), "+f"((c)[1]), "+f"((c)[2]), "+f"((c)[3]) \
        : "r"((a)[0]), "r"((a)[1]), "r"((a)[2]), "r"((a)[3]), "r"(b0), "r"(b1))

// ==================== tensor-core GEMM ====================
// out[M x 128] = (Ahi+Alo)[M x K] @ (Bhi+Blo)^T (+bias)(+add)
// A row-major [>=M x K] bf16; B [128 x K] bf16 (row n = K contiguous).
// K multiple of 64. Grid: ceil(M/128) blocks x 256 threads.
// 3-term split: Ahi*Bhi + Alo*Bhi + Ahi*Blo.
#define BKP 72                                      // padded k-stride (halves)
#define GEMM_SMEM (4 * 128 * BKP * 2)               // 73728 B

__global__ __launch_bounds__(256) void mma_gemm_kernel(
    const bf16* __restrict__ Ahi, const bf16* __restrict__ Alo,
    const bf16* __restrict__ Bhi, const bf16* __restrict__ Blo,
    const float* __restrict__ bias, const float* __restrict__ add,
    float* __restrict__ out, int M, int K)
{
    extern __shared__ __align__(16) bf16 sm[];
    bf16* sAhi = sm;
    bf16* sAlo = sm + 128 * BKP;
    bf16* sBhi = sm + 2 * 128 * BKP;
    bf16* sBlo = sm + 3 * 128 * BKP;
    uint32_t uAhi = smem_to_u32(sAhi);
    uint32_t uAlo = smem_to_u32(sAlo);
    uint32_t uBhi = smem_to_u32(sBhi);
    uint32_t uBlo = smem_to_u32(sBlo);

    int tid = threadIdx.x, lane = tid & 31, wid = tid >> 5;
    int warp_m = wid & 3;        // 0..3 -> 32 rows each
    int warp_n = wid >> 2;       // 0..1 -> 64 cols each
    int m0 = blockIdx.x * 128;

    float acc[2][8][4];
#pragma unroll
    for (int mt = 0; mt < 2; ++mt)
#pragma unroll
        for (int nt = 0; nt < 8; ++nt)
#pragma unroll
            for (int j = 0; j < 4; ++j) acc[mt][nt][j] = 0.f;

    for (int k0 = 0; k0 < K; k0 += 64) {
        __syncthreads();
        // global -> smem: 4 matrices x 128 rows x 64 halves
#pragma unroll
        for (int it = 0; it < 4; ++it) {
            int idx = tid + it * 256;          // 0..1023
            int row = idx >> 3, seg = idx & 7;
            size_t gA = (size_t)(m0 + row) * K + k0 + seg * 8;
            size_t gB = (size_t)row * K + k0 + seg * 8;
            int so = row * BKP + seg * 8;
            *(uint4*)&sAhi[so] = *(const uint4*)&Ahi[gA];
            *(uint4*)&sAlo[so] = *(const uint4*)&Alo[gA];
            *(uint4*)&sBhi[so] = *(const uint4*)&Bhi[gB];
            *(uint4*)&sBlo[so] = *(const uint4*)&Blo[gB];
        }
        __syncthreads();

#pragma unroll
        for (int ks = 0; ks < 4; ++ks) {
            uint32_t ahi[2][4], alo[2][4];
#pragma unroll
            for (int mt = 0; mt < 2; ++mt) {
                int r = warp_m * 32 + mt * 16 + (lane & 15);
                int c = ks * 16 + ((lane >> 4) << 3);
                uint32_t off = (uint32_t)(r * BKP + c) * 2;
                LDSM4(ahi[mt], uAhi + off);
                LDSM4(alo[mt], uAlo + off);
            }
#pragma unroll
            for (int np = 0; np < 4; ++np) {
                int j = lane >> 3;
                int rn = warp_n * 64 + np * 16 + ((j >> 1) << 3) + (lane & 7);
                int cn = ks * 16 + ((j & 1) << 3);
                uint32_t off = (uint32_t)(rn * BKP + cn) * 2;
                uint32_t bhi[4], blo[4];
                LDSM4(bhi, uBhi + off);
                LDSM4(blo, uBlo + off);
#pragma unroll
                for (int mt = 0; mt < 2; ++mt) {
                    MMA_BF16(acc[mt][2 * np],     ahi[mt], bhi[0], bhi[1]);
                    MMA_BF16(acc[mt][2 * np],     alo[mt], bhi[0], bhi[1]);
                    MMA_BF16(acc[mt][2 * np],     ahi[mt], blo[0], blo[1]);
                    MMA_BF16(acc[mt][2 * np + 1], ahi[mt], bhi[2], bhi[3]);
                    MMA_BF16(acc[mt][2 * np + 1], alo[mt], bhi[2], bhi[3]);
                    MMA_BF16(acc[mt][2 * np + 1], ahi[mt], blo[2], blo[3]);
                }
            }
        }
    }

    // epilogue: each thread owns 2x8 tiles of (2 rows x 2 cols)
#pragma unroll
    for (int mt = 0; mt < 2; ++mt) {
        int r0 = m0 + warp_m * 32 + mt * 16 + (lane >> 2);
        int r1 = r0 + 8;
#pragma unroll
        for (int nt = 0; nt < 8; ++nt) {
            int c = warp_n * 64 + nt * 8 + 2 * (lane & 3);
            float bx = 0.f, by = 0.f;
            if (bias) { float2 bv = *(const float2*)&bias[c]; bx = bv.x; by = bv.y; }
            if (r0 < M) {
                float vx = acc[mt][nt][0] + bx, vy = acc[mt][nt][1] + by;
                if (add) {
                    float2 av = *(const float2*)&add[(size_t)r0 * HID + c];
                    vx += av.x; vy += av.y;
                }
                float2 o; o.x = vx; o.y = vy;
                *(float2*)&out[(size_t)r0 * HID + c] = o;
            }
            if (r1 < M) {
                float vx = acc[mt][nt][2] + bx, vy = acc[mt][nt][3] + by;
                if (add) {
                    float2 av = *(const float2*)&add[(size_t)r1 * HID + c];
                    vx += av.x; vy += av.y;
                }
                float2 o; o.x = vx; o.y = vy;
                *(float2*)&out[(size_t)r1 * HID + c] = o;
            }
        }
    }
}

// ==================== small kernels ====================
__global__ void pool_init_kernel() {
    int i = blockIdx.x * blockDim.x + threadIdx.x;
    int stride = gridDim.x * blockDim.x;
    for (int j = i; j < NB * HID; j += stride) g_pooled[j] = 0.f;
    if (i == 0) { g_umax = 0u; g_sumexp = 0.f; }
}

__global__ void node_embed_kernel(const float* __restrict__ x,
                                  const float* __restrict__ w,
                                  const float* __restrict__ b) {
    int idx = blockIdx.x * blockDim.x + threadIdx.x;
    if (idx >= NN * HID) return;
    int n = idx >> 7, c = idx & 127;
    float v = b[c];
    v += x[n * 4 + 0] * w[0 * HID + c];
    v += x[n * 4 + 1] * w[1 * HID + c];
    v += x[n * 4 + 2] * w[2 * HID + c];
    v += x[n * 4 + 3] * w[3 * HID + c];
    g_h[idx] = v;
    bf16 hi = __float2bfloat16(v);
    g_hhi[idx] = hi;
    g_hlo[idx] = __float2bfloat16(v - __bfloat162float(hi));
}

// fk_w [l][f][i][n] -> g_Wfk [l][n][k=f*128+i] (hi/lo bf16)
__global__ void conv_fkw_kernel(const float* __restrict__ fkw) {
    int idx = blockIdx.x * blockDim.x + threadIdx.x;
    if (idx >= DEPTH * KFK * HID) return;
    int l = idx / (KFK * HID);
    int rem = idx - l * (KFK * HID);
    int k = rem >> 7;
    int n = rem & 127;
    float w = fkw[((size_t)l * KFK + k) * HID + n];
    bf16 hi = __float2bfloat16(w);
    bf16 lo = __float2bfloat16(w - __bfloat162float(hi));
    size_t o = ((size_t)l * HID + n) * KFK + k;
    g_Wfk_hi[o] = hi;
    g_Wfk_lo[o] = lo;
}

// lin_w [l][259][128]: rows 0..127 (dst), 128..255 (src) -> [l][p][n][k]
__global__ void conv_linw_kernel(const float* __restrict__ linw) {
    int idx = blockIdx.x * blockDim.x + threadIdx.x;
    if (idx >= DEPTH * 2 * HID * HID) return;
    int l = idx / (2 * HID * HID);
    int rem = idx - l * (2 * HID * HID);
    int p = rem >> 14;
    int nk = rem & 16383;
    int n = nk >> 7, k = nk & 127;
    float w = linw[((size_t)l * 259 + p * 128 + k) * HID + n];
    bf16 hi = __float2bfloat16(w);
    bf16 lo = __float2bfloat16(w - __bfloat162float(hi));
    size_t o = (((size_t)l * 2 + p) * HID + n) * HID + k;
    g_Wlin_hi[o] = hi;
    g_Wlin_lo[o] = lo;
}

// S[n, f*128+i] = sin+cos(2*pi*(f+1)*h[n,i]) -> bf16 hi/lo
__global__ void fk_s_kernel() {
    int idx = blockIdx.x * blockDim.x + threadIdx.x;
    if (idx >= NN * HID) return;
    int n = idx >> 7, i = idx & 127;
    size_t base = (size_t)n * KFK + i;
    float theta = TWO_PI_F * g_h[idx];
    float s1, c1;
    sincosf(theta, &s1, &c1);
    float s = s1, c = c1;
#pragma unroll
    for (int f = 0; f < NFREQ; ++f) {
        if (f > 0) {
            float s2 = s * c1 + c * s1;
            float c2 = c * c1 - s * s1;
            s = s2; c = c2;
        }
        float v = s + c;
        bf16 hi = __float2bfloat16(v);
        g_Shi[base + f * HID] = hi;
        g_Slo[base + f * HID] = __float2bfloat16(v - __bfloat162float(hi));
    }
}

// ==================== q1/q2 ====================
// NOTE: attw = att_w + l*259 NOT 16B-aligned for l>0 -> scalar loads.
__global__ void q_kernel(const float* __restrict__ h, const float* __restrict__ attw) {
    int gwarp = (blockIdx.x * blockDim.x + threadIdx.x) >> 5;
    int lane = threadIdx.x & 31;
    if (gwarp >= NN) return;
    float4 hv = *(const float4*)&h[(size_t)gwarp * HID + lane * 4];
    int c = lane * 4;
    float a10 = attw[c + 0], a11 = attw[c + 1], a12 = attw[c + 2], a13 = attw[c + 3];
    float a20 = attw[HID + c + 0], a21 = attw[HID + c + 1], a22 = attw[HID + c + 2], a23 = attw[HID + c + 3];
    float s1 = hv.x * a10 + hv.y * a11 + hv.z * a12 + hv.w * a13;
    float s2 = hv.x * a20 + hv.y * a21 + hv.z * a22 + hv.w * a23;
#pragma unroll
    for (int o = 16; o > 0; o >>= 1) {
        s1 += __shfl_xor_sync(0xffffffffu, s1, o);
        s2 += __shfl_xor_sync(0xffffffffu, s2, o);
    }
    if (lane == 0) { g_q1[gwarp] = s1; g_q2[gwarp] = s2; }
}

// ==================== edge conv ====================
__global__ __launch_bounds__(256) void edge_kernel(
    const int* __restrict__ ei, const float* __restrict__ ea,
    const float* __restrict__ linw, const float* __restrict__ linb,
    const float* __restrict__ attw, const float* __restrict__ attb_p, int l)
{
    __shared__ float s_w0[HID], s_w1[HID], s_w2[HID], s_lb[HID];
    __shared__ float s_awe[3];
    __shared__ float s_attb;
    int tid = threadIdx.x;
    if (tid < HID) {
        s_w0[tid] = linw[256 * HID + tid];
        s_w1[tid] = linw[257 * HID + tid];
        s_w2[tid] = linw[258 * HID + tid];
        s_lb[tid] = linb[tid];
    }
    if (tid < 3) s_awe[tid] = attw[256 + tid];
    if (tid == 3) s_attb = attb_p[l];
    __syncthreads();

    int e = blockIdx.x * 8 + (tid >> 5);
    if (e >= NE) return;
    int lane = tid & 31;
    int src = ei[e];
    int dst = ei[NE + e];
    float e0 = ea[e * 3 + 0], e1 = ea[e * 3 + 1], e2 = ea[e * 3 + 2];
    float lg = g_q1[dst] + g_q2[src] + e0 * s_awe[0] + e1 * s_awe[1] + e2 * s_awe[2] + s_attb;
    float alpha = 1.f / (1.f + expf(-lg));
    int c = lane * 4;
    float4 v1 = *(const float4*)&g_p1[(size_t)dst * HID + c];
    float4 v2 = *(const float4*)&g_p2[(size_t)src * HID + c];
    float m0 = alpha * (v1.x + v2.x + e0 * s_w0[c + 0] + e1 * s_w1[c + 0] + e2 * s_w2[c + 0] + s_lb[c + 0]);
    float m1 = alpha * (v1.y + v2.y + e0 * s_w0[c + 1] + e1 * s_w1[c + 1] + e2 * s_w2[c + 1] + s_lb[c + 1]);
    float m2 = alpha * (v1.z + v2.z + e0 * s_w0[c + 2] + e1 * s_w1[c + 2] + e2 * s_w2[c + 2] + s_lb[c + 2]);
    float m3 = alpha * (v1.w + v2.w + e0 * s_w0[c + 3] + e1 * s_w1[c + 3] + e2 * s_w2[c + 3] + s_lb[c + 3]);
    float* outp = &g_hconv[(size_t)dst * HID + c];
    atomicAdd(outp + 0, m0);
    atomicAdd(outp + 1, m1);
    atomicAdd(outp + 2, m2);
    atomicAdd(outp + 3, m3);
}

// ==================== batchnorm ====================
__global__ void bn_stat_kernel(const float* __restrict__ h, int rows_per_block) {
    int c = threadIdx.x;
    int r0 = blockIdx.x * rows_per_block;
    int r1 = min(NN, r0 + rows_per_block);
    float s = 0.f, ss = 0.f;
    for (int r = r0; r < r1; ++r) {
        float v = h[(size_t)r * HID + c];
        s += v; ss += v * v;
    }
    atomicAdd(&g_stats[c], s);
    atomicAdd(&g_stats[HID + c], ss);
}

__global__ void bn_apply_kernel(float* __restrict__ h,
                                const float* __restrict__ g,
                                const float* __restrict__ b) {
    int idx = blockIdx.x * blockDim.x + threadIdx.x;
    if (idx >= NN * HID) return;
    int c = idx & 127;
    const float invN = 1.f / (float)NN;
    float mu = g_stats[c] * invN;
    float var = g_stats[HID + c] * invN - mu * mu;
    float rstd = rsqrtf(var + 1e-5f);
    float v = (h[idx] - mu) * rstd * g[c] + b[c];
    v = fmaxf(v, 0.f);
    h[idx] = v;
    bf16 hi = __float2bfloat16(v);
    g_hhi[idx] = hi;
    g_hlo[idx] = __float2bfloat16(v - __bfloat162float(hi));
}

// ==================== attention pooling ====================
__device__ __forceinline__ unsigned float_key(float f) {
    unsigned u = __float_as_uint(f);
    return (u & 0x80000000u) ? ~u : (u | 0x80000000u);
}

__global__ void pool_logit_kernel(const float* __restrict__ h,
                                  const float* __restrict__ pool_w,
                                  const float* __restrict__ pool_b) {
    int gwarp = (blockIdx.x * blockDim.x + threadIdx.x) >> 5;
    int lane = threadIdx.x & 31;
    if (gwarp >= NN) return;
    float4 hv = *(const float4*)&h[(size_t)gwarp * HID + lane * 4];
    float4 wv = *(const float4*)&pool_w[lane * 4];
    float s = hv.x * wv.x + hv.y * wv.y + hv.z * wv.z + hv.w * wv.w;
#pragma unroll
    for (int o = 16; o > 0; o >>= 1) s += __shfl_xor_sync(0xffffffffu, s, o);
    if (lane == 0) {
        s += pool_b[0];
        g_logits[gwarp] = s;
        atomicMax(&g_umax, float_key(s));
    }
}

__global__ void pool_sumexp_kernel() {
    unsigned k = g_umax;
    float maxv = (k & 0x80000000u) ? __uint_as_float(k ^ 0x80000000u)
                                   : __uint_as_float(~k);
    int i = blockIdx.x * blockDim.x + threadIdx.x;
    int stride = gridDim.x * blockDim.x;
    float local = 0.f;
    for (; i < NN; i += stride) local += expf(g_logits[i] - maxv);
#pragma unroll
    for (int o = 16; o > 0; o >>= 1) local += __shfl_xor_sync(0xffffffffu, local, o);
    __shared__ float ws[8];
    int lane = threadIdx.x & 31, wid = threadIdx.x >> 5;
    if (lane == 0) ws[wid] = local;
    __syncthreads();
    if (wid == 0) {
        float v = (lane < (blockDim.x >> 5)) ? ws[lane] : 0.f;
#pragma unroll
        for (int o = 16; o > 0; o >>= 1) v += __shfl_xor_sync(0xffffffffu, v, o);
        if (lane == 0) atomicAdd(&g_sumexp, v);
    }
}

__global__ void pool_scatter_kernel(const float* __restrict__ h,
                                    const int* __restrict__ batch) {
    int gwarp = (blockIdx.x * blockDim.x + threadIdx.x) >> 5;
    int lane = threadIdx.x & 31;
    if (gwarp >= NN) return;
    unsigned k = g_umax;
    float maxv = (k & 0x80000000u) ? __uint_as_float(k ^ 0x80000000u)
                                   : __uint_as_float(~k);
    float w = expf(g_logits[gwarp] - maxv) / g_sumexp;
    int b = batch[gwarp];
    int c = lane * 4;
    float4 hv = *(const float4*)&h[(size_t)gwarp * HID + c];
    float* outp = &g_pooled[b * HID + c];
    atomicAdd(outp + 0, w * hv.x);
    atomicAdd(outp + 1, w * hv.y);
    atomicAdd(outp + 2, w * hv.z);
    atomicAdd(outp + 3, w * hv.w);
}

// ==================== heads ====================
__global__ __launch_bounds__(128) void head_kernel(
    const float* __restrict__ sg_table, const int* __restrict__ sgidx,
    const float* __restrict__ hw1, const float* __restrict__ hb1,
    const float* __restrict__ w2e, const float* __restrict__ b2e,
    const float* __restrict__ w2s, const float* __restrict__ b2s,
    const float* __restrict__ w2c, const float* __restrict__ b2c,
    const float* __restrict__ w2m, const float* __restrict__ b2m,
    float* __restrict__ out)
{
    int b = blockIdx.x;
    int t = threadIdx.x;
    __shared__ float comb[2 * HID];
    __shared__ float z[HID];
    comb[t] = g_pooled[b * HID + t];
    comb[HID + t] = sg_table[sgidx[b] * HID + t];
    __syncthreads();

    const float* w2arr[4] = { w2e, w2s, w2c, w2m };
    const float* b2arr[4] = { b2e, b2s, b2c, b2m };
    const int od[4] = { 1, 3, 7, 3 };
    const int off[4] = { 0, NB * 1, NB * 4, NB * 11 };

    for (int i = 0; i < 4; ++i) {
        float accz = hb1[i * HID + t];
        const float* W = hw1 + (size_t)i * 2 * HID * HID;
#pragma unroll 8
        for (int j = 0; j < 2 * HID; ++j) accz += comb[j] * W[j * HID + t];
        z[t] = fmaxf(accz, 0.f);
        __syncthreads();
        if (t < od[i]) {
            const float* w2 = w2arr[i];
            float acc = b2arr[i][t];
            for (int j = 0; j < HID; ++j) acc += z[j] * w2[j * od[i] + t];
            out[off[i] + b * od[i] + t] = acc;
        }
        __syncthreads();
    }
}

// ==================== host ====================
extern "C" void kernel_launch(void* const* d_in, const int* in_sizes, int n_in,
                              void* d_out, int out_size) {
    const float* x        = (const float*)d_in[0];
    const int*   ei       = (const int*)d_in[1];
    const float* ea       = (const float*)d_in[2];
    const int*   batch    = (const int*)d_in[3];
    const int*   sgidx    = (const int*)d_in[4];
    const float* node_w   = (const float*)d_in[5];
    const float* node_b   = (const float*)d_in[6];
    const float* sg_table = (const float*)d_in[7];
    const float* lin_w    = (const float*)d_in[8];
    const float* lin_b    = (const float*)d_in[9];
    const float* att_w    = (const float*)d_in[10];
    const float* att_b    = (const float*)d_in[11];
    const float* fk_w     = (const float*)d_in[12];
    const float* fk_b     = (const float*)d_in[13];
    const float* bn_g     = (const float*)d_in[14];
    const float* bn_b     = (const float*)d_in[15];
    const float* pool_w   = (const float*)d_in[16];
    const float* pool_b   = (const float*)d_in[17];
    const float* head_w1  = (const float*)d_in[18];
    const float* head_b1  = (const float*)d_in[19];
    const float* w2e = (const float*)d_in[20];
    const float* b2e = (const float*)d_in[21];
    const float* w2s = (const float*)d_in[22];
    const float* b2s = (const float*)d_in[23];
    const float* w2c = (const float*)d_in[24];
    const float* b2c = (const float*)d_in[25];
    const float* w2m = (const float*)d_in[26];
    const float* b2m = (const float*)d_in[27];
    float* out = (float*)d_out;

    cudaFuncSetAttribute(mma_gemm_kernel, cudaFuncAttributeMaxDynamicSharedMemorySize,
                         GEMM_SMEM);

    float *p_h, *p_p1, *p_p2, *p_hconv, *p_stats;
    bf16 *p_hhi, *p_hlo, *p_Shi, *p_Slo, *p_Wfk_hi, *p_Wfk_lo, *p_Wlin_hi, *p_Wlin_lo;
    cudaGetSymbolAddress((void**)&p_h, g_h);
    cudaGetSymbolAddress((void**)&p_p1, g_p1);
    cudaGetSymbolAddress((void**)&p_p2, g_p2);
    cudaGetSymbolAddress((void**)&p_hconv, g_hconv);
    cudaGetSymbolAddress((void**)&p_stats, g_stats);
    cudaGetSymbolAddress((void**)&p_hhi, g_hhi);
    cudaGetSymbolAddress((void**)&p_hlo, g_hlo);
    cudaGetSymbolAddress((void**)&p_Shi, g_Shi);
    cudaGetSymbolAddress((void**)&p_Slo, g_Slo);
    cudaGetSymbolAddress((void**)&p_Wfk_hi, g_Wfk_hi);
    cudaGetSymbolAddress((void**)&p_Wfk_lo, g_Wfk_lo);
    cudaGetSymbolAddress((void**)&p_Wlin_hi, g_Wlin_hi);
    cudaGetSymbolAddress((void**)&p_Wlin_lo, g_Wlin_lo);

    const int elem_blocks = (NN * HID + 255) / 256;   // 10000
    const int warp_blocks = (NN + 7) / 8;             // 2500
    const int edge_blocks = (NE + 7) / 8;             // 40000
    const int tile_blocks = (NN + 127) / 128;         // 157

    // weight conversions (constant per call, deterministic)
    conv_fkw_kernel<<<(DEPTH * KFK * HID + 255) / 256, 256>>>(fk_w);
    conv_linw_kernel<<<(DEPTH * 2 * HID * HID + 255) / 256, 256>>>(lin_w);

    node_embed_kernel<<<elem_blocks, 256>>>(x, node_w, node_b);

    for (int l = 0; l < DEPTH; ++l) {
        const float* lw = lin_w + (size_t)l * 259 * HID;
        const float* lb = lin_b + (size_t)l * HID;
        const float* aw = att_w + (size_t)l * 259;
        const bf16* Wdst_hi = p_Wlin_hi + ((size_t)l * 2 + 0) * HID * HID;
        const bf16* Wdst_lo = p_Wlin_lo + ((size_t)l * 2 + 0) * HID * HID;
        const bf16* Wsrc_hi = p_Wlin_hi + ((size_t)l * 2 + 1) * HID * HID;
        const bf16* Wsrc_lo = p_Wlin_lo + ((size_t)l * 2 + 1) * HID * HID;

        mma_gemm_kernel<<<tile_blocks, 256, GEMM_SMEM>>>(
            p_hhi, p_hlo, Wdst_hi, Wdst_lo, nullptr, nullptr, p_p1, NN, HID);
        mma_gemm_kernel<<<tile_blocks, 256, GEMM_SMEM>>>(
            p_hhi, p_hlo, Wsrc_hi, Wsrc_lo, nullptr, nullptr, p_p2, NN, HID);
        q_kernel<<<warp_blocks, 256>>>(p_h, aw);
        fk_s_kernel<<<elem_blocks, 256>>>();
        cudaMemsetAsync(p_hconv, 0, (size_t)NN * HID * sizeof(float), 0);
        edge_kernel<<<edge_blocks, 256>>>(ei, ea, lw, lb, aw, att_b, l);
        mma_gemm_kernel<<<tile_blocks, 256, GEMM_SMEM>>>(
            p_Shi, p_Slo, p_Wfk_hi + (size_t)l * HID * KFK, p_Wfk_lo + (size_t)l * HID * KFK,
            fk_b + (size_t)l * HID, p_hconv, p_h, NN, KFK);
        cudaMemsetAsync(p_stats, 0, 2 * HID * sizeof(float), 0);
        bn_stat_kernel<<<160, 128>>>(p_h, (NN + 159) / 160);
        bn_apply_kernel<<<elem_blocks, 256>>>(p_h, bn_g + (size_t)l * HID, bn_b + (size_t)l * HID);
    }

    pool_init_kernel<<<32, 256>>>();
    pool_logit_kernel<<<warp_blocks, 256>>>(p_h, pool_w, pool_b);
    pool_sumexp_kernel<<<80, 256>>>();
    pool_scatter_kernel<<<warp_blocks, 256>>>(p_h, batch);

    head_kernel<<<NB, 128>>>(sg_table, sgidx, head_w1, head_b1,
                             w2e, b2e, w2s, b2s, w2c, b2c, w2m, b2m, out);
}

// round 7
// speedup vs baseline: 1.6667x; 1.6667x over previous
#include <cuda_runtime.h>
#include <cuda_bf16.h>
#include <math.h>
#include <stdint.h>

#define NN 20000
#define MPAD 20096          // 157 * 128
#define NE 320000
#define NB 64
#define HID 128
#define DEPTH 4
#define NFREQ 8
#define KFK (NFREQ * HID)   // 1024
#define TWO_PI_F 6.283185307179586f

typedef __nv_bfloat16 bf16;

// ==================== scratch (static device allocations) ====================
__device__ float g_h[MPAD * HID];
__device__ float g_p1[NN * HID];
__device__ float g_p2[NN * HID];
__device__ float g_hconv[NN * HID];
__device__ bf16 g_hhi[MPAD * HID];
__device__ bf16 g_hlo[MPAD * HID];
__device__ bf16 g_Shi[(size_t)MPAD * KFK];
__device__ bf16 g_Slo[(size_t)MPAD * KFK];
__device__ bf16 g_Wfk_hi[DEPTH * HID * KFK];      // [l][n][k]
__device__ bf16 g_Wfk_lo[DEPTH * HID * KFK];
__device__ bf16 g_Wlin_hi[DEPTH * 2 * HID * HID]; // [l][part][n][k]
__device__ bf16 g_Wlin_lo[DEPTH * 2 * HID * HID];
__device__ float g_q1[NN];
__device__ float g_q2[NN];
__device__ float g_logits[NN];
__device__ float g_stats[2 * HID];
__device__ float g_pooled[NB * HID];
__device__ unsigned g_umax;
__device__ float g_sumexp;

// ==================== mma.sync / cp.async helpers ====================
__device__ __forceinline__ uint32_t smem_to_u32(const void* p) {
    uint32_t a;
    asm("{ .reg .u64 t; cvta.to.shared.u64 t, %1; cvt.u32.u64 %0, t; }" : "=r"(a) : "l"(p));
    return a;
}

#define LDSM4(r, addr) \
    asm volatile("ldmatrix.sync.aligned.m8n8.x4.shared.b16 {%0,%1,%2,%3}, [%4];" \
        : "=r"((r)[0]), "=r"((r)[1]), "=r"((r)[2]), "=r"((r)[3]) : "r"(addr))

#define MMA_BF16(c, a, b0, b1) \
    asm volatile("mma.sync.aligned.m16n8k16.row.col.f32.bf16.bf16.f32 " \
        "{%0,%1,%2,%3}, {%4,%5,%6,%7}, {%8,%9}, {%0,%1,%2,%3};" \
        : "+f"((c)[0]), "+f"((c)[1]), "+f"((c)[2]), "+f"((c)[3]) \
        : "r"((a)[0]), "r"((a)[1]), "r"((a)[2]), "r"((a)[3]), "r"(b0), "r"(b1))

__device__ __forceinline__ void cp16(uint32_t dst, const void* src) {
    asm volatile("cp.async.cg.shared.global [%0], [%1], 16;" :: "r"(dst), "l"(src));
}
#define CP_COMMIT() asm volatile("cp.async.commit_group;" ::: "memory")
#define CP_WAIT(n)  asm volatile("cp.async.wait_group %0;" :: "n"(n) : "memory")

// ==================== tensor-core GEMM (2-stage cp.async pipeline) ====================
// out[M x 128] = (Ahi+Alo)[M x K] @ (Bhi+Blo)^T (+bias)(+add)
// A row-major [>=M x K] bf16; B [128 x K] bf16. K multiple of 64.
// 3-term split: Ahi*Bhi + Alo*Bhi + Ahi*Blo.
#define BKP 72                                  // padded k-stride (halves); 144B rows (16B-aligned)
#define MAT_BYTES (128 * BKP * 2)               // 18432
#define STAGE_BYTES (4 * MAT_BYTES)             // 73728
#define GEMM_SMEM (2 * STAGE_BYTES)             // 147456

__global__ __launch_bounds__(256) void mma_gemm_kernel(
    const bf16* __restrict__ Ahi, const bf16* __restrict__ Alo,
    const bf16* __restrict__ Bhi, const bf16* __restrict__ Blo,
    const float* __restrict__ bias, const float* __restrict__ add,
    float* __restrict__ out, int M, int K)
{
    extern __shared__ __align__(16) char sm[];
    uint32_t smem_base = smem_to_u32(sm);
    int tid = threadIdx.x, lane = tid & 31, wid = tid >> 5;
    int warp_m = wid & 3;        // 4 warps over M (32 rows each)
    int warp_n = wid >> 2;       // 2 warps over N (64 cols each)
    int m0 = blockIdx.x * 128;

    // per-thread copy mapping: 16 transfers of 16B per stage
    // idx = tid + it*256 ; mat = idx>>10 ; row = (idx&1023)>>3 ; seg = idx&7
    const bf16* gsrc[4] = { Ahi, Alo, Bhi, Blo };

    float acc[2][8][4];
#pragma unroll
    for (int mt = 0; mt < 2; ++mt)
#pragma unroll
        for (int nt = 0; nt < 8; ++nt)
#pragma unroll
            for (int j = 0; j < 4; ++j) acc[mt][nt][j] = 0.f;

    int nchunks = K >> 6;

    // ---- stage loader (issues 16 cp.async, no commit) ----
    auto load_stage = [&](int stage, int k0) {
        uint32_t sbase = smem_base + stage * STAGE_BYTES;
#pragma unroll
        for (int it = 0; it < 16; ++it) {
            int idx = tid + it * 256;
            int mat = idx >> 10;
            int rem = idx & 1023;
            int row = rem >> 3, seg = rem & 7;
            int grow = (mat < 2) ? (m0 + row) : row;
            const bf16* src = gsrc[mat] + (size_t)grow * K + k0 + seg * 8;
            uint32_t dst = sbase + mat * MAT_BYTES + (uint32_t)(row * BKP + seg * 8) * 2;
            cp16(dst, src);
        }
    };

    load_stage(0, 0);
    CP_COMMIT();

    for (int c = 0; c < nchunks; ++c) {
        if (c + 1 < nchunks) {
            load_stage((c + 1) & 1, (c + 1) << 6);
            CP_COMMIT();
            CP_WAIT(1);
        } else {
            CP_WAIT(0);
        }
        __syncthreads();

        uint32_t sb = smem_base + (c & 1) * STAGE_BYTES;
        uint32_t uAhi = sb;
        uint32_t uAlo = sb + MAT_BYTES;
        uint32_t uBhi = sb + 2 * MAT_BYTES;
        uint32_t uBlo = sb + 3 * MAT_BYTES;

#pragma unroll
        for (int ks = 0; ks < 4; ++ks) {
            uint32_t ahi[2][4], alo[2][4];
#pragma unroll
            for (int mt = 0; mt < 2; ++mt) {
                int r = warp_m * 32 + mt * 16 + (lane & 15);
                int cc = ks * 16 + ((lane >> 4) << 3);
                uint32_t off = (uint32_t)(r * BKP + cc) * 2;
                LDSM4(ahi[mt], uAhi + off);
                LDSM4(alo[mt], uAlo + off);
            }
#pragma unroll
            for (int np = 0; np < 4; ++np) {
                int j = lane >> 3;
                int rn = warp_n * 64 + np * 16 + ((j >> 1) << 3) + (lane & 7);
                int cn = ks * 16 + ((j & 1) << 3);
                uint32_t off = (uint32_t)(rn * BKP + cn) * 2;
                uint32_t bhi[4], blo[4];
                LDSM4(bhi, uBhi + off);
                LDSM4(blo, uBlo + off);
#pragma unroll
                for (int mt = 0; mt < 2; ++mt) {
                    MMA_BF16(acc[mt][2 * np],     ahi[mt], bhi[0], bhi[1]);
                    MMA_BF16(acc[mt][2 * np],     alo[mt], bhi[0], bhi[1]);
                    MMA_BF16(acc[mt][2 * np],     ahi[mt], blo[0], blo[1]);
                    MMA_BF16(acc[mt][2 * np + 1], ahi[mt], bhi[2], bhi[3]);
                    MMA_BF16(acc[mt][2 * np + 1], alo[mt], bhi[2], bhi[3]);
                    MMA_BF16(acc[mt][2 * np + 1], ahi[mt], blo[2], blo[3]);
                }
            }
        }
        __syncthreads();
    }

    // epilogue: each thread owns 2x8 tiles of (2 rows x 2 cols)
#pragma unroll
    for (int mt = 0; mt < 2; ++mt) {
        int r0 = m0 + warp_m * 32 + mt * 16 + (lane >> 2);
        int r1 = r0 + 8;
#pragma unroll
        for (int nt = 0; nt < 8; ++nt) {
            int c = warp_n * 64 + nt * 8 + 2 * (lane & 3);
            float bx = 0.f, by = 0.f;
            if (bias) { float2 bv = *(const float2*)&bias[c]; bx = bv.x; by = bv.y; }
            if (r0 < M) {
                float vx = acc[mt][nt][0] + bx, vy = acc[mt][nt][1] + by;
                if (add) {
                    float2 av = *(const float2*)&add[(size_t)r0 * HID + c];
                    vx += av.x; vy += av.y;
                }
                float2 o; o.x = vx; o.y = vy;
                *(float2*)&out[(size_t)r0 * HID + c] = o;
            }
            if (r1 < M) {
                float vx = acc[mt][nt][2] + bx, vy = acc[mt][nt][3] + by;
                if (add) {
                    float2 av = *(const float2*)&add[(size_t)r1 * HID + c];
                    vx += av.x; vy += av.y;
                }
                float2 o; o.x = vx; o.y = vy;
                *(float2*)&out[(size_t)r1 * HID + c] = o;
            }
        }
    }
}

// ==================== small kernels ====================
__global__ void pool_init_kernel() {
    int i = blockIdx.x * blockDim.x + threadIdx.x;
    int stride = gridDim.x * blockDim.x;
    for (int j = i; j < NB * HID; j += stride) g_pooled[j] = 0.f;
    if (i == 0) { g_umax = 0u; g_sumexp = 0.f; }
}

__global__ void node_embed_kernel(const float* __restrict__ x,
                                  const float* __restrict__ w,
                                  const float* __restrict__ b) {
    int idx = blockIdx.x * blockDim.x + threadIdx.x;
    if (idx >= NN * HID) return;
    int n = idx >> 7, c = idx & 127;
    float v = b[c];
    v += x[n * 4 + 0] * w[0 * HID + c];
    v += x[n * 4 + 1] * w[1 * HID + c];
    v += x[n * 4 + 2] * w[2 * HID + c];
    v += x[n * 4 + 3] * w[3 * HID + c];
    g_h[idx] = v;
    bf16 hi = __float2bfloat16(v);
    g_hhi[idx] = hi;
    g_hlo[idx] = __float2bfloat16(v - __bfloat162float(hi));
}

// fk_w [l][f][i][n] -> g_Wfk [l][n][k=f*128+i] (hi/lo bf16)
__global__ void conv_fkw_kernel(const float* __restrict__ fkw) {
    int idx = blockIdx.x * blockDim.x + threadIdx.x;
    if (idx >= DEPTH * KFK * HID) return;
    int l = idx / (KFK * HID);
    int rem = idx - l * (KFK * HID);
    int k = rem >> 7;
    int n = rem & 127;
    float w = fkw[((size_t)l * KFK + k) * HID + n];
    bf16 hi = __float2bfloat16(w);
    bf16 lo = __float2bfloat16(w - __bfloat162float(hi));
    size_t o = ((size_t)l * HID + n) * KFK + k;
    g_Wfk_hi[o] = hi;
    g_Wfk_lo[o] = lo;
}

// lin_w [l][259][128]: rows 0..127 (dst), 128..255 (src) -> [l][p][n][k]
__global__ void conv_linw_kernel(const float* __restrict__ linw) {
    int idx = blockIdx.x * blockDim.x + threadIdx.x;
    if (idx >= DEPTH * 2 * HID * HID) return;
    int l = idx / (2 * HID * HID);
    int rem = idx - l * (2 * HID * HID);
    int p = rem >> 14;
    int nk = rem & 16383;
    int n = nk >> 7, k = nk & 127;
    float w = linw[((size_t)l * 259 + p * 128 + k) * HID + n];
    bf16 hi = __float2bfloat16(w);
    bf16 lo = __float2bfloat16(w - __bfloat162float(hi));
    size_t o = (((size_t)l * 2 + p) * HID + n) * HID + k;
    g_Wlin_hi[o] = hi;
    g_Wlin_lo[o] = lo;
}

// S[n, f*128+i] = sin+cos(2*pi*(f+1)*h[n,i]) -> bf16 hi/lo
__global__ void fk_s_kernel() {
    int idx = blockIdx.x * blockDim.x + threadIdx.x;
    if (idx >= NN * HID) return;
    int n = idx >> 7, i = idx & 127;
    size_t base = (size_t)n * KFK + i;
    float theta = TWO_PI_F * g_h[idx];
    float s1, c1;
    sincosf(theta, &s1, &c1);
    float s = s1, c = c1;
#pragma unroll
    for (int f = 0; f < NFREQ; ++f) {
        if (f > 0) {
            float s2 = s * c1 + c * s1;
            float c2 = c * c1 - s * s1;
            s = s2; c = c2;
        }
        float v = s + c;
        bf16 hi = __float2bfloat16(v);
        g_Shi[base + f * HID] = hi;
        g_Slo[base + f * HID] = __float2bfloat16(v - __bfloat162float(hi));
    }
}

// ==================== q1/q2 ====================
// NOTE: attw = att_w + l*259 NOT 16B-aligned for l>0 -> scalar loads.
__global__ void q_kernel(const float* __restrict__ h, const float* __restrict__ attw) {
    int gwarp = (blockIdx.x * blockDim.x + threadIdx.x) >> 5;
    int lane = threadIdx.x & 31;
    if (gwarp >= NN) return;
    float4 hv = *(const float4*)&h[(size_t)gwarp * HID + lane * 4];
    int c = lane * 4;
    float a10 = attw[c + 0], a11 = attw[c + 1], a12 = attw[c + 2], a13 = attw[c + 3];
    float a20 = attw[HID + c + 0], a21 = attw[HID + c + 1], a22 = attw[HID + c + 2], a23 = attw[HID + c + 3];
    float s1 = hv.x * a10 + hv.y * a11 + hv.z * a12 + hv.w * a13;
    float s2 = hv.x * a20 + hv.y * a21 + hv.z * a22 + hv.w * a23;
#pragma unroll
    for (int o = 16; o > 0; o >>= 1) {
        s1 += __shfl_xor_sync(0xffffffffu, s1, o);
        s2 += __shfl_xor_sync(0xffffffffu, s2, o);
    }
    if (lane == 0) { g_q1[gwarp] = s1; g_q2[gwarp] = s2; }
}

// ==================== edge conv ====================
__global__ __launch_bounds__(256) void edge_kernel(
    const int* __restrict__ ei, const float* __restrict__ ea,
    const float* __restrict__ linw, const float* __restrict__ linb,
    const float* __restrict__ attw, const float* __restrict__ attb_p, int l)
{
    __shared__ float s_w0[HID], s_w1[HID], s_w2[HID], s_lb[HID];
    __shared__ float s_awe[3];
    __shared__ float s_attb;
    int tid = threadIdx.x;
    if (tid < HID) {
        s_w0[tid] = linw[256 * HID + tid];
        s_w1[tid] = linw[257 * HID + tid];
        s_w2[tid] = linw[258 * HID + tid];
        s_lb[tid] = linb[tid];
    }
    if (tid < 3) s_awe[tid] = attw[256 + tid];
    if (tid == 3) s_attb = attb_p[l];
    __syncthreads();

    int e = blockIdx.x * 8 + (tid >> 5);
    if (e >= NE) return;
    int lane = tid & 31;
    int src = ei[e];
    int dst = ei[NE + e];
    float e0 = ea[e * 3 + 0], e1 = ea[e * 3 + 1], e2 = ea[e * 3 + 2];
    float lg = g_q1[dst] + g_q2[src] + e0 * s_awe[0] + e1 * s_awe[1] + e2 * s_awe[2] + s_attb;
    float alpha = 1.f / (1.f + expf(-lg));
    int c = lane * 4;
    float4 v1 = *(const float4*)&g_p1[(size_t)dst * HID + c];
    float4 v2 = *(const float4*)&g_p2[(size_t)src * HID + c];
    float m0 = alpha * (v1.x + v2.x + e0 * s_w0[c + 0] + e1 * s_w1[c + 0] + e2 * s_w2[c + 0] + s_lb[c + 0]);
    float m1 = alpha * (v1.y + v2.y + e0 * s_w0[c + 1] + e1 * s_w1[c + 1] + e2 * s_w2[c + 1] + s_lb[c + 1]);
    float m2 = alpha * (v1.z + v2.z + e0 * s_w0[c + 2] + e1 * s_w1[c + 2] + e2 * s_w2[c + 2] + s_lb[c + 2]);
    float m3 = alpha * (v1.w + v2.w + e0 * s_w0[c + 3] + e1 * s_w1[c + 3] + e2 * s_w2[c + 3] + s_lb[c + 3]);
    float* outp = &g_hconv[(size_t)dst * HID + c];
    atomicAdd(outp + 0, m0);
    atomicAdd(outp + 1, m1);
    atomicAdd(outp + 2, m2);
    atomicAdd(outp + 3, m3);
}

// ==================== batchnorm ====================
__global__ void bn_stat_kernel(const float* __restrict__ h, int rows_per_block) {
    int c = threadIdx.x;
    int r0 = blockIdx.x * rows_per_block;
    int r1 = min(NN, r0 + rows_per_block);
    float s = 0.f, ss = 0.f;
    for (int r = r0; r < r1; ++r) {
        float v = h[(size_t)r * HID + c];
        s += v; ss += v * v;
    }
    atomicAdd(&g_stats[c], s);
    atomicAdd(&g_stats[HID + c], ss);
}

__global__ void bn_apply_kernel(float* __restrict__ h,
                                const float* __restrict__ g,
                                const float* __restrict__ b) {
    int idx = blockIdx.x * blockDim.x + threadIdx.x;
    if (idx >= NN * HID) return;
    int c = idx & 127;
    const float invN = 1.f / (float)NN;
    float mu = g_stats[c] * invN;
    float var = g_stats[HID + c] * invN - mu * mu;
    float rstd = rsqrtf(var + 1e-5f);
    float v = (h[idx] - mu) * rstd * g[c] + b[c];
    v = fmaxf(v, 0.f);
    h[idx] = v;
    bf16 hi = __float2bfloat16(v);
    g_hhi[idx] = hi;
    g_hlo[idx] = __float2bfloat16(v - __bfloat162float(hi));
}

// ==================== attention pooling ====================
__device__ __forceinline__ unsigned float_key(float f) {
    unsigned u = __float_as_uint(f);
    return (u & 0x80000000u) ? ~u : (u | 0x80000000u);
}

__global__ void pool_logit_kernel(const float* __restrict__ h,
                                  const float* __restrict__ pool_w,
                                  const float* __restrict__ pool_b) {
    int gwarp = (blockIdx.x * blockDim.x + threadIdx.x) >> 5;
    int lane = threadIdx.x & 31;
    if (gwarp >= NN) return;
    float4 hv = *(const float4*)&h[(size_t)gwarp * HID + lane * 4];
    float4 wv = *(const float4*)&pool_w[lane * 4];
    float s = hv.x * wv.x + hv.y * wv.y + hv.z * wv.z + hv.w * wv.w;
#pragma unroll
    for (int o = 16; o > 0; o >>= 1) s += __shfl_xor_sync(0xffffffffu, s, o);
    if (lane == 0) {
        s += pool_b[0];
        g_logits[gwarp] = s;
        atomicMax(&g_umax, float_key(s));
    }
}

__global__ void pool_sumexp_kernel() {
    unsigned k = g_umax;
    float maxv = (k & 0x80000000u) ? __uint_as_float(k ^ 0x80000000u)
                                   : __uint_as_float(~k);
    int i = blockIdx.x * blockDim.x + threadIdx.x;
    int stride = gridDim.x * blockDim.x;
    float local = 0.f;
    for (; i < NN; i += stride) local += expf(g_logits[i] - maxv);
#pragma unroll
    for (int o = 16; o > 0; o >>= 1) local += __shfl_xor_sync(0xffffffffu, local, o);
    __shared__ float ws[8];
    int lane = threadIdx.x & 31, wid = threadIdx.x >> 5;
    if (lane == 0) ws[wid] = local;
    __syncthreads();
    if (wid == 0) {
        float v = (lane < (blockDim.x >> 5)) ? ws[lane] : 0.f;
#pragma unroll
        for (int o = 16; o > 0; o >>= 1) v += __shfl_xor_sync(0xffffffffu, v, o);
        if (lane == 0) atomicAdd(&g_sumexp, v);
    }
}

__global__ void pool_scatter_kernel(const float* __restrict__ h,
                                    const int* __restrict__ batch) {
    int gwarp = (blockIdx.x * blockDim.x + threadIdx.x) >> 5;
    int lane = threadIdx.x & 31;
    if (gwarp >= NN) return;
    unsigned k = g_umax;
    float maxv = (k & 0x80000000u) ? __uint_as_float(k ^ 0x80000000u)
                                   : __uint_as_float(~k);
    float w = expf(g_logits[gwarp] - maxv) / g_sumexp;
    int b = batch[gwarp];
    int c = lane * 4;
    float4 hv = *(const float4*)&h[(size_t)gwarp * HID + c];
    float* outp = &g_pooled[b * HID + c];
    atomicAdd(outp + 0, w * hv.x);
    atomicAdd(outp + 1, w * hv.y);
    atomicAdd(outp + 2, w * hv.z);
    atomicAdd(outp + 3, w * hv.w);
}

// ==================== heads ====================
__global__ __launch_bounds__(128) void head_kernel(
    const float* __restrict__ sg_table, const int* __restrict__ sgidx,
    const float* __restrict__ hw1, const float* __restrict__ hb1,
    const float* __restrict__ w2e, const float* __restrict__ b2e,
    const float* __restrict__ w2s, const float* __restrict__ b2s,
    const float* __restrict__ w2c, const float* __restrict__ b2c,
    const float* __restrict__ w2m, const float* __restrict__ b2m,
    float* __restrict__ out)
{
    int b = blockIdx.x;
    int t = threadIdx.x;
    __shared__ float comb[2 * HID];
    __shared__ float z[HID];
    comb[t] = g_pooled[b * HID + t];
    comb[HID + t] = sg_table[sgidx[b] * HID + t];
    __syncthreads();

    const float* w2arr[4] = { w2e, w2s, w2c, w2m };
    const float* b2arr[4] = { b2e, b2s, b2c, b2m };
    const int od[4] = { 1, 3, 7, 3 };
    const int off[4] = { 0, NB * 1, NB * 4, NB * 11 };

    for (int i = 0; i < 4; ++i) {
        float accz = hb1[i * HID + t];
        const float* W = hw1 + (size_t)i * 2 * HID * HID;
#pragma unroll 8
        for (int j = 0; j < 2 * HID; ++j) accz += comb[j] * W[j * HID + t];
        z[t] = fmaxf(accz, 0.f);
        __syncthreads();
        if (t < od[i]) {
            const float* w2 = w2arr[i];
            float acc = b2arr[i][t];
            for (int j = 0; j < HID; ++j) acc += z[j] * w2[j * od[i] + t];
            out[off[i] + b * od[i] + t] = acc;
        }
        __syncthreads();
    }
}

// ==================== host ====================
extern "C" void kernel_launch(void* const* d_in, const int* in_sizes, int n_in,
                              void* d_out, int out_size) {
    const float* x        = (const float*)d_in[0];
    const int*   ei       = (const int*)d_in[1];
    const float* ea       = (const float*)d_in[2];
    const int*   batch    = (const int*)d_in[3];
    const int*   sgidx    = (const int*)d_in[4];
    const float* node_w   = (const float*)d_in[5];
    const float* node_b   = (const float*)d_in[6];
    const float* sg_table = (const float*)d_in[7];
    const float* lin_w    = (const float*)d_in[8];
    const float* lin_b    = (const float*)d_in[9];
    const float* att_w    = (const float*)d_in[10];
    const float* att_b    = (const float*)d_in[11];
    const float* fk_w     = (const float*)d_in[12];
    const float* fk_b     = (const float*)d_in[13];
    const float* bn_g     = (const float*)d_in[14];
    const float* bn_b     = (const float*)d_in[15];
    const float* pool_w   = (const float*)d_in[16];
    const float* pool_b   = (const float*)d_in[17];
    const float* head_w1  = (const float*)d_in[18];
    const float* head_b1  = (const float*)d_in[19];
    const float* w2e = (const float*)d_in[20];
    const float* b2e = (const float*)d_in[21];
    const float* w2s = (const float*)d_in[22];
    const float* b2s = (const float*)d_in[23];
    const float* w2c = (const float*)d_in[24];
    const float* b2c = (const float*)d_in[25];
    const float* w2m = (const float*)d_in[26];
    const float* b2m = (const float*)d_in[27];
    float* out = (float*)d_out;

    cudaFuncSetAttribute(mma_gemm_kernel, cudaFuncAttributeMaxDynamicSharedMemorySize,
                         GEMM_SMEM);

    float *p_h, *p_p1, *p_p2, *p_hconv, *p_stats;
    bf16 *p_hhi, *p_hlo, *p_Shi, *p_Slo, *p_Wfk_hi, *p_Wfk_lo, *p_Wlin_hi, *p_Wlin_lo;
    cudaGetSymbolAddress((void**)&p_h, g_h);
    cudaGetSymbolAddress((void**)&p_p1, g_p1);
    cudaGetSymbolAddress((void**)&p_p2, g_p2);
    cudaGetSymbolAddress((void**)&p_hconv, g_hconv);
    cudaGetSymbolAddress((void**)&p_stats, g_stats);
    cudaGetSymbolAddress((void**)&p_hhi, g_hhi);
    cudaGetSymbolAddress((void**)&p_hlo, g_hlo);
    cudaGetSymbolAddress((void**)&p_Shi, g_Shi);
    cudaGetSymbolAddress((void**)&p_Slo, g_Slo);
    cudaGetSymbolAddress((void**)&p_Wfk_hi, g_Wfk_hi);
    cudaGetSymbolAddress((void**)&p_Wfk_lo, g_Wfk_lo);
    cudaGetSymbolAddress((void**)&p_Wlin_hi, g_Wlin_hi);
    cudaGetSymbolAddress((void**)&p_Wlin_lo, g_Wlin_lo);

    const int elem_blocks = (NN * HID + 255) / 256;   // 10000
    const int warp_blocks = (NN + 7) / 8;             // 2500
    const int edge_blocks = (NE + 7) / 8;             // 40000
    const int tile_blocks = (NN + 127) / 128;         // 157

    conv_fkw_kernel<<<(DEPTH * KFK * HID + 255) / 256, 256>>>(fk_w);
    conv_linw_kernel<<<(DEPTH * 2 * HID * HID + 255) / 256, 256>>>(lin_w);

    node_embed_kernel<<<elem_blocks, 256>>>(x, node_w, node_b);

    for (int l = 0; l < DEPTH; ++l) {
        const float* lw = lin_w + (size_t)l * 259 * HID;
        const float* lb = lin_b + (size_t)l * HID;
        const float* aw = att_w + (size_t)l * 259;
        const bf16* Wdst_hi = p_Wlin_hi + ((size_t)l * 2 + 0) * HID * HID;
        const bf16* Wdst_lo = p_Wlin_lo + ((size_t)l * 2 + 0) * HID * HID;
        const bf16* Wsrc_hi = p_Wlin_hi + ((size_t)l * 2 + 1) * HID * HID;
        const bf16* Wsrc_lo = p_Wlin_lo + ((size_t)l * 2 + 1) * HID * HID;

        mma_gemm_kernel<<<tile_blocks, 256, GEMM_SMEM>>>(
            p_hhi, p_hlo, Wdst_hi, Wdst_lo, nullptr, nullptr, p_p1, NN, HID);
        mma_gemm_kernel<<<tile_blocks, 256, GEMM_SMEM>>>(
            p_hhi, p_hlo, Wsrc_hi, Wsrc_lo, nullptr, nullptr, p_p2, NN, HID);
        q_kernel<<<warp_blocks, 256>>>(p_h, aw);
        fk_s_kernel<<<elem_blocks, 256>>>();
        cudaMemsetAsync(p_hconv, 0, (size_t)NN * HID * sizeof(float), 0);
        edge_kernel<<<edge_blocks, 256>>>(ei, ea, lw, lb, aw, att_b, l);
        mma_gemm_kernel<<<tile_blocks, 256, GEMM_SMEM>>>(
            p_Shi, p_Slo, p_Wfk_hi + (size_t)l * HID * KFK, p_Wfk_lo + (size_t)l * HID * KFK,
            fk_b + (size_t)l * HID, p_hconv, p_h, NN, KFK);
        cudaMemsetAsync(p_stats, 0, 2 * HID * sizeof(float), 0);
        bn_stat_kernel<<<160, 128>>>(p_h, (NN + 159) / 160);
        bn_apply_kernel<<<elem_blocks, 256>>>(p_h, bn_g + (size_t)l * HID, bn_b + (size_t)l * HID);
    }

    pool_init_kernel<<<32, 256>>>();
    pool_logit_kernel<<<warp_blocks, 256>>>(p_h, pool_w, pool_b);
    pool_sumexp_kernel<<<80, 256>>>();
    pool_scatter_kernel<<<warp_blocks, 256>>>(p_h, batch);

    head_kernel<<<NB, 128>>>(sg_table, sgidx, head_w1, head_b1,
                             w2e, b2e, w2s, b2s, w2c, b2c, w2m, b2m, out);
}

// round 10
// speedup vs baseline: 2.2674x; 1.3605x over previous
#include <cuda_runtime.h>
#include <cuda_bf16.h>
#include <math.h>
#include <stdint.h>

#define NN 20000
#define MPAD 20096          // 157 * 128
#define NE 320000
#define NB 64
#define HID 128
#define DEPTH 4
#define NFREQ 8
#define KFK (NFREQ * HID)   // 1024
#define TWO_PI_F 6.283185307179586f

typedef __nv_bfloat16 bf16;

// ==================== scratch (static device allocations) ====================
__device__ float g_h[MPAD * HID];
__device__ float g_p1[NN * HID];
__device__ float g_p2[NN * HID];
__device__ float g_hconv[NN * HID];
__device__ bf16 g_hhi[MPAD * HID];
__device__ bf16 g_hlo[MPAD * HID];
__device__ bf16 g_Shi[(size_t)MPAD * KFK];
__device__ bf16 g_Slo[(size_t)MPAD * KFK];
__device__ bf16 g_Wfk_hi[DEPTH * HID * KFK];      // [l][n][k]
__device__ bf16 g_Wfk_lo[DEPTH * HID * KFK];
__device__ bf16 g_Wlin_hi[DEPTH * 2 * HID * HID]; // [l][part][n][k]
__device__ bf16 g_Wlin_lo[DEPTH * 2 * HID * HID];
__device__ float g_q1[NN];
__device__ float g_q2[NN];
__device__ float g_logits[NN];
__device__ float g_stats[2 * HID];
__device__ float g_pooled[NB * HID];
__device__ unsigned g_umax;
__device__ float g_sumexp;
// CSR for edge aggregation (built once per launch)
__device__ int g_count[NN];
__device__ int g_rowstart[NN + 1];
__device__ int g_perm[NE];

// ==================== mma.sync / cp.async helpers ====================
__device__ __forceinline__ uint32_t smem_to_u32(const void* p) {
    uint32_t a;
    asm("{ .reg .u64 t; cvta.to.shared.u64 t, %1; cvt.u32.u64 %0, t; }" : "=r"(a) : "l"(p));
    return a;
}

#define LDSM4(r, addr) \
    asm volatile("ldmatrix.sync.aligned.m8n8.x4.shared.b16 {%0,%1,%2,%3}, [%4];" \
        : "=r"((r)[0]), "=r"((r)[1]), "=r"((r)[2]), "=r"((r)[3]) : "r"(addr))

#define MMA_BF16(c, a, b0, b1) \
    asm volatile("mma.sync.aligned.m16n8k16.row.col.f32.bf16.bf16.f32 " \
        "{%0,%1,%2,%3}, {%4,%5,%6,%7}, {%8,%9}, {%0,%1,%2,%3};" \
        : "+f"((c)[0]), "+f"((c)[1]), "+f"((c)[2]), "+f"((c)[3]) \
        : "r"((a)[0]), "r"((a)[1]), "r"((a)[2]), "r"((a)[3]), "r"(b0), "r"(b1))

__device__ __forceinline__ void cp16(uint32_t dst, const void* src) {
    asm volatile("cp.async.cg.shared.global [%0], [%1], 16;" :: "r"(dst), "l"(src));
}
#define CP_COMMIT() asm volatile("cp.async.commit_group;" ::: "memory")
#define CP_WAIT(n)  asm volatile("cp.async.wait_group %0;" :: "n"(n) : "memory")

// ==================== tensor-core GEMM (64-row tiles, 2 CTA/SM) ====================
// out[M x 128] = (Ahi+Alo)[M x K] @ (Bhi+Blo)^T (+bias)(+add), K mult of 64
// 3-term split: Ahi*Bhi + Alo*Bhi + Ahi*Blo.
#define BKP 72                                  // padded k-stride (halves)
#define A_MAT_B (64 * BKP * 2)                  // 9216
#define B_MAT_B (128 * BKP * 2)                 // 18432
#define STAGE_BYTES (2 * A_MAT_B + 2 * B_MAT_B) // 55296
#define GEMM_SMEM (2 * STAGE_BYTES)             // 110592

__global__ __launch_bounds__(256, 2) void mma_gemm_kernel(
    const bf16* __restrict__ Ahi, const bf16* __restrict__ Alo,
    const bf16* __restrict__ Bhi, const bf16* __restrict__ Blo,
    const float* __restrict__ bias, const float* __restrict__ add,
    float* __restrict__ out, int M, int K)
{
    extern __shared__ __align__(16) char sm[];
    uint32_t smem_base = smem_to_u32(sm);
    int tid = threadIdx.x, lane = tid & 31, wid = tid >> 5;
    int warp_m = wid & 1;        // 2 warps over M (32 rows each)
    int warp_n = wid >> 1;       // 4 warps over N (32 cols each)
    int m0 = blockIdx.x * 64;

    float acc[2][4][4];
#pragma unroll
    for (int mt = 0; mt < 2; ++mt)
#pragma unroll
        for (int nt = 0; nt < 4; ++nt)
#pragma unroll
            for (int j = 0; j < 4; ++j) acc[mt][nt][j] = 0.f;

    int nchunks = K >> 6;

    auto load_stage = [&](int stage, int k0) {
        uint32_t sbase = smem_base + stage * STAGE_BYTES;
#pragma unroll
        for (int it = 0; it < 12; ++it) {
            int idx = tid + it * 256;            // 0..3071
            const bf16* src;
            uint32_t dst;
            if (idx < 1024) {                    // A hi/lo: 64 rows x 8 segs each
                int amat = idx >> 9;
                int rem = idx & 511;
                int row = rem >> 3, seg = rem & 7;
                src = (amat ? Alo : Ahi) + (size_t)(m0 + row) * K + k0 + seg * 8;
                dst = sbase + amat * A_MAT_B + (uint32_t)(row * BKP + seg * 8) * 2;
            } else {                             // B hi/lo: 128 rows x 8 segs each
                int idx2 = idx - 1024;
                int bmat = idx2 >> 10;
                int rem = idx2 & 1023;
                int row = rem >> 3, seg = rem & 7;
                src = (bmat ? Blo : Bhi) + (size_t)row * K + k0 + seg * 8;
                dst = sbase + 2 * A_MAT_B + bmat * B_MAT_B + (uint32_t)(row * BKP + seg * 8) * 2;
            }
            cp16(dst, src);
        }
    };

    load_stage(0, 0);
    CP_COMMIT();

    for (int c = 0; c < nchunks; ++c) {
        if (c + 1 < nchunks) {
            load_stage((c + 1) & 1, (c + 1) << 6);
            CP_COMMIT();
            CP_WAIT(1);
        } else {
            CP_WAIT(0);
        }
        __syncthreads();

        uint32_t sb = smem_base + (c & 1) * STAGE_BYTES;
        uint32_t uAhi = sb;
        uint32_t uAlo = sb + A_MAT_B;
        uint32_t uBhi = sb + 2 * A_MAT_B;
        uint32_t uBlo = sb + 2 * A_MAT_B + B_MAT_B;

#pragma unroll
        for (int ks = 0; ks < 4; ++ks) {
            uint32_t ahi[2][4], alo[2][4];
#pragma unroll
            for (int mt = 0; mt < 2; ++mt) {
                int r = warp_m * 32 + mt * 16 + (lane & 15);
                int cc = ks * 16 + ((lane >> 4) << 3);
                uint32_t off = (uint32_t)(r * BKP + cc) * 2;
                LDSM4(ahi[mt], uAhi + off);
                LDSM4(alo[mt], uAlo + off);
            }
#pragma unroll
            for (int np = 0; np < 2; ++np) {
                int j = lane >> 3;
                int rn = warp_n * 32 + np * 16 + ((j >> 1) << 3) + (lane & 7);
                int cn = ks * 16 + ((j & 1) << 3);
                uint32_t off = (uint32_t)(rn * BKP + cn) * 2;
                uint32_t bhi[4], blo[4];
                LDSM4(bhi, uBhi + off);
                LDSM4(blo, uBlo + off);
#pragma unroll
                for (int mt = 0; mt < 2; ++mt) {
                    MMA_BF16(acc[mt][2 * np],     ahi[mt], bhi[0], bhi[1]);
                    MMA_BF16(acc[mt][2 * np],     alo[mt], bhi[0], bhi[1]);
                    MMA_BF16(acc[mt][2 * np],     ahi[mt], blo[0], blo[1]);
                    MMA_BF16(acc[mt][2 * np + 1], ahi[mt], bhi[2], bhi[3]);
                    MMA_BF16(acc[mt][2 * np + 1], alo[mt], bhi[2], bhi[3]);
                    MMA_BF16(acc[mt][2 * np + 1], ahi[mt], blo[2], blo[3]);
                }
            }
        }
        __syncthreads();
    }

    // epilogue
#pragma unroll
    for (int mt = 0; mt < 2; ++mt) {
        int r0 = m0 + warp_m * 32 + mt * 16 + (lane >> 2);
        int r1 = r0 + 8;
#pragma unroll
        for (int nt = 0; nt < 4; ++nt) {
            int c = warp_n * 32 + nt * 8 + 2 * (lane & 3);
            float bx = 0.f, by = 0.f;
            if (bias) { float2 bv = *(const float2*)&bias[c]; bx = bv.x; by = bv.y; }
            if (r0 < M) {
                float vx = acc[mt][nt][0] + bx, vy = acc[mt][nt][1] + by;
                if (add) {
                    float2 av = *(const float2*)&add[(size_t)r0 * HID + c];
                    vx += av.x; vy += av.y;
                }
                float2 o; o.x = vx; o.y = vy;
                *(float2*)&out[(size_t)r0 * HID + c] = o;
            }
            if (r1 < M) {
                float vx = acc[mt][nt][2] + bx, vy = acc[mt][nt][3] + by;
                if (add) {
                    float2 av = *(const float2*)&add[(size_t)r1 * HID + c];
                    vx += av.x; vy += av.y;
                }
                float2 o; o.x = vx; o.y = vy;
                *(float2*)&out[(size_t)r1 * HID + c] = o;
            }
        }
    }
}

// ==================== CSR construction ====================
__global__ void hist_kernel(const int* __restrict__ ei) {
    int e = blockIdx.x * blockDim.x + threadIdx.x;
    if (e < NE) atomicAdd(&g_count[ei[NE + e]], 1);
}

#define SCH 20
__global__ __launch_bounds__(1024) void scan_kernel() {
    int t = threadIdx.x;
    int base = t * SCH;
    int loc[SCH];
    int s = 0;
#pragma unroll
    for (int i = 0; i < SCH; ++i) {
        int n = base + i;
        int v = (n < NN) ? g_count[n] : 0;
        loc[i] = s;
        s += v;
    }
    int lane = t & 31, w = t >> 5;
    int ps = s;
#pragma unroll
    for (int o = 1; o < 32; o <<= 1) {
        int x = __shfl_up_sync(0xffffffffu, ps, o);
        if (lane >= o) ps += x;
    }
    __shared__ int wsum[32];
    if (lane == 31) wsum[w] = ps;
    __syncthreads();
    if (w == 0) {
        int x = wsum[lane];
#pragma unroll
        for (int o = 1; o < 32; o <<= 1) {
            int y = __shfl_up_sync(0xffffffffu, x, o);
            if (lane >= o) x += y;
        }
        wsum[lane] = x;
    }
    __syncthreads();
    int off = ps - s + (w > 0 ? wsum[w - 1] : 0);
#pragma unroll
    for (int i = 0; i < SCH; ++i) {
        int n = base + i;
        if (n < NN) g_rowstart[n] = off + loc[i];
    }
    if (t == 0) g_rowstart[NN] = NE;
}

__global__ void scatter_kernel(const int* __restrict__ ei) {
    int e = blockIdx.x * blockDim.x + threadIdx.x;
    if (e < NE) {
        int dst = ei[NE + e];
        int pos = g_rowstart[dst] + atomicAdd(&g_count[dst], 1);
        g_perm[pos] = e;
    }
}

// ==================== edge conv (CSR, warp per dst, no atomics) ====================
__global__ __launch_bounds__(256) void edge_csr_kernel(
    const int* __restrict__ ei, const float* __restrict__ ea,
    const float* __restrict__ linw, const float* __restrict__ linb,
    const float* __restrict__ attw, const float* __restrict__ attb_p, int l)
{
    __shared__ float s_w0[HID], s_w1[HID], s_w2[HID], s_lb[HID];
    __shared__ float s_awe[3];
    __shared__ float s_attb;
    int tid = threadIdx.x;
    if (tid < HID) {
        s_w0[tid] = linw[256 * HID + tid];
        s_w1[tid] = linw[257 * HID + tid];
        s_w2[tid] = linw[258 * HID + tid];
        s_lb[tid] = linb[tid];
    }
    if (tid < 3) s_awe[tid] = attw[256 + tid];
    if (tid == 3) s_attb = attb_p[l];
    __syncthreads();

    int node = blockIdx.x * 8 + (tid >> 5);     // grid covers exactly NN warps
    int lane = tid & 31;
    int start = g_rowstart[node], end = g_rowstart[node + 1];
    float q1d = g_q1[node];
    float aw0 = s_awe[0], aw1 = s_awe[1], aw2 = s_awe[2], ab = s_attb;

    float a0 = 0.f, a1 = 0.f, a2 = 0.f, a3 = 0.f;
    float sa = 0.f, se0 = 0.f, se1 = 0.f, se2 = 0.f;
    for (int j = start; j < end; ++j) {
        int e = g_perm[j];
        int src = ei[e];
        float e0 = ea[3 * e + 0], e1 = ea[3 * e + 1], e2 = ea[3 * e + 2];
        float lg = q1d + g_q2[src] + e0 * aw0 + e1 * aw1 + e2 * aw2 + ab;
        float al = 1.f / (1.f + expf(-lg));
        float4 v2 = *(const float4*)&g_p2[(size_t)src * HID + lane * 4];
        a0 += al * v2.x; a1 += al * v2.y; a2 += al * v2.z; a3 += al * v2.w;
        sa += al; se0 += al * e0; se1 += al * e1; se2 += al * e2;
    }
    int c = lane * 4;
    float4 p1v = *(const float4*)&g_p1[(size_t)node * HID + c];
    float4 r;
    r.x = a0 + se0 * s_w0[c + 0] + se1 * s_w1[c + 0] + se2 * s_w2[c + 0] + sa * (p1v.x + s_lb[c + 0]);
    r.y = a1 + se0 * s_w0[c + 1] + se1 * s_w1[c + 1] + se2 * s_w2[c + 1] + sa * (p1v.y + s_lb[c + 1]);
    r.z = a2 + se0 * s_w0[c + 2] + se1 * s_w1[c + 2] + se2 * s_w2[c + 2] + sa * (p1v.z + s_lb[c + 2]);
    r.w = a3 + se0 * s_w0[c + 3] + se1 * s_w1[c + 3] + se2 * s_w2[c + 3] + sa * (p1v.w + s_lb[c + 3]);
    *(float4*)&g_hconv[(size_t)node * HID + c] = r;
}

// ==================== small kernels ====================
__global__ void pool_init_kernel() {
    int i = blockIdx.x * blockDim.x + threadIdx.x;
    int stride = gridDim.x * blockDim.x;
    for (int j = i; j < NB * HID; j += stride) g_pooled[j] = 0.f;
    if (i == 0) { g_umax = 0u; g_sumexp = 0.f; }
}

__global__ void node_embed_kernel(const float* __restrict__ x,
                                  const float* __restrict__ w,
                                  const float* __restrict__ b) {
    int idx = blockIdx.x * blockDim.x + threadIdx.x;
    if (idx >= NN * HID) return;
    int n = idx >> 7, c = idx & 127;
    float v = b[c];
    v += x[n * 4 + 0] * w[0 * HID + c];
    v += x[n * 4 + 1] * w[1 * HID + c];
    v += x[n * 4 + 2] * w[2 * HID + c];
    v += x[n * 4 + 3] * w[3 * HID + c];
    g_h[idx] = v;
    bf16 hi = __float2bfloat16(v);
    g_hhi[idx] = hi;
    g_hlo[idx] = __float2bfloat16(v - __bfloat162float(hi));
}

__global__ void conv_fkw_kernel(const float* __restrict__ fkw) {
    int idx = blockIdx.x * blockDim.x + threadIdx.x;
    if (idx >= DEPTH * KFK * HID) return;
    int l = idx / (KFK * HID);
    int rem = idx - l * (KFK * HID);
    int k = rem >> 7;
    int n = rem & 127;
    float w = fkw[((size_t)l * KFK + k) * HID + n];
    bf16 hi = __float2bfloat16(w);
    bf16 lo = __float2bfloat16(w - __bfloat162float(hi));
    size_t o = ((size_t)l * HID + n) * KFK + k;
    g_Wfk_hi[o] = hi;
    g_Wfk_lo[o] = lo;
}

__global__ void conv_linw_kernel(const float* __restrict__ linw) {
    int idx = blockIdx.x * blockDim.x + threadIdx.x;
    if (idx >= DEPTH * 2 * HID * HID) return;
    int l = idx / (2 * HID * HID);
    int rem = idx - l * (2 * HID * HID);
    int p = rem >> 14;
    int nk = rem & 16383;
    int n = nk >> 7, k = nk & 127;
    float w = linw[((size_t)l * 259 + p * 128 + k) * HID + n];
    bf16 hi = __float2bfloat16(w);
    bf16 lo = __float2bfloat16(w - __bfloat162float(hi));
    size_t o = (((size_t)l * 2 + p) * HID + n) * HID + k;
    g_Wlin_hi[o] = hi;
    g_Wlin_lo[o] = lo;
}

__global__ void fk_s_kernel() {
    int idx = blockIdx.x * blockDim.x + threadIdx.x;
    if (idx >= NN * HID) return;
    int n = idx >> 7, i = idx & 127;
    size_t base = (size_t)n * KFK + i;
    float theta = TWO_PI_F * g_h[idx];
    float s1, c1;
    sincosf(theta, &s1, &c1);
    float s = s1, c = c1;
#pragma unroll
    for (int f = 0; f < NFREQ; ++f) {
        if (f > 0) {
            float s2 = s * c1 + c * s1;
            float c2 = c * c1 - s * s1;
            s = s2; c = c2;
        }
        float v = s + c;
        bf16 hi = __float2bfloat16(v);
        g_Shi[base + f * HID] = hi;
        g_Slo[base + f * HID] = __float2bfloat16(v - __bfloat162float(hi));
    }
}

// NOTE: attw = att_w + l*259 NOT 16B-aligned for l>0 -> scalar loads.
__global__ void q_kernel(const float* __restrict__ h, const float* __restrict__ attw) {
    int gwarp = (blockIdx.x * blockDim.x + threadIdx.x) >> 5;
    int lane = threadIdx.x & 31;
    if (gwarp >= NN) return;
    float4 hv = *(const float4*)&h[(size_t)gwarp * HID + lane * 4];
    int c = lane * 4;
    float a10 = attw[c + 0], a11 = attw[c + 1], a12 = attw[c + 2], a13 = attw[c + 3];
    float a20 = attw[HID + c + 0], a21 = attw[HID + c + 1], a22 = attw[HID + c + 2], a23 = attw[HID + c + 3];
    float s1 = hv.x * a10 + hv.y * a11 + hv.z * a12 + hv.w * a13;
    float s2 = hv.x * a20 + hv.y * a21 + hv.z * a22 + hv.w * a23;
#pragma unroll
    for (int o = 16; o > 0; o >>= 1) {
        s1 += __shfl_xor_sync(0xffffffffu, s1, o);
        s2 += __shfl_xor_sync(0xffffffffu, s2, o);
    }
    if (lane == 0) { g_q1[gwarp] = s1; g_q2[gwarp] = s2; }
}

// ==================== batchnorm ====================
__global__ void bn_stat_kernel(const float* __restrict__ h, int rows_per_block) {
    int c = threadIdx.x;
    int r0 = blockIdx.x * rows_per_block;
    int r1 = min(NN, r0 + rows_per_block);
    float s = 0.f, ss = 0.f;
    for (int r = r0; r < r1; ++r) {
        float v = h[(size_t)r * HID + c];
        s += v; ss += v * v;
    }
    atomicAdd(&g_stats[c], s);
    atomicAdd(&g_stats[HID + c], ss);
}

__global__ void bn_apply_kernel(float* __restrict__ h,
                                const float* __restrict__ g,
                                const float* __restrict__ b) {
    int idx = blockIdx.x * blockDim.x + threadIdx.x;
    if (idx >= NN * HID) return;
    int c = idx & 127;
    const float invN = 1.f / (float)NN;
    float mu = g_stats[c] * invN;
    float var = g_stats[HID + c] * invN - mu * mu;
    float rstd = rsqrtf(var + 1e-5f);
    float v = (h[idx] - mu) * rstd * g[c] + b[c];
    v = fmaxf(v, 0.f);
    h[idx] = v;
    bf16 hi = __float2bfloat16(v);
    g_hhi[idx] = hi;
    g_hlo[idx] = __float2bfloat16(v - __bfloat162float(hi));
}

// ==================== attention pooling ====================
__device__ __forceinline__ unsigned float_key(float f) {
    unsigned u = __float_as_uint(f);
    return (u & 0x80000000u) ? ~u : (u | 0x80000000u);
}

__global__ void pool_logit_kernel(const float* __restrict__ h,
                                  const float* __restrict__ pool_w,
                                  const float* __restrict__ pool_b) {
    int gwarp = (blockIdx.x * blockDim.x + threadIdx.x) >> 5;
    int lane = threadIdx.x & 31;
    if (gwarp >= NN) return;
    float4 hv = *(const float4*)&h[(size_t)gwarp * HID + lane * 4];
    float4 wv = *(const float4*)&pool_w[lane * 4];
    float s = hv.x * wv.x + hv.y * wv.y + hv.z * wv.z + hv.w * wv.w;
#pragma unroll
    for (int o = 16; o > 0; o >>= 1) s += __shfl_xor_sync(0xffffffffu, s, o);
    if (lane == 0) {
        s += pool_b[0];
        g_logits[gwarp] = s;
        atomicMax(&g_umax, float_key(s));
    }
}

__global__ void pool_sumexp_kernel() {
    unsigned k = g_umax;
    float maxv = (k & 0x80000000u) ? __uint_as_float(k ^ 0x80000000u)
                                   : __uint_as_float(~k);
    int i = blockIdx.x * blockDim.x + threadIdx.x;
    int stride = gridDim.x * blockDim.x;
    float local = 0.f;
    for (; i < NN; i += stride) local += expf(g_logits[i] - maxv);
#pragma unroll
    for (int o = 16; o > 0; o >>= 1) local += __shfl_xor_sync(0xffffffffu, local, o);
    __shared__ float ws[8];
    int lane = threadIdx.x & 31, wid = threadIdx.x >> 5;
    if (lane == 0) ws[wid] = local;
    __syncthreads();
    if (wid == 0) {
        float v = (lane < (blockDim.x >> 5)) ? ws[lane] : 0.f;
#pragma unroll
        for (int o = 16; o > 0; o >>= 1) v += __shfl_xor_sync(0xffffffffu, v, o);
        if (lane == 0) atomicAdd(&g_sumexp, v);
    }
}

__global__ void pool_scatter_kernel(const float* __restrict__ h,
                                    const int* __restrict__ batch) {
    int gwarp = (blockIdx.x * blockDim.x + threadIdx.x) >> 5;
    int lane = threadIdx.x & 31;
    if (gwarp >= NN) return;
    unsigned k = g_umax;
    float maxv = (k & 0x80000000u) ? __uint_as_float(k ^ 0x80000000u)
                                   : __uint_as_float(~k);
    float w = expf(g_logits[gwarp] - maxv) / g_sumexp;
    int b = batch[gwarp];
    int c = lane * 4;
    float4 hv = *(const float4*)&h[(size_t)gwarp * HID + c];
    float* outp = &g_pooled[b * HID + c];
    atomicAdd(outp + 0, w * hv.x);
    atomicAdd(outp + 1, w * hv.y);
    atomicAdd(outp + 2, w * hv.z);
    atomicAdd(outp + 3, w * hv.w);
}

// ==================== heads ====================
__global__ __launch_bounds__(128) void head_kernel(
    const float* __restrict__ sg_table, const int* __restrict__ sgidx,
    const float* __restrict__ hw1, const float* __restrict__ hb1,
    const float* __restrict__ w2e, const float* __restrict__ b2e,
    const float* __restrict__ w2s, const float* __restrict__ b2s,
    const float* __restrict__ w2c, const float* __restrict__ b2c,
    const float* __restrict__ w2m, const float* __restrict__ b2m,
    float* __restrict__ out)
{
    int b = blockIdx.x;
    int t = threadIdx.x;
    __shared__ float comb[2 * HID];
    __shared__ float z[HID];
    comb[t] = g_pooled[b * HID + t];
    comb[HID + t] = sg_table[sgidx[b] * HID + t];
    __syncthreads();

    const float* w2arr[4] = { w2e, w2s, w2c, w2m };
    const float* b2arr[4] = { b2e, b2s, b2c, b2m };
    const int od[4] = { 1, 3, 7, 3 };
    const int off[4] = { 0, NB * 1, NB * 4, NB * 11 };

    for (int i = 0; i < 4; ++i) {
        float accz = hb1[i * HID + t];
        const float* W = hw1 + (size_t)i * 2 * HID * HID;
#pragma unroll 8
        for (int j = 0; j < 2 * HID; ++j) accz += comb[j] * W[j * HID + t];
        z[t] = fmaxf(accz, 0.f);
        __syncthreads();
        if (t < od[i]) {
            const float* w2 = w2arr[i];
            float acc = b2arr[i][t];
            for (int j = 0; j < HID; ++j) acc += z[j] * w2[j * od[i] + t];
            out[off[i] + b * od[i] + t] = acc;
        }
        __syncthreads();
    }
}

// ==================== host ====================
extern "C" void kernel_launch(void* const* d_in, const int* in_sizes, int n_in,
                              void* d_out, int out_size) {
    const float* x        = (const float*)d_in[0];
    const int*   ei       = (const int*)d_in[1];
    const float* ea       = (const float*)d_in[2];
    const int*   batch    = (const int*)d_in[3];
    const int*   sgidx    = (const int*)d_in[4];
    const float* node_w   = (const float*)d_in[5];
    const float* node_b   = (const float*)d_in[6];
    const float* sg_table = (const float*)d_in[7];
    const float* lin_w    = (const float*)d_in[8];
    const float* lin_b    = (const float*)d_in[9];
    const float* att_w    = (const float*)d_in[10];
    const float* att_b    = (const float*)d_in[11];
    const float* fk_w     = (const float*)d_in[12];
    const float* fk_b     = (const float*)d_in[13];
    const float* bn_g     = (const float*)d_in[14];
    const float* bn_b     = (const float*)d_in[15];
    const float* pool_w   = (const float*)d_in[16];
    const float* pool_b   = (const float*)d_in[17];
    const float* head_w1  = (const float*)d_in[18];
    const float* head_b1  = (const float*)d_in[19];
    const float* w2e = (const float*)d_in[20];
    const float* b2e = (const float*)d_in[21];
    const float* w2s = (const float*)d_in[22];
    const float* b2s = (const float*)d_in[23];
    const float* w2c = (const float*)d_in[24];
    const float* b2c = (const float*)d_in[25];
    const float* w2m = (const float*)d_in[26];
    const float* b2m = (const float*)d_in[27];
    float* out = (float*)d_out;

    cudaFuncSetAttribute(mma_gemm_kernel, cudaFuncAttributeMaxDynamicSharedMemorySize,
                         GEMM_SMEM);

    float *p_h, *p_p1, *p_p2, *p_hconv, *p_stats;
    bf16 *p_hhi, *p_hlo, *p_Shi, *p_Slo, *p_Wfk_hi, *p_Wfk_lo, *p_Wlin_hi, *p_Wlin_lo;
    int *p_count;
    cudaGetSymbolAddress((void**)&p_h, g_h);
    cudaGetSymbolAddress((void**)&p_p1, g_p1);
    cudaGetSymbolAddress((void**)&p_p2, g_p2);
    cudaGetSymbolAddress((void**)&p_hconv, g_hconv);
    cudaGetSymbolAddress((void**)&p_stats, g_stats);
    cudaGetSymbolAddress((void**)&p_hhi, g_hhi);
    cudaGetSymbolAddress((void**)&p_hlo, g_hlo);
    cudaGetSymbolAddress((void**)&p_Shi, g_Shi);
    cudaGetSymbolAddress((void**)&p_Slo, g_Slo);
    cudaGetSymbolAddress((void**)&p_Wfk_hi, g_Wfk_hi);
    cudaGetSymbolAddress((void**)&p_Wfk_lo, g_Wfk_lo);
    cudaGetSymbolAddress((void**)&p_Wlin_hi, g_Wlin_hi);
    cudaGetSymbolAddress((void**)&p_Wlin_lo, g_Wlin_lo);
    cudaGetSymbolAddress((void**)&p_count, g_count);

    const int elem_blocks = (NN * HID + 255) / 256;   // 10000
    const int warp_blocks = (NN + 7) / 8;             // 2500
    const int tile_blocks = (NN + 63) / 64;           // 313

    // CSR construction (edge_index is layer-invariant)
    cudaMemsetAsync(p_count, 0, NN * sizeof(int), 0);
    hist_kernel<<<(NE + 255) / 256, 256>>>(ei);
    scan_kernel<<<1, 1024>>>();
    cudaMemsetAsync(p_count, 0, NN * sizeof(int), 0);
    scatter_kernel<<<(NE + 255) / 256, 256>>>(ei);

    conv_fkw_kernel<<<(DEPTH * KFK * HID + 255) / 256, 256>>>(fk_w);
    conv_linw_kernel<<<(DEPTH * 2 * HID * HID + 255) / 256, 256>>>(lin_w);

    node_embed_kernel<<<elem_blocks, 256>>>(x, node_w, node_b);

    for (int l = 0; l < DEPTH; ++l) {
        const float* lw = lin_w + (size_t)l * 259 * HID;
        const float* lb = lin_b + (size_t)l * HID;
        const float* aw = att_w + (size_t)l * 259;
        const bf16* Wdst_hi = p_Wlin_hi + ((size_t)l * 2 + 0) * HID * HID;
        const bf16* Wdst_lo = p_Wlin_lo + ((size_t)l * 2 + 0) * HID * HID;
        const bf16* Wsrc_hi = p_Wlin_hi + ((size_t)l * 2 + 1) * HID * HID;
        const bf16* Wsrc_lo = p_Wlin_lo + ((size_t)l * 2 + 1) * HID * HID;

        mma_gemm_kernel<<<tile_blocks, 256, GEMM_SMEM>>>(
            p_hhi, p_hlo, Wdst_hi, Wdst_lo, nullptr, nullptr, p_p1, NN, HID);
        mma_gemm_kernel<<<tile_blocks, 256, GEMM_SMEM>>>(
            p_hhi, p_hlo, Wsrc_hi, Wsrc_lo, nullptr, nullptr, p_p2, NN, HID);
        q_kernel<<<warp_blocks, 256>>>(p_h, aw);
        fk_s_kernel<<<elem_blocks, 256>>>();
        edge_csr_kernel<<<warp_blocks, 256>>>(ei, ea, lw, lb, aw, att_b, l);
        mma_gemm_kernel<<<tile_blocks, 256, GEMM_SMEM>>>(
            p_Shi, p_Slo, p_Wfk_hi + (size_t)l * HID * KFK, p_Wfk_lo + (size_t)l * HID * KFK,
            fk_b + (size_t)l * HID, p_hconv, p_h, NN, KFK);
        cudaMemsetAsync(p_stats, 0, 2 * HID * sizeof(float), 0);
        bn_stat_kernel<<<160, 128>>>(p_h, (NN + 159) / 160);
        bn_apply_kernel<<<elem_blocks, 256>>>(p_h, bn_g + (size_t)l * HID, bn_b + (size_t)l * HID);
    }

    pool_init_kernel<<<32, 256>>>();
    pool_logit_kernel<<<warp_blocks, 256>>>(p_h, pool_w, pool_b);
    pool_sumexp_kernel<<<80, 256>>>();
    pool_scatter_kernel<<<warp_blocks, 256>>>(p_h, batch);

    head_kernel<<<NB, 128>>>(sg_table, sgidx, head_w1, head_b1,
                             w2e, b2e, w2s, b2s, w2c, b2c, w2m, b2m, out);
}

// round 12
// speedup vs baseline: 2.4936x; 1.0997x over previous
#include <cuda_runtime.h>
#include <cuda_bf16.h>
#include <math.h>
#include <stdint.h>

#define NN 20000
#define MPAD 20096          // 314 * 64
#define NE 320000
#define NB 64
#define HID 128
#define DEPTH 4
#define NFREQ 8
#define KFK (NFREQ * HID)   // 1024
#define TWO_PI_F 6.283185307179586f

typedef __nv_bfloat16 bf16;

// ==================== scratch (static device allocations) ====================
__device__ float g_h[MPAD * HID];
__device__ float g_p1[NN * HID];
__device__ float g_p2[NN * HID];
__device__ float g_hconv[NN * HID];
__device__ bf16 g_hhi[MPAD * HID];
__device__ bf16 g_hlo[MPAD * HID];
__device__ bf16 g_Wfk_hi[DEPTH * HID * KFK];      // [l][n][k= i*8+f]
__device__ bf16 g_Wfk_lo[DEPTH * HID * KFK];
__device__ bf16 g_Wlin_hi[DEPTH * 2 * HID * HID]; // [l][part][n][k]
__device__ bf16 g_Wlin_lo[DEPTH * 2 * HID * HID];
__device__ float g_q1[NN];
__device__ float g_q2[NN];
__device__ float g_logits[NN];
__device__ float g_stats[2 * HID];
__device__ float g_pooled[NB * HID];
__device__ unsigned g_umax;
__device__ float g_sumexp;
// CSR for edge aggregation (built once per launch)
__device__ int g_count[NN];
__device__ int g_rowstart[NN + 1];
__device__ int g_perm[NE];

// ==================== mma.sync / cp.async helpers ====================
__device__ __forceinline__ uint32_t smem_to_u32(const void* p) {
    uint32_t a;
    asm("{ .reg .u64 t; cvta.to.shared.u64 t, %1; cvt.u32.u64 %0, t; }" : "=r"(a) : "l"(p));
    return a;
}

#define LDSM4(r, addr) \
    asm volatile("ldmatrix.sync.aligned.m8n8.x4.shared.b16 {%0,%1,%2,%3}, [%4];" \
        : "=r"((r)[0]), "=r"((r)[1]), "=r"((r)[2]), "=r"((r)[3]) : "r"(addr))

#define MMA_BF16(c, a, b0, b1) \
    asm volatile("mma.sync.aligned.m16n8k16.row.col.f32.bf16.bf16.f32 " \
        "{%0,%1,%2,%3}, {%4,%5,%6,%7}, {%8,%9}, {%0,%1,%2,%3};" \
        : "+f"((c)[0]), "+f"((c)[1]), "+f"((c)[2]), "+f"((c)[3]) \
        : "r"((a)[0]), "r"((a)[1]), "r"((a)[2]), "r"((a)[3]), "r"(b0), "r"(b1))

__device__ __forceinline__ void cp16(uint32_t dst, const void* src) {
    asm volatile("cp.async.cg.shared.global [%0], [%1], 16;" :: "r"(dst), "l"(src));
}
#define CP_COMMIT() asm volatile("cp.async.commit_group;" ::: "memory")
#define CP_WAIT(n)  asm volatile("cp.async.wait_group %0;" :: "n"(n) : "memory")

#define BKP 72                                  // padded k-stride (halves)
#define A_MAT_B (64 * BKP * 2)                  // 9216
#define B_MAT_B (128 * BKP * 2)                 // 18432
#define STAGE_BYTES (2 * A_MAT_B + 2 * B_MAT_B) // 55296
#define GEMM_SMEM (2 * STAGE_BYTES)             // 110592

// ==================== shared MMA core (64xM, 128xN tile) ====================
struct AccT { float a[2][4][4]; };

__device__ __forceinline__ void mma_chunk(uint32_t sb, int lane, int warp_m, int warp_n,
                                          AccT& acc) {
    uint32_t uAhi = sb;
    uint32_t uAlo = sb + A_MAT_B;
    uint32_t uBhi = sb + 2 * A_MAT_B;
    uint32_t uBlo = sb + 2 * A_MAT_B + B_MAT_B;
#pragma unroll
    for (int ks = 0; ks < 4; ++ks) {
        uint32_t ahi[2][4], alo[2][4];
#pragma unroll
        for (int mt = 0; mt < 2; ++mt) {
            int r = warp_m * 32 + mt * 16 + (lane & 15);
            int cc = ks * 16 + ((lane >> 4) << 3);
            uint32_t off = (uint32_t)(r * BKP + cc) * 2;
            LDSM4(ahi[mt], uAhi + off);
            LDSM4(alo[mt], uAlo + off);
        }
#pragma unroll
        for (int np = 0; np < 2; ++np) {
            int j = lane >> 3;
            int rn = warp_n * 32 + np * 16 + ((j >> 1) << 3) + (lane & 7);
            int cn = ks * 16 + ((j & 1) << 3);
            uint32_t off = (uint32_t)(rn * BKP + cn) * 2;
            uint32_t bhi[4], blo[4];
            LDSM4(bhi, uBhi + off);
            LDSM4(blo, uBlo + off);
#pragma unroll
            for (int mt = 0; mt < 2; ++mt) {
                MMA_BF16(acc.a[mt][2 * np],     ahi[mt], bhi[0], bhi[1]);
                MMA_BF16(acc.a[mt][2 * np],     alo[mt], bhi[0], bhi[1]);
                MMA_BF16(acc.a[mt][2 * np],     ahi[mt], blo[0], blo[1]);
                MMA_BF16(acc.a[mt][2 * np + 1], ahi[mt], bhi[2], bhi[3]);
                MMA_BF16(acc.a[mt][2 * np + 1], alo[mt], bhi[2], bhi[3]);
                MMA_BF16(acc.a[mt][2 * np + 1], ahi[mt], blo[2], blo[3]);
            }
        }
    }
}

__device__ __forceinline__ void epilogue(const AccT& acc, int m0, int lane,
                                         int warp_m, int warp_n,
                                         const float* bias, const float* add,
                                         float* out, int M) {
#pragma unroll
    for (int mt = 0; mt < 2; ++mt) {
        int r0 = m0 + warp_m * 32 + mt * 16 + (lane >> 2);
        int r1 = r0 + 8;
#pragma unroll
        for (int nt = 0; nt < 4; ++nt) {
            int c = warp_n * 32 + nt * 8 + 2 * (lane & 3);
            float bx = 0.f, by = 0.f;
            if (bias) { float2 bv = *(const float2*)&bias[c]; bx = bv.x; by = bv.y; }
            if (r0 < M) {
                float vx = acc.a[mt][nt][0] + bx, vy = acc.a[mt][nt][1] + by;
                if (add) {
                    float2 av = *(const float2*)&add[(size_t)r0 * HID + c];
                    vx += av.x; vy += av.y;
                }
                float2 o; o.x = vx; o.y = vy;
                *(float2*)&out[(size_t)r0 * HID + c] = o;
            }
            if (r1 < M) {
                float vx = acc.a[mt][nt][2] + bx, vy = acc.a[mt][nt][3] + by;
                if (add) {
                    float2 av = *(const float2*)&add[(size_t)r1 * HID + c];
                    vx += av.x; vy += av.y;
                }
                float2 o; o.x = vx; o.y = vy;
                *(float2*)&out[(size_t)r1 * HID + c] = o;
            }
        }
    }
}

// ==================== generic GEMM (precomputed bf16 A) ====================
__global__ __launch_bounds__(256, 2) void mma_gemm_kernel(
    const bf16* __restrict__ Ahi, const bf16* __restrict__ Alo,
    const bf16* __restrict__ Bhi, const bf16* __restrict__ Blo,
    const float* __restrict__ bias, const float* __restrict__ add,
    float* __restrict__ out, int M, int K)
{
    extern __shared__ __align__(16) char sm[];
    uint32_t smem_base = smem_to_u32(sm);
    int tid = threadIdx.x, lane = tid & 31, wid = tid >> 5;
    int warp_m = wid & 1;
    int warp_n = wid >> 1;
    int m0 = blockIdx.x * 64;

    AccT acc;
#pragma unroll
    for (int mt = 0; mt < 2; ++mt)
#pragma unroll
        for (int nt = 0; nt < 4; ++nt)
#pragma unroll
            for (int j = 0; j < 4; ++j) acc.a[mt][nt][j] = 0.f;

    int nchunks = K >> 6;

    auto load_stage = [&](int stage, int k0) {
        uint32_t sbase = smem_base + stage * STAGE_BYTES;
#pragma unroll
        for (int it = 0; it < 12; ++it) {
            int idx = tid + it * 256;
            const bf16* src;
            uint32_t dst;
            if (idx < 1024) {
                int amat = idx >> 9;
                int rem = idx & 511;
                int row = rem >> 3, seg = rem & 7;
                src = (amat ? Alo : Ahi) + (size_t)(m0 + row) * K + k0 + seg * 8;
                dst = sbase + amat * A_MAT_B + (uint32_t)(row * BKP + seg * 8) * 2;
            } else {
                int idx2 = idx - 1024;
                int bmat = idx2 >> 10;
                int rem = idx2 & 1023;
                int row = rem >> 3, seg = rem & 7;
                src = (bmat ? Blo : Bhi) + (size_t)row * K + k0 + seg * 8;
                dst = sbase + 2 * A_MAT_B + bmat * B_MAT_B + (uint32_t)(row * BKP + seg * 8) * 2;
            }
            cp16(dst, src);
        }
    };

    load_stage(0, 0);
    CP_COMMIT();

    for (int c = 0; c < nchunks; ++c) {
        if (c + 1 < nchunks) {
            load_stage((c + 1) & 1, (c + 1) << 6);
            CP_COMMIT();
            CP_WAIT(1);
        } else {
            CP_WAIT(0);
        }
        __syncthreads();
        mma_chunk(smem_base + (c & 1) * STAGE_BYTES, lane, warp_m, warp_n, acc);
        __syncthreads();
    }
    epilogue(acc, m0, lane, warp_m, warp_n, bias, add, out, M);
}

// ==================== FK GEMM: A = (sin+cos Fourier features) generated in-kernel ====
// K ordering: k = i*8 + f, i in 0..127 (h column), f in 0..7 (freq-1).
// B (weights) pre-transposed to match. out may alias h (per-CTA row ownership).
__global__ __launch_bounds__(256, 2) void fk_gemm_kernel(
    const float* __restrict__ h,                       // [MPAD x 128] fp32
    const bf16* __restrict__ Bhi, const bf16* __restrict__ Blo, // [128 x 1024]
    const float* __restrict__ bias, const float* __restrict__ add,
    float* __restrict__ out, int M)
{
    extern __shared__ __align__(16) char sm[];
    uint32_t smem_base = smem_to_u32(sm);
    int tid = threadIdx.x, lane = tid & 31, wid = tid >> 5;
    int warp_m = wid & 1;
    int warp_n = wid >> 1;
    int m0 = blockIdx.x * 64;
    const int K = KFK;

    AccT acc;
#pragma unroll
    for (int mt = 0; mt < 2; ++mt)
#pragma unroll
        for (int nt = 0; nt < 4; ++nt)
#pragma unroll
            for (int j = 0; j < 4; ++j) acc.a[mt][nt][j] = 0.f;

    auto load_B = [&](int stage, int k0) {
        uint32_t sbase = smem_base + stage * STAGE_BYTES + 2 * A_MAT_B;
#pragma unroll
        for (int it = 0; it < 8; ++it) {
            int idx = tid + it * 256;            // 0..2047
            int bmat = idx >> 10;
            int rem = idx & 1023;
            int row = rem >> 3, seg = rem & 7;
            const bf16* src = (bmat ? Blo : Bhi) + (size_t)row * K + k0 + seg * 8;
            uint32_t dst = sbase + bmat * B_MAT_B + (uint32_t)(row * BKP + seg * 8) * 2;
            cp16(dst, src);
        }
    };

    // compute A chunk: rows 64, k_local = il*8 + f, il = 0..7 (i = c*8 + il)
    auto compute_A = [&](int stage, int c) {
        uint32_t aHi = smem_base + stage * STAGE_BYTES;
        uint32_t aLo = aHi + A_MAT_B;
        int i0 = c << 3;
#pragma unroll
        for (int half = 0; half < 2; ++half) {
            int p = tid + half * 256;            // 0..511
            int row = p >> 3, il = p & 7;
            float hv = h[(size_t)(m0 + row) * HID + i0 + il];
            float th = TWO_PI_F * hv;
            float s1, c1;
            sincosf(th, &s1, &c1);
            float s = s1, cc = c1;
            uint32_t hi4[4], lo4[4];
#pragma unroll
            for (int fp = 0; fp < 4; ++fp) {
                float v0 = s + cc;               // freq 2*fp+1
                float s2 = s * c1 + cc * s1;     // advance
                float c2 = cc * c1 - s * s1;
                s = s2; cc = c2;
                float v1 = s + cc;               // freq 2*fp+2
                s2 = s * c1 + cc * s1;
                c2 = cc * c1 - s * s1;
                s = s2; cc = c2;
                bf16 h0 = __float2bfloat16(v0);
                bf16 h1 = __float2bfloat16(v1);
                bf16 l0 = __float2bfloat16(v0 - __bfloat162float(h0));
                bf16 l1 = __float2bfloat16(v1 - __bfloat162float(h1));
                hi4[fp] = (uint32_t)__bfloat16_as_ushort(h0) |
                          ((uint32_t)__bfloat16_as_ushort(h1) << 16);
                lo4[fp] = (uint32_t)__bfloat16_as_ushort(l0) |
                          ((uint32_t)__bfloat16_as_ushort(l1) << 16);
            }
            uint32_t off = (uint32_t)(row * BKP + il * 8) * 2;
            asm volatile("st.shared.v4.b32 [%0], {%1,%2,%3,%4};"
                :: "r"(aHi + off), "r"(hi4[0]), "r"(hi4[1]), "r"(hi4[2]), "r"(hi4[3]));
            asm volatile("st.shared.v4.b32 [%0], {%1,%2,%3,%4};"
                :: "r"(aLo + off), "r"(lo4[0]), "r"(lo4[1]), "r"(lo4[2]), "r"(lo4[3]));
        }
    };

    const int nchunks = K >> 6;   // 16
    compute_A(0, 0);
    load_B(0, 0);
    CP_COMMIT();

    for (int c = 0; c < nchunks; ++c) {
        if (c + 1 < nchunks) {
            load_B((c + 1) & 1, (c + 1) << 6);
            CP_COMMIT();
            compute_A((c + 1) & 1, c + 1);
            CP_WAIT(1);
        } else {
            CP_WAIT(0);
        }
        __syncthreads();
        mma_chunk(smem_base + (c & 1) * STAGE_BYTES, lane, warp_m, warp_n, acc);
        __syncthreads();
    }
    epilogue(acc, m0, lane, warp_m, warp_n, bias, add, out, M);
}

// ==================== CSR construction ====================
__global__ void hist_kernel(const int* __restrict__ ei) {
    int e = blockIdx.x * blockDim.x + threadIdx.x;
    if (e < NE) atomicAdd(&g_count[ei[NE + e]], 1);
}

#define SCH 20
__global__ __launch_bounds__(1024) void scan_kernel() {
    int t = threadIdx.x;
    int base = t * SCH;
    int loc[SCH];
    int s = 0;
#pragma unroll
    for (int i = 0; i < SCH; ++i) {
        int n = base + i;
        int v = (n < NN) ? g_count[n] : 0;
        loc[i] = s;
        s += v;
    }
    int lane = t & 31, w = t >> 5;
    int ps = s;
#pragma unroll
    for (int o = 1; o < 32; o <<= 1) {
        int x = __shfl_up_sync(0xffffffffu, ps, o);
        if (lane >= o) ps += x;
    }
    __shared__ int wsum[32];
    if (lane == 31) wsum[w] = ps;
    __syncthreads();
    if (w == 0) {
        int x = wsum[lane];
#pragma unroll
        for (int o = 1; o < 32; o <<= 1) {
            int y = __shfl_up_sync(0xffffffffu, x, o);
            if (lane >= o) x += y;
        }
        wsum[lane] = x;
    }
    __syncthreads();
    int off = ps - s + (w > 0 ? wsum[w - 1] : 0);
#pragma unroll
    for (int i = 0; i < SCH; ++i) {
        int n = base + i;
        if (n < NN) g_rowstart[n] = off + loc[i];
    }
    if (t == 0) g_rowstart[NN] = NE;
}

__global__ void scatter_kernel(const int* __restrict__ ei) {
    int e = blockIdx.x * blockDim.x + threadIdx.x;
    if (e < NE) {
        int dst = ei[NE + e];
        int pos = g_rowstart[dst] + atomicAdd(&g_count[dst], 1);
        g_perm[pos] = e;
    }
}

// ==================== edge conv (CSR, warp per dst, 2-way unrolled) ====================
__global__ __launch_bounds__(256) void edge_csr_kernel(
    const int* __restrict__ ei, const float* __restrict__ ea,
    const float* __restrict__ linw, const float* __restrict__ linb,
    const float* __restrict__ attw, const float* __restrict__ attb_p, int l)
{
    __shared__ float s_w0[HID], s_w1[HID], s_w2[HID], s_lb[HID];
    __shared__ float s_awe[3];
    __shared__ float s_attb;
    int tid = threadIdx.x;
    if (tid < HID) {
        s_w0[tid] = linw[256 * HID + tid];
        s_w1[tid] = linw[257 * HID + tid];
        s_w2[tid] = linw[258 * HID + tid];
        s_lb[tid] = linb[tid];
    }
    if (tid < 3) s_awe[tid] = attw[256 + tid];
    if (tid == 3) s_attb = attb_p[l];
    __syncthreads();

    int node = blockIdx.x * 8 + (tid >> 5);
    int lane = tid & 31;
    int start = g_rowstart[node], end = g_rowstart[node + 1];
    float q1d = g_q1[node];
    float aw0 = s_awe[0], aw1 = s_awe[1], aw2 = s_awe[2], ab = s_attb;

    float a0 = 0.f, a1 = 0.f, a2 = 0.f, a3 = 0.f;
    float sa = 0.f, se0 = 0.f, se1 = 0.f, se2 = 0.f;
    int j = start;
    for (; j + 1 < end; j += 2) {
        int eA = g_perm[j], eB = g_perm[j + 1];
        int sA = ei[eA], sB = ei[eB];
        float eA0 = ea[3 * eA + 0], eA1 = ea[3 * eA + 1], eA2 = ea[3 * eA + 2];
        float eB0 = ea[3 * eB + 0], eB1 = ea[3 * eB + 1], eB2 = ea[3 * eB + 2];
        float qA = g_q2[sA], qB = g_q2[sB];
        float4 vA = *(const float4*)&g_p2[(size_t)sA * HID + lane * 4];
        float4 vB = *(const float4*)&g_p2[(size_t)sB * HID + lane * 4];
        float lgA = q1d + qA + eA0 * aw0 + eA1 * aw1 + eA2 * aw2 + ab;
        float lgB = q1d + qB + eB0 * aw0 + eB1 * aw1 + eB2 * aw2 + ab;
        float alA = 1.f / (1.f + expf(-lgA));
        float alB = 1.f / (1.f + expf(-lgB));
        a0 += alA * vA.x + alB * vB.x;
        a1 += alA * vA.y + alB * vB.y;
        a2 += alA * vA.z + alB * vB.z;
        a3 += alA * vA.w + alB * vB.w;
        sa += alA + alB;
        se0 += alA * eA0 + alB * eB0;
        se1 += alA * eA1 + alB * eB1;
        se2 += alA * eA2 + alB * eB2;
    }
    if (j < end) {
        int e = g_perm[j];
        int src = ei[e];
        float e0 = ea[3 * e + 0], e1 = ea[3 * e + 1], e2 = ea[3 * e + 2];
        float lg = q1d + g_q2[src] + e0 * aw0 + e1 * aw1 + e2 * aw2 + ab;
        float al = 1.f / (1.f + expf(-lg));
        float4 v2 = *(const float4*)&g_p2[(size_t)src * HID + lane * 4];
        a0 += al * v2.x; a1 += al * v2.y; a2 += al * v2.z; a3 += al * v2.w;
        sa += al; se0 += al * e0; se1 += al * e1; se2 += al * e2;
    }
    int c = lane * 4;
    float4 p1v = *(const float4*)&g_p1[(size_t)node * HID + c];
    float4 r;
    r.x = a0 + se0 * s_w0[c + 0] + se1 * s_w1[c + 0] + se2 * s_w2[c + 0] + sa * (p1v.x + s_lb[c + 0]);
    r.y = a1 + se0 * s_w0[c + 1] + se1 * s_w1[c + 1] + se2 * s_w2[c + 1] + sa * (p1v.y + s_lb[c + 1]);
    r.z = a2 + se0 * s_w0[c + 2] + se1 * s_w1[c + 2] + se2 * s_w2[c + 2] + sa * (p1v.z + s_lb[c + 2]);
    r.w = a3 + se0 * s_w0[c + 3] + se1 * s_w1[c + 3] + se2 * s_w2[c + 3] + sa * (p1v.w + s_lb[c + 3]);
    *(float4*)&g_hconv[(size_t)node * HID + c] = r;
}

// ==================== small kernels ====================
__global__ void pool_init_kernel() {
    int i = blockIdx.x * blockDim.x + threadIdx.x;
    int stride = gridDim.x * blockDim.x;
    for (int j = i; j < NB * HID; j += stride) g_pooled[j] = 0.f;
    if (i == 0) { g_umax = 0u; g_sumexp = 0.f; }
}

__global__ void node_embed_kernel(const float* __restrict__ x,
                                  const float* __restrict__ w,
                                  const float* __restrict__ b) {
    int idx = blockIdx.x * blockDim.x + threadIdx.x;
    if (idx >= NN * HID) return;
    int n = idx >> 7, c = idx & 127;
    float v = b[c];
    v += x[n * 4 + 0] * w[0 * HID + c];
    v += x[n * 4 + 1] * w[1 * HID + c];
    v += x[n * 4 + 2] * w[2 * HID + c];
    v += x[n * 4 + 3] * w[3 * HID + c];
    g_h[idx] = v;
    bf16 hi = __float2bfloat16(v);
    g_hhi[idx] = hi;
    g_hlo[idx] = __float2bfloat16(v - __bfloat162float(hi));
}

// fk_w [l][f][i][n] -> g_Wfk [l][n][k = i*8+f] (hi/lo bf16)
__global__ void conv_fkw_kernel(const float* __restrict__ fkw) {
    int idx = blockIdx.x * blockDim.x + threadIdx.x;
    if (idx >= DEPTH * KFK * HID) return;
    int l = idx / (KFK * HID);
    int rem = idx - l * (KFK * HID);
    int kold = rem >> 7;       // f*128 + i
    int n = rem & 127;
    int f = kold >> 7, i = kold & 127;
    float w = fkw[((size_t)l * KFK + kold) * HID + n];
    bf16 hi = __float2bfloat16(w);
    bf16 lo = __float2bfloat16(w - __bfloat162float(hi));
    size_t o = ((size_t)l * HID + n) * KFK + (i * 8 + f);
    g_Wfk_hi[o] = hi;
    g_Wfk_lo[o] = lo;
}

__global__ void conv_linw_kernel(const float* __restrict__ linw) {
    int idx = blockIdx.x * blockDim.x + threadIdx.x;
    if (idx >= DEPTH * 2 * HID * HID) return;
    int l = idx / (2 * HID * HID);
    int rem = idx - l * (2 * HID * HID);
    int p = rem >> 14;
    int nk = rem & 16383;
    int n = nk >> 7, k = nk & 127;
    float w = linw[((size_t)l * 259 + p * 128 + k) * HID + n];
    bf16 hi = __float2bfloat16(w);
    bf16 lo = __float2bfloat16(w - __bfloat162float(hi));
    size_t o = (((size_t)l * 2 + p) * HID + n) * HID + k;
    g_Wlin_hi[o] = hi;
    g_Wlin_lo[o] = lo;
}

// NOTE: attw = att_w + l*259 NOT 16B-aligned for l>0 -> scalar loads.
__global__ void q_kernel(const float* __restrict__ h, const float* __restrict__ attw) {
    int gwarp = (blockIdx.x * blockDim.x + threadIdx.x) >> 5;
    int lane = threadIdx.x & 31;
    if (gwarp >= NN) return;
    float4 hv = *(const float4*)&h[(size_t)gwarp * HID + lane * 4];
    int c = lane * 4;
    float a10 = attw[c + 0], a11 = attw[c + 1], a12 = attw[c + 2], a13 = attw[c + 3];
    float a20 = attw[HID + c + 0], a21 = attw[HID + c + 1], a22 = attw[HID + c + 2], a23 = attw[HID + c + 3];
    float s1 = hv.x * a10 + hv.y * a11 + hv.z * a12 + hv.w * a13;
    float s2 = hv.x * a20 + hv.y * a21 + hv.z * a22 + hv.w * a23;
#pragma unroll
    for (int o = 16; o > 0; o >>= 1) {
        s1 += __shfl_xor_sync(0xffffffffu, s1, o);
        s2 += __shfl_xor_sync(0xffffffffu, s2, o);
    }
    if (lane == 0) { g_q1[gwarp] = s1; g_q2[gwarp] = s2; }
}

// ==================== batchnorm ====================
__global__ void bn_stat_kernel(const float* __restrict__ h, int rows_per_block) {
    int c = threadIdx.x;
    int r0 = blockIdx.x * rows_per_block;
    int r1 = min(NN, r0 + rows_per_block);
    float s = 0.f, ss = 0.f;
    for (int r = r0; r < r1; ++r) {
        float v = h[(size_t)r * HID + c];
        s += v; ss += v * v;
    }
    atomicAdd(&g_stats[c], s);
    atomicAdd(&g_stats[HID + c], ss);
}

__global__ void bn_apply_kernel(float* __restrict__ h,
                                const float* __restrict__ g,
                                const float* __restrict__ b) {
    int idx = blockIdx.x * blockDim.x + threadIdx.x;
    if (idx >= NN * HID) return;
    int c = idx & 127;
    const float invN = 1.f / (float)NN;
    float mu = g_stats[c] * invN;
    float var = g_stats[HID + c] * invN - mu * mu;
    float rstd = rsqrtf(var + 1e-5f);
    float v = (h[idx] - mu) * rstd * g[c] + b[c];
    v = fmaxf(v, 0.f);
    h[idx] = v;
    bf16 hi = __float2bfloat16(v);
    g_hhi[idx] = hi;
    g_hlo[idx] = __float2bfloat16(v - __bfloat162float(hi));
}

// ==================== attention pooling ====================
__device__ __forceinline__ unsigned float_key(float f) {
    unsigned u = __float_as_uint(f);
    return (u & 0x80000000u) ? ~u : (u | 0x80000000u);
}

__global__ void pool_logit_kernel(const float* __restrict__ h,
                                  const float* __restrict__ pool_w,
                                  const float* __restrict__ pool_b) {
    int gwarp = (blockIdx.x * blockDim.x + threadIdx.x) >> 5;
    int lane = threadIdx.x & 31;
    if (gwarp >= NN) return;
    float4 hv = *(const float4*)&h[(size_t)gwarp * HID + lane * 4];
    float4 wv = *(const float4*)&pool_w[lane * 4];
    float s = hv.x * wv.x + hv.y * wv.y + hv.z * wv.z + hv.w * wv.w;
#pragma unroll
    for (int o = 16; o > 0; o >>= 1) s += __shfl_xor_sync(0xffffffffu, s, o);
    if (lane == 0) {
        s += pool_b[0];
        g_logits[gwarp] = s;
        atomicMax(&g_umax, float_key(s));
    }
}

__global__ void pool_sumexp_kernel() {
    unsigned k = g_umax;
    float maxv = (k & 0x80000000u) ? __uint_as_float(k ^ 0x80000000u)
                                   : __uint_as_float(~k);
    int i = blockIdx.x * blockDim.x + threadIdx.x;
    int stride = gridDim.x * blockDim.x;
    float local = 0.f;
    for (; i < NN; i += stride) local += expf(g_logits[i] - maxv);
#pragma unroll
    for (int o = 16; o > 0; o >>= 1) local += __shfl_xor_sync(0xffffffffu, local, o);
    __shared__ float ws[8];
    int lane = threadIdx.x & 31, wid = threadIdx.x >> 5;
    if (lane == 0) ws[wid] = local;
    __syncthreads();
    if (wid == 0) {
        float v = (lane < (blockDim.x >> 5)) ? ws[lane] : 0.f;
#pragma unroll
        for (int o = 16; o > 0; o >>= 1) v += __shfl_xor_sync(0xffffffffu, v, o);
        if (lane == 0) atomicAdd(&g_sumexp, v);
    }
}

__global__ void pool_scatter_kernel(const float* __restrict__ h,
                                    const int* __restrict__ batch) {
    int gwarp = (blockIdx.x * blockDim.x + threadIdx.x) >> 5;
    int lane = threadIdx.x & 31;
    if (gwarp >= NN) return;
    unsigned k = g_umax;
    float maxv = (k & 0x80000000u) ? __uint_as_float(k ^ 0x80000000u)
                                   : __uint_as_float(~k);
    float w = expf(g_logits[gwarp] - maxv) / g_sumexp;
    int b = batch[gwarp];
    int c = lane * 4;
    float4 hv = *(const float4*)&h[(size_t)gwarp * HID + c];
    float* outp = &g_pooled[b * HID + c];
    atomicAdd(outp + 0, w * hv.x);
    atomicAdd(outp + 1, w * hv.y);
    atomicAdd(outp + 2, w * hv.z);
    atomicAdd(outp + 3, w * hv.w);
}

// ==================== heads ====================
__global__ __launch_bounds__(128) void head_kernel(
    const float* __restrict__ sg_table, const int* __restrict__ sgidx,
    const float* __restrict__ hw1, const float* __restrict__ hb1,
    const float* __restrict__ w2e, const float* __restrict__ b2e,
    const float* __restrict__ w2s, const float* __restrict__ b2s,
    const float* __restrict__ w2c, const float* __restrict__ b2c,
    const float* __restrict__ w2m, const float* __restrict__ b2m,
    float* __restrict__ out)
{
    int b = blockIdx.x;
    int t = threadIdx.x;
    __shared__ float comb[2 * HID];
    __shared__ float z[HID];
    comb[t] = g_pooled[b * HID + t];
    comb[HID + t] = sg_table[sgidx[b] * HID + t];
    __syncthreads();

    const float* w2arr[4] = { w2e, w2s, w2c, w2m };
    const float* b2arr[4] = { b2e, b2s, b2c, b2m };
    const int od[4] = { 1, 3, 7, 3 };
    const int off[4] = { 0, NB * 1, NB * 4, NB * 11 };

    for (int i = 0; i < 4; ++i) {
        float accz = hb1[i * HID + t];
        const float* W = hw1 + (size_t)i * 2 * HID * HID;
#pragma unroll 8
        for (int j = 0; j < 2 * HID; ++j) accz += comb[j] * W[j * HID + t];
        z[t] = fmaxf(accz, 0.f);
        __syncthreads();
        if (t < od[i]) {
            const float* w2 = w2arr[i];
            float acc = b2arr[i][t];
            for (int j = 0; j < HID; ++j) acc += z[j] * w2[j * od[i] + t];
            out[off[i] + b * od[i] + t] = acc;
        }
        __syncthreads();
    }
}

// ==================== host ====================
extern "C" void kernel_launch(void* const* d_in, const int* in_sizes, int n_in,
                              void* d_out, int out_size) {
    const float* x        = (const float*)d_in[0];
    const int*   ei       = (const int*)d_in[1];
    const float* ea       = (const float*)d_in[2];
    const int*   batch    = (const int*)d_in[3];
    const int*   sgidx    = (const int*)d_in[4];
    const float* node_w   = (const float*)d_in[5];
    const float* node_b   = (const float*)d_in[6];
    const float* sg_table = (const float*)d_in[7];
    const float* lin_w    = (const float*)d_in[8];
    const float* lin_b    = (const float*)d_in[9];
    const float* att_w    = (const float*)d_in[10];
    const float* att_b    = (const float*)d_in[11];
    const float* fk_w     = (const float*)d_in[12];
    const float* fk_b     = (const float*)d_in[13];
    const float* bn_g     = (const float*)d_in[14];
    const float* bn_b     = (const float*)d_in[15];
    const float* pool_w   = (const float*)d_in[16];
    const float* pool_b   = (const float*)d_in[17];
    const float* head_w1  = (const float*)d_in[18];
    const float* head_b1  = (const float*)d_in[19];
    const float* w2e = (const float*)d_in[20];
    const float* b2e = (const float*)d_in[21];
    const float* w2s = (const float*)d_in[22];
    const float* b2s = (const float*)d_in[23];
    const float* w2c = (const float*)d_in[24];
    const float* b2c = (const float*)d_in[25];
    const float* w2m = (const float*)d_in[26];
    const float* b2m = (const float*)d_in[27];
    float* out = (float*)d_out;

    cudaFuncSetAttribute(mma_gemm_kernel, cudaFuncAttributeMaxDynamicSharedMemorySize,
                         GEMM_SMEM);
    cudaFuncSetAttribute(fk_gemm_kernel, cudaFuncAttributeMaxDynamicSharedMemorySize,
                         GEMM_SMEM);

    float *p_h, *p_p1, *p_p2, *p_hconv, *p_stats;
    bf16 *p_hhi, *p_hlo, *p_Wfk_hi, *p_Wfk_lo, *p_Wlin_hi, *p_Wlin_lo;
    int *p_count;
    cudaGetSymbolAddress((void**)&p_h, g_h);
    cudaGetSymbolAddress((void**)&p_p1, g_p1);
    cudaGetSymbolAddress((void**)&p_p2, g_p2);
    cudaGetSymbolAddress((void**)&p_hconv, g_hconv);
    cudaGetSymbolAddress((void**)&p_stats, g_stats);
    cudaGetSymbolAddress((void**)&p_hhi, g_hhi);
    cudaGetSymbolAddress((void**)&p_hlo, g_hlo);
    cudaGetSymbolAddress((void**)&p_Wfk_hi, g_Wfk_hi);
    cudaGetSymbolAddress((void**)&p_Wfk_lo, g_Wfk_lo);
    cudaGetSymbolAddress((void**)&p_Wlin_hi, g_Wlin_hi);
    cudaGetSymbolAddress((void**)&p_Wlin_lo, g_Wlin_lo);
    cudaGetSymbolAddress((void**)&p_count, g_count);

    const int elem_blocks = (NN * HID + 255) / 256;   // 10000
    const int warp_blocks = (NN + 7) / 8;             // 2500
    const int tile_blocks = (NN + 63) / 64;           // 313

    // CSR construction (edge_index is layer-invariant)
    cudaMemsetAsync(p_count, 0, NN * sizeof(int), 0);
    hist_kernel<<<(NE + 255) / 256, 256>>>(ei);
    scan_kernel<<<1, 1024>>>();
    cudaMemsetAsync(p_count, 0, NN * sizeof(int), 0);
    scatter_kernel<<<(NE + 255) / 256, 256>>>(ei);

    conv_fkw_kernel<<<(DEPTH * KFK * HID + 255) / 256, 256>>>(fk_w);
    conv_linw_kernel<<<(DEPTH * 2 * HID * HID + 255) / 256, 256>>>(lin_w);

    node_embed_kernel<<<elem_blocks, 256>>>(x, node_w, node_b);

    for (int l = 0; l < DEPTH; ++l) {
        const float* lw = lin_w + (size_t)l * 259 * HID;
        const float* lb = lin_b + (size_t)l * HID;
        const float* aw = att_w + (size_t)l * 259;
        const bf16* Wdst_hi = p_Wlin_hi + ((size_t)l * 2 + 0) * HID * HID;
        const bf16* Wdst_lo = p_Wlin_lo + ((size_t)l * 2 + 0) * HID * HID;
        const bf16* Wsrc_hi = p_Wlin_hi + ((size_t)l * 2 + 1) * HID * HID;
        const bf16* Wsrc_lo = p_Wlin_lo + ((size_t)l * 2 + 1) * HID * HID;

        mma_gemm_kernel<<<tile_blocks, 256, GEMM_SMEM>>>(
            p_hhi, p_hlo, Wdst_hi, Wdst_lo, nullptr, nullptr, p_p1, NN, HID);
        mma_gemm_kernel<<<tile_blocks, 256, GEMM_SMEM>>>(
            p_hhi, p_hlo, Wsrc_hi, Wsrc_lo, nullptr, nullptr, p_p2, NN, HID);
        q_kernel<<<warp_blocks, 256>>>(p_h, aw);
        edge_csr_kernel<<<warp_blocks, 256>>>(ei, ea, lw, lb, aw, att_b, l);
        // FK branch: Fourier features generated in-kernel; out aliases h (safe per-CTA)
        fk_gemm_kernel<<<tile_blocks, 256, GEMM_SMEM>>>(
            p_h, p_Wfk_hi + (size_t)l * HID * KFK, p_Wfk_lo + (size_t)l * HID * KFK,
            fk_b + (size_t)l * HID, p_hconv, p_h, NN);
        cudaMemsetAsync(p_stats, 0, 2 * HID * sizeof(float), 0);
        bn_stat_kernel<<<160, 128>>>(p_h, (NN + 159) / 160);
        bn_apply_kernel<<<elem_blocks, 256>>>(p_h, bn_g + (size_t)l * HID, bn_b + (size_t)l * HID);
    }

    pool_init_kernel<<<32, 256>>>();
    pool_logit_kernel<<<warp_blocks, 256>>>(p_h, pool_w, pool_b);
    pool_sumexp_kernel<<<80, 256>>>();
    pool_scatter_kernel<<<warp_blocks, 256>>>(p_h, batch);

    head_kernel<<<NB, 128>>>(sg_table, sgidx, head_w1, head_b1,
                             w2e, b2e, w2s, b2s, w2c, b2c, w2m, b2m, out);
}

// round 14
// speedup vs baseline: 2.7494x; 1.1026x over previous
#include <cuda_runtime.h>
#include <cuda_bf16.h>
#include <math.h>
#include <stdint.h>

#define NN 20000
#define MPAD 20096          // 314 * 64
#define NE 320000
#define NB 64
#define HID 128
#define DEPTH 4
#define NFREQ 8
#define KFK (NFREQ * HID)   // 1024
#define TWO_PI_F 6.283185307179586f
#define TILE_BLOCKS 313

typedef __nv_bfloat16 bf16;

// ==================== scratch (static device allocations) ====================
__device__ float g_h[MPAD * HID];
__device__ float g_p12[2 * NN * HID];             // p1 | p2
__device__ float g_hconv[NN * HID];
__device__ bf16 g_hhi[MPAD * HID];
__device__ bf16 g_hlo[MPAD * HID];
__device__ bf16 g_Wfk_hi[DEPTH * HID * KFK];      // [l][n][k = i*8+f]
__device__ bf16 g_Wfk_lo[DEPTH * HID * KFK];
__device__ bf16 g_Wlin_hi[DEPTH * 2 * HID * HID]; // [l][part][n][k]
__device__ bf16 g_Wlin_lo[DEPTH * 2 * HID * HID];
__device__ float g_q1[NN];
__device__ float g_q2[NN];
__device__ float g_logits[NN];
__device__ float g_stats[2 * HID];
__device__ float g_pooled[NB * HID];
__device__ unsigned g_umax;
__device__ float g_sumexp;
// CSR (built once per launch)
__device__ int g_count[NN];
__device__ int g_rowstart[NN + 1];
__device__ int g_perm[NE];
__device__ int g_esrc[NE];                        // src in CSR order
__device__ float4 g_eax[NE];                      // edge_attr (xyz) in CSR order

// ==================== mma.sync / cp.async helpers ====================
__device__ __forceinline__ uint32_t smem_to_u32(const void* p) {
    uint32_t a;
    asm("{ .reg .u64 t; cvta.to.shared.u64 t, %1; cvt.u32.u64 %0, t; }" : "=r"(a) : "l"(p));
    return a;
}

#define LDSM4(r, addr) \
    asm volatile("ldmatrix.sync.aligned.m8n8.x4.shared.b16 {%0,%1,%2,%3}, [%4];" \
        : "=r"((r)[0]), "=r"((r)[1]), "=r"((r)[2]), "=r"((r)[3]) : "r"(addr))

#define MMA_BF16(c, a, b0, b1) \
    asm volatile("mma.sync.aligned.m16n8k16.row.col.f32.bf16.bf16.f32 " \
        "{%0,%1,%2,%3}, {%4,%5,%6,%7}, {%8,%9}, {%0,%1,%2,%3};" \
        : "+f"((c)[0]), "+f"((c)[1]), "+f"((c)[2]), "+f"((c)[3]) \
        : "r"((a)[0]), "r"((a)[1]), "r"((a)[2]), "r"((a)[3]), "r"(b0), "r"(b1))

__device__ __forceinline__ void cp16(uint32_t dst, const void* src) {
    asm volatile("cp.async.cg.shared.global [%0], [%1], 16;" :: "r"(dst), "l"(src));
}
#define CP_COMMIT() asm volatile("cp.async.commit_group;" ::: "memory")
#define CP_WAIT(n)  asm volatile("cp.async.wait_group %0;" :: "n"(n) : "memory")

#define BKP 72
#define A_MAT_B (64 * BKP * 2)                  // 9216
#define B_MAT_B (128 * BKP * 2)                 // 18432
#define STAGE_BYTES (2 * A_MAT_B + 2 * B_MAT_B) // 55296
#define GEMM_SMEM (2 * STAGE_BYTES)             // 110592

// ==================== shared MMA core ====================
struct AccT { float a[2][4][4]; };

__device__ __forceinline__ void mma_chunk(uint32_t sb, int lane, int warp_m, int warp_n,
                                          AccT& acc) {
    uint32_t uAhi = sb;
    uint32_t uAlo = sb + A_MAT_B;
    uint32_t uBhi = sb + 2 * A_MAT_B;
    uint32_t uBlo = sb + 2 * A_MAT_B + B_MAT_B;
#pragma unroll
    for (int ks = 0; ks < 4; ++ks) {
        uint32_t ahi[2][4], alo[2][4];
#pragma unroll
        for (int mt = 0; mt < 2; ++mt) {
            int r = warp_m * 32 + mt * 16 + (lane & 15);
            int cc = ks * 16 + ((lane >> 4) << 3);
            uint32_t off = (uint32_t)(r * BKP + cc) * 2;
            LDSM4(ahi[mt], uAhi + off);
            LDSM4(alo[mt], uAlo + off);
        }
#pragma unroll
        for (int np = 0; np < 2; ++np) {
            int j = lane >> 3;
            int rn = warp_n * 32 + np * 16 + ((j >> 1) << 3) + (lane & 7);
            int cn = ks * 16 + ((j & 1) << 3);
            uint32_t off = (uint32_t)(rn * BKP + cn) * 2;
            uint32_t bhi[4], blo[4];
            LDSM4(bhi, uBhi + off);
            LDSM4(blo, uBlo + off);
#pragma unroll
            for (int mt = 0; mt < 2; ++mt) {
                MMA_BF16(acc.a[mt][2 * np],     ahi[mt], bhi[0], bhi[1]);
                MMA_BF16(acc.a[mt][2 * np],     alo[mt], bhi[0], bhi[1]);
                MMA_BF16(acc.a[mt][2 * np],     ahi[mt], blo[0], blo[1]);
                MMA_BF16(acc.a[mt][2 * np + 1], ahi[mt], bhi[2], bhi[3]);
                MMA_BF16(acc.a[mt][2 * np + 1], alo[mt], bhi[2], bhi[3]);
                MMA_BF16(acc.a[mt][2 * np + 1], ahi[mt], blo[2], blo[3]);
            }
        }
    }
}

__device__ __forceinline__ void epilogue(const AccT& acc, int m0, int lane,
                                         int warp_m, int warp_n,
                                         const float* bias, const float* add,
                                         float* out, int M) {
#pragma unroll
    for (int mt = 0; mt < 2; ++mt) {
        int r0 = m0 + warp_m * 32 + mt * 16 + (lane >> 2);
        int r1 = r0 + 8;
#pragma unroll
        for (int nt = 0; nt < 4; ++nt) {
            int c = warp_n * 32 + nt * 8 + 2 * (lane & 3);
            float bx = 0.f, by = 0.f;
            if (bias) { float2 bv = *(const float2*)&bias[c]; bx = bv.x; by = bv.y; }
            if (r0 < M) {
                float vx = acc.a[mt][nt][0] + bx, vy = acc.a[mt][nt][1] + by;
                if (add) {
                    float2 av = *(const float2*)&add[(size_t)r0 * HID + c];
                    vx += av.x; vy += av.y;
                }
                float2 o; o.x = vx; o.y = vy;
                *(float2*)&out[(size_t)r0 * HID + c] = o;
            }
            if (r1 < M) {
                float vx = acc.a[mt][nt][2] + bx, vy = acc.a[mt][nt][3] + by;
                if (add) {
                    float2 av = *(const float2*)&add[(size_t)r1 * HID + c];
                    vx += av.x; vy += av.y;
                }
                float2 o; o.x = vx; o.y = vy;
                *(float2*)&out[(size_t)r1 * HID + c] = o;
            }
        }
    }
}

// ==================== merged p1/p2 GEMM (K=128, B picked by blockIdx) ============
__global__ __launch_bounds__(256, 2) void mma_gemm2_kernel(
    const bf16* __restrict__ Ahi, const bf16* __restrict__ Alo,
    const bf16* __restrict__ Bhi0, const bf16* __restrict__ Blo0,
    float* __restrict__ out0, int M)
{
    extern __shared__ __align__(16) char sm[];
    uint32_t smem_base = smem_to_u32(sm);
    int tid = threadIdx.x, lane = tid & 31, wid = tid >> 5;
    int warp_m = wid & 1;
    int warp_n = wid >> 1;
    int sel = (blockIdx.x >= TILE_BLOCKS) ? 1 : 0;
    int m0 = (blockIdx.x - sel * TILE_BLOCKS) * 64;
    const bf16* Bhi = Bhi0 + (size_t)sel * HID * HID;
    const bf16* Blo = Blo0 + (size_t)sel * HID * HID;
    float* out = out0 + (size_t)sel * NN * HID;
    const int K = HID;

    AccT acc;
#pragma unroll
    for (int mt = 0; mt < 2; ++mt)
#pragma unroll
        for (int nt = 0; nt < 4; ++nt)
#pragma unroll
            for (int j = 0; j < 4; ++j) acc.a[mt][nt][j] = 0.f;

    auto load_stage = [&](int stage, int k0) {
        uint32_t sbase = smem_base + stage * STAGE_BYTES;
#pragma unroll
        for (int it = 0; it < 12; ++it) {
            int idx = tid + it * 256;
            const bf16* src;
            uint32_t dst;
            if (idx < 1024) {
                int amat = idx >> 9;
                int rem = idx & 511;
                int row = rem >> 3, seg = rem & 7;
                src = (amat ? Alo : Ahi) + (size_t)(m0 + row) * K + k0 + seg * 8;
                dst = sbase + amat * A_MAT_B + (uint32_t)(row * BKP + seg * 8) * 2;
            } else {
                int idx2 = idx - 1024;
                int bmat = idx2 >> 10;
                int rem = idx2 & 1023;
                int row = rem >> 3, seg = rem & 7;
                src = (bmat ? Blo : Bhi) + (size_t)row * K + k0 + seg * 8;
                dst = sbase + 2 * A_MAT_B + bmat * B_MAT_B + (uint32_t)(row * BKP + seg * 8) * 2;
            }
            cp16(dst, src);
        }
    };

    load_stage(0, 0);
    CP_COMMIT();
    for (int c = 0; c < 2; ++c) {
        if (c == 0) {
            load_stage(1, 64);
            CP_COMMIT();
            CP_WAIT(1);
        } else {
            CP_WAIT(0);
        }
        __syncthreads();
        mma_chunk(smem_base + (c & 1) * STAGE_BYTES, lane, warp_m, warp_n, acc);
        __syncthreads();
    }
    epilogue(acc, m0, lane, warp_m, warp_n, nullptr, nullptr, out, M);
}

// ==================== FK GEMM with in-kernel Fourier features ====================
__global__ __launch_bounds__(256, 2) void fk_gemm_kernel(
    const float* __restrict__ h,
    const bf16* __restrict__ Bhi, const bf16* __restrict__ Blo,
    const float* __restrict__ bias, const float* __restrict__ add,
    float* __restrict__ out, int M)
{
    extern __shared__ __align__(16) char sm[];
    uint32_t smem_base = smem_to_u32(sm);
    int tid = threadIdx.x, lane = tid & 31, wid = tid >> 5;
    int warp_m = wid & 1;
    int warp_n = wid >> 1;
    int m0 = blockIdx.x * 64;
    const int K = KFK;

    AccT acc;
#pragma unroll
    for (int mt = 0; mt < 2; ++mt)
#pragma unroll
        for (int nt = 0; nt < 4; ++nt)
#pragma unroll
            for (int j = 0; j < 4; ++j) acc.a[mt][nt][j] = 0.f;

    auto load_B = [&](int stage, int k0) {
        uint32_t sbase = smem_base + stage * STAGE_BYTES + 2 * A_MAT_B;
#pragma unroll
        for (int it = 0; it < 8; ++it) {
            int idx = tid + it * 256;
            int bmat = idx >> 10;
            int rem = idx & 1023;
            int row = rem >> 3, seg = rem & 7;
            const bf16* src = (bmat ? Blo : Bhi) + (size_t)row * K + k0 + seg * 8;
            uint32_t dst = sbase + bmat * B_MAT_B + (uint32_t)(row * BKP + seg * 8) * 2;
            cp16(dst, src);
        }
    };

    auto compute_A = [&](int stage, int c) {
        uint32_t aHi = smem_base + stage * STAGE_BYTES;
        uint32_t aLo = aHi + A_MAT_B;
        int i0 = c << 3;
#pragma unroll
        for (int half = 0; half < 2; ++half) {
            int p = tid + half * 256;
            int row = p >> 3, il = p & 7;
            float hv = h[(size_t)(m0 + row) * HID + i0 + il];
            float th = TWO_PI_F * hv;
            float s1, c1;
            __sincosf(th, &s1, &c1);
            float s = s1, cc = c1;
            uint32_t hi4[4], lo4[4];
#pragma unroll
            for (int fp = 0; fp < 4; ++fp) {
                float v0 = s + cc;
                float s2 = s * c1 + cc * s1;
                float c2 = cc * c1 - s * s1;
                s = s2; cc = c2;
                float v1 = s + cc;
                s2 = s * c1 + cc * s1;
                c2 = cc * c1 - s * s1;
                s = s2; cc = c2;
                bf16 h0 = __float2bfloat16(v0);
                bf16 h1 = __float2bfloat16(v1);
                bf16 l0 = __float2bfloat16(v0 - __bfloat162float(h0));
                bf16 l1 = __float2bfloat16(v1 - __bfloat162float(h1));
                hi4[fp] = (uint32_t)__bfloat16_as_ushort(h0) |
                          ((uint32_t)__bfloat16_as_ushort(h1) << 16);
                lo4[fp] = (uint32_t)__bfloat16_as_ushort(l0) |
                          ((uint32_t)__bfloat16_as_ushort(l1) << 16);
            }
            uint32_t off = (uint32_t)(row * BKP + il * 8) * 2;
            asm volatile("st.shared.v4.b32 [%0], {%1,%2,%3,%4};"
                :: "r"(aHi + off), "r"(hi4[0]), "r"(hi4[1]), "r"(hi4[2]), "r"(hi4[3]));
            asm volatile("st.shared.v4.b32 [%0], {%1,%2,%3,%4};"
                :: "r"(aLo + off), "r"(lo4[0]), "r"(lo4[1]), "r"(lo4[2]), "r"(lo4[3]));
        }
    };

    const int nchunks = K >> 6;   // 16
    compute_A(0, 0);
    load_B(0, 0);
    CP_COMMIT();

    for (int c = 0; c < nchunks; ++c) {
        if (c + 1 < nchunks) {
            load_B((c + 1) & 1, (c + 1) << 6);
            CP_COMMIT();
            compute_A((c + 1) & 1, c + 1);
            CP_WAIT(1);
        } else {
            CP_WAIT(0);
        }
        __syncthreads();
        mma_chunk(smem_base + (c & 1) * STAGE_BYTES, lane, warp_m, warp_n, acc);
        __syncthreads();
    }
    epilogue(acc, m0, lane, warp_m, warp_n, bias, add, out, M);
}

// ==================== CSR construction ====================
__global__ void hist_kernel(const int* __restrict__ ei) {
    int e = blockIdx.x * blockDim.x + threadIdx.x;
    if (e < NE) atomicAdd(&g_count[ei[NE + e]], 1);
}

#define SCH 20
__global__ __launch_bounds__(1024) void scan_kernel() {
    int t = threadIdx.x;
    int base = t * SCH;
    int loc[SCH];
    int s = 0;
#pragma unroll
    for (int i = 0; i < SCH; ++i) {
        int n = base + i;
        int v = (n < NN) ? g_count[n] : 0;
        loc[i] = s;
        s += v;
    }
    int lane = t & 31, w = t >> 5;
    int ps = s;
#pragma unroll
    for (int o = 1; o < 32; o <<= 1) {
        int x = __shfl_up_sync(0xffffffffu, ps, o);
        if (lane >= o) ps += x;
    }
    __shared__ int wsum[32];
    if (lane == 31) wsum[w] = ps;
    __syncthreads();
    if (w == 0) {
        int x = wsum[lane];
#pragma unroll
        for (int o = 1; o < 32; o <<= 1) {
            int y = __shfl_up_sync(0xffffffffu, x, o);
            if (lane >= o) x += y;
        }
        wsum[lane] = x;
    }
    __syncthreads();
    int off = ps - s + (w > 0 ? wsum[w - 1] : 0);
#pragma unroll
    for (int i = 0; i < SCH; ++i) {
        int n = base + i;
        if (n < NN) g_rowstart[n] = off + loc[i];
    }
    if (t == 0) g_rowstart[NN] = NE;
}

__global__ void scatter_kernel(const int* __restrict__ ei) {
    int e = blockIdx.x * blockDim.x + threadIdx.x;
    if (e < NE) {
        int dst = ei[NE + e];
        int pos = g_rowstart[dst] + atomicAdd(&g_count[dst], 1);
        g_perm[pos] = e;
    }
}

// gather edge payloads into CSR order (once per launch)
__global__ void csr_gather_kernel(const int* __restrict__ ei, const float* __restrict__ ea) {
    int j = blockIdx.x * blockDim.x + threadIdx.x;
    if (j < NE) {
        int e = g_perm[j];
        g_esrc[j] = ei[e];
        float4 v;
        v.x = ea[3 * e + 0]; v.y = ea[3 * e + 1]; v.z = ea[3 * e + 2]; v.w = 0.f;
        g_eax[j] = v;
    }
}

// ==================== edge conv (CSR order, coalesced payloads) ====================
__global__ __launch_bounds__(256) void edge_csr_kernel(
    const float* __restrict__ linw, const float* __restrict__ linb,
    const float* __restrict__ attw, const float* __restrict__ attb_p, int l)
{
    __shared__ float s_w0[HID], s_w1[HID], s_w2[HID], s_lb[HID];
    __shared__ float s_awe[3];
    __shared__ float s_attb;
    int tid = threadIdx.x;
    if (tid < HID) {
        s_w0[tid] = linw[256 * HID + tid];
        s_w1[tid] = linw[257 * HID + tid];
        s_w2[tid] = linw[258 * HID + tid];
        s_lb[tid] = linb[tid];
    }
    if (tid < 3) s_awe[tid] = attw[256 + tid];
    if (tid == 3) s_attb = attb_p[l];
    __syncthreads();

    int node = blockIdx.x * 8 + (tid >> 5);
    int lane = tid & 31;
    int start = g_rowstart[node], end = g_rowstart[node + 1];
    float q1d = g_q1[node];
    float aw0 = s_awe[0], aw1 = s_awe[1], aw2 = s_awe[2], ab = s_attb;

    float a0 = 0.f, a1 = 0.f, a2 = 0.f, a3 = 0.f;
    float sa = 0.f, se0 = 0.f, se1 = 0.f, se2 = 0.f;
    int j = start;
    for (; j + 1 < end; j += 2) {
        int sA = g_esrc[j], sB = g_esrc[j + 1];
        float4 eA = g_eax[j], eB = g_eax[j + 1];
        float qA = g_q2[sA], qB = g_q2[sB];
        float4 vA = *(const float4*)&g_p12[(size_t)(NN + sA) * HID + lane * 4];
        float4 vB = *(const float4*)&g_p12[(size_t)(NN + sB) * HID + lane * 4];
        float lgA = q1d + qA + eA.x * aw0 + eA.y * aw1 + eA.z * aw2 + ab;
        float lgB = q1d + qB + eB.x * aw0 + eB.y * aw1 + eB.z * aw2 + ab;
        float alA = 1.f / (1.f + __expf(-lgA));
        float alB = 1.f / (1.f + __expf(-lgB));
        a0 += alA * vA.x + alB * vB.x;
        a1 += alA * vA.y + alB * vB.y;
        a2 += alA * vA.z + alB * vB.z;
        a3 += alA * vA.w + alB * vB.w;
        sa += alA + alB;
        se0 += alA * eA.x + alB * eB.x;
        se1 += alA * eA.y + alB * eB.y;
        se2 += alA * eA.z + alB * eB.z;
    }
    if (j < end) {
        int src = g_esrc[j];
        float4 e4 = g_eax[j];
        float lg = q1d + g_q2[src] + e4.x * aw0 + e4.y * aw1 + e4.z * aw2 + ab;
        float al = 1.f / (1.f + __expf(-lg));
        float4 v2 = *(const float4*)&g_p12[(size_t)(NN + src) * HID + lane * 4];
        a0 += al * v2.x; a1 += al * v2.y; a2 += al * v2.z; a3 += al * v2.w;
        sa += al; se0 += al * e4.x; se1 += al * e4.y; se2 += al * e4.z;
    }
    int c = lane * 4;
    float4 p1v = *(const float4*)&g_p12[(size_t)node * HID + c];
    float4 r;
    r.x = a0 + se0 * s_w0[c + 0] + se1 * s_w1[c + 0] + se2 * s_w2[c + 0] + sa * (p1v.x + s_lb[c + 0]);
    r.y = a1 + se0 * s_w0[c + 1] + se1 * s_w1[c + 1] + se2 * s_w2[c + 1] + sa * (p1v.y + s_lb[c + 1]);
    r.z = a2 + se0 * s_w0[c + 2] + se1 * s_w1[c + 2] + se2 * s_w2[c + 2] + sa * (p1v.z + s_lb[c + 2]);
    r.w = a3 + se0 * s_w0[c + 3] + se1 * s_w1[c + 3] + se2 * s_w2[c + 3] + sa * (p1v.w + s_lb[c + 3]);
    *(float4*)&g_hconv[(size_t)node * HID + c] = r;
}

// ==================== init / embed ====================
__global__ void pool_init_kernel() {
    int i = blockIdx.x * blockDim.x + threadIdx.x;
    int stride = gridDim.x * blockDim.x;
    for (int j = i; j < NB * HID; j += stride) g_pooled[j] = 0.f;
    if (i == 0) { g_umax = 0u; g_sumexp = 0.f; }
}

// warp per row: h = x@node_w + node_b, split bf16, and q for layer 0
__global__ __launch_bounds__(256) void node_embed_q_kernel(
    const float* __restrict__ x, const float* __restrict__ w,
    const float* __restrict__ b, const float* __restrict__ attw) {
    int row = (blockIdx.x * blockDim.x + threadIdx.x) >> 5;
    int lane = threadIdx.x & 31;
    if (row >= NN) return;
    int c = lane * 4;
    float4 xv = *(const float4*)&x[row * 4];
    float v[4];
#pragma unroll
    for (int jj = 0; jj < 4; ++jj) {
        int cc = c + jj;
        v[jj] = b[cc] + xv.x * w[cc] + xv.y * w[HID + cc]
              + xv.z * w[2 * HID + cc] + xv.w * w[3 * HID + cc];
    }
    size_t o = (size_t)row * HID + c;
    *(float4*)&g_h[o] = make_float4(v[0], v[1], v[2], v[3]);
    uint32_t hp[2], lp[2];
#pragma unroll
    for (int half = 0; half < 2; ++half) {
        bf16 h0 = __float2bfloat16(v[2 * half]);
        bf16 h1 = __float2bfloat16(v[2 * half + 1]);
        bf16 l0 = __float2bfloat16(v[2 * half] - __bfloat162float(h0));
        bf16 l1 = __float2bfloat16(v[2 * half + 1] - __bfloat162float(h1));
        hp[half] = (uint32_t)__bfloat16_as_ushort(h0) | ((uint32_t)__bfloat16_as_ushort(h1) << 16);
        lp[half] = (uint32_t)__bfloat16_as_ushort(l0) | ((uint32_t)__bfloat16_as_ushort(l1) << 16);
    }
    *(uint2*)&g_hhi[o] = make_uint2(hp[0], hp[1]);
    *(uint2*)&g_hlo[o] = make_uint2(lp[0], lp[1]);
    float s1 = v[0] * attw[c] + v[1] * attw[c + 1] + v[2] * attw[c + 2] + v[3] * attw[c + 3];
    float s2 = v[0] * attw[HID + c] + v[1] * attw[HID + c + 1]
             + v[2] * attw[HID + c + 2] + v[3] * attw[HID + c + 3];
#pragma unroll
    for (int o2 = 16; o2 > 0; o2 >>= 1) {
        s1 += __shfl_xor_sync(0xffffffffu, s1, o2);
        s2 += __shfl_xor_sync(0xffffffffu, s2, o2);
    }
    if (lane == 0) { g_q1[row] = s1; g_q2[row] = s2; }
}

// ==================== weight conversions ====================
// fk_w [l][f][i][n] -> g_Wfk [l][n][k = i*8+f]; coalesced writes (uint4), gather reads
__global__ void conv_fkw_kernel(const float* __restrict__ fkw) {
    int idx = blockIdx.x * blockDim.x + threadIdx.x;   // (l, n, i)
    if (idx >= DEPTH * HID * HID) return;
    int l = idx >> 14;
    int rem = idx & 16383;
    int n = rem >> 7, i = rem & 127;
    uint32_t hi4[4], lo4[4];
#pragma unroll
    for (int fp = 0; fp < 4; ++fp) {
        float w0 = fkw[(((size_t)l * NFREQ + 2 * fp) * HID + i) * HID + n];
        float w1 = fkw[(((size_t)l * NFREQ + 2 * fp + 1) * HID + i) * HID + n];
        bf16 h0 = __float2bfloat16(w0);
        bf16 h1 = __float2bfloat16(w1);
        bf16 l0 = __float2bfloat16(w0 - __bfloat162float(h0));
        bf16 l1 = __float2bfloat16(w1 - __bfloat162float(h1));
        hi4[fp] = (uint32_t)__bfloat16_as_ushort(h0) | ((uint32_t)__bfloat16_as_ushort(h1) << 16);
        lo4[fp] = (uint32_t)__bfloat16_as_ushort(l0) | ((uint32_t)__bfloat16_as_ushort(l1) << 16);
    }
    size_t o = ((size_t)l * HID + n) * KFK + i * 8;
    *(uint4*)&g_Wfk_hi[o] = make_uint4(hi4[0], hi4[1], hi4[2], hi4[3]);
    *(uint4*)&g_Wfk_lo[o] = make_uint4(lo4[0], lo4[1], lo4[2], lo4[3]);
}

__global__ void conv_linw_kernel(const float* __restrict__ linw) {
    int idx = blockIdx.x * blockDim.x + threadIdx.x;
    if (idx >= DEPTH * 2 * HID * HID) return;
    int l = idx / (2 * HID * HID);
    int rem = idx - l * (2 * HID * HID);
    int p = rem >> 14;
    int nk = rem & 16383;
    int n = nk >> 7, k = nk & 127;
    float w = linw[((size_t)l * 259 + p * 128 + k) * HID + n];
    bf16 hi = __float2bfloat16(w);
    bf16 lo = __float2bfloat16(w - __bfloat162float(hi));
    size_t o = (((size_t)l * 2 + p) * HID + n) * HID + k;
    g_Wlin_hi[o] = hi;
    g_Wlin_lo[o] = lo;
}

// ==================== batchnorm ====================
__global__ void bn_stat_kernel(const float* __restrict__ h, int rows_per_block) {
    int c = threadIdx.x;
    int r0 = blockIdx.x * rows_per_block;
    int r1 = min(NN, r0 + rows_per_block);
    float s = 0.f, ss = 0.f;
    for (int r = r0; r < r1; ++r) {
        float v = h[(size_t)r * HID + c];
        s += v; ss += v * v;
    }
    atomicAdd(&g_stats[c], s);
    atomicAdd(&g_stats[HID + c], ss);
}

__device__ __forceinline__ unsigned float_key(float f) {
    unsigned u = __float_as_uint(f);
    return (u & 0x80000000u) ? ~u : (u | 0x80000000u);
}

// warp per row: BN + ReLU + bf16 split + next-layer q (wb!=null) or pool logit (wb==null)
__global__ __launch_bounds__(256) void bn_apply_q_kernel(
    float* __restrict__ h, const float* __restrict__ g, const float* __restrict__ b,
    const float* __restrict__ wa, const float* __restrict__ wb,
    const float* __restrict__ pb) {
    int row = (blockIdx.x * blockDim.x + threadIdx.x) >> 5;
    int lane = threadIdx.x & 31;
    if (row >= NN) return;
    int c = lane * 4;
    size_t o = (size_t)row * HID + c;
    float4 hv = *(const float4*)&h[o];
    float v[4] = { hv.x, hv.y, hv.z, hv.w };
    const float invN = 1.f / (float)NN;
#pragma unroll
    for (int jj = 0; jj < 4; ++jj) {
        int cc = c + jj;
        float mu = g_stats[cc] * invN;
        float var = g_stats[HID + cc] * invN - mu * mu;
        float rstd = rsqrtf(var + 1e-5f);
        v[jj] = fmaxf((v[jj] - mu) * rstd * g[cc] + b[cc], 0.f);
    }
    *(float4*)&h[o] = make_float4(v[0], v[1], v[2], v[3]);
    uint32_t hp[2], lp[2];
#pragma unroll
    for (int half = 0; half < 2; ++half) {
        bf16 h0 = __float2bfloat16(v[2 * half]);
        bf16 h1 = __float2bfloat16(v[2 * half + 1]);
        bf16 l0 = __float2bfloat16(v[2 * half] - __bfloat162float(h0));
        bf16 l1 = __float2bfloat16(v[2 * half + 1] - __bfloat162float(h1));
        hp[half] = (uint32_t)__bfloat16_as_ushort(h0) | ((uint32_t)__bfloat16_as_ushort(h1) << 16);
        lp[half] = (uint32_t)__bfloat16_as_ushort(l0) | ((uint32_t)__bfloat16_as_ushort(l1) << 16);
    }
    *(uint2*)&g_hhi[o] = make_uint2(hp[0], hp[1]);
    *(uint2*)&g_hlo[o] = make_uint2(lp[0], lp[1]);

    float s1 = v[0] * wa[c] + v[1] * wa[c + 1] + v[2] * wa[c + 2] + v[3] * wa[c + 3];
    if (wb) {
        float s2 = v[0] * wb[c] + v[1] * wb[c + 1] + v[2] * wb[c + 2] + v[3] * wb[c + 3];
#pragma unroll
        for (int o2 = 16; o2 > 0; o2 >>= 1) {
            s1 += __shfl_xor_sync(0xffffffffu, s1, o2);
            s2 += __shfl_xor_sync(0xffffffffu, s2, o2);
        }
        if (lane == 0) { g_q1[row] = s1; g_q2[row] = s2; }
    } else {
#pragma unroll
        for (int o2 = 16; o2 > 0; o2 >>= 1)
            s1 += __shfl_xor_sync(0xffffffffu, s1, o2);
        if (lane == 0) {
            s1 += pb[0];
            g_logits[row] = s1;
            atomicMax(&g_umax, float_key(s1));
        }
    }
}

// ==================== attention pooling tail ====================
__global__ void pool_sumexp_kernel() {
    unsigned k = g_umax;
    float maxv = (k & 0x80000000u) ? __uint_as_float(k ^ 0x80000000u)
                                   : __uint_as_float(~k);
    int i = blockIdx.x * blockDim.x + threadIdx.x;
    int stride = gridDim.x * blockDim.x;
    float local = 0.f;
    for (; i < NN; i += stride) local += __expf(g_logits[i] - maxv);
#pragma unroll
    for (int o = 16; o > 0; o >>= 1) local += __shfl_xor_sync(0xffffffffu, local, o);
    __shared__ float ws[8];
    int lane = threadIdx.x & 31, wid = threadIdx.x >> 5;
    if (lane == 0) ws[wid] = local;
    __syncthreads();
    if (wid == 0) {
        float v = (lane < (blockDim.x >> 5)) ? ws[lane] : 0.f;
#pragma unroll
        for (int o = 16; o > 0; o >>= 1) v += __shfl_xor_sync(0xffffffffu, v, o);
        if (lane == 0) atomicAdd(&g_sumexp, v);
    }
}

__global__ void pool_scatter_kernel(const float* __restrict__ h,
                                    const int* __restrict__ batch) {
    int gwarp = (blockIdx.x * blockDim.x + threadIdx.x) >> 5;
    int lane = threadIdx.x & 31;
    if (gwarp >= NN) return;
    unsigned k = g_umax;
    float maxv = (k & 0x80000000u) ? __uint_as_float(k ^ 0x80000000u)
                                   : __uint_as_float(~k);
    float w = __expf(g_logits[gwarp] - maxv) / g_sumexp;
    int b = batch[gwarp];
    int c = lane * 4;
    float4 hv = *(const float4*)&h[(size_t)gwarp * HID + c];
    float* outp = &g_pooled[b * HID + c];
    atomicAdd(outp + 0, w * hv.x);
    atomicAdd(outp + 1, w * hv.y);
    atomicAdd(outp + 2, w * hv.z);
    atomicAdd(outp + 3, w * hv.w);
}

// ==================== heads ====================
__global__ __launch_bounds__(128) void head_kernel(
    const float* __restrict__ sg_table, const int* __restrict__ sgidx,
    const float* __restrict__ hw1, const float* __restrict__ hb1,
    const float* __restrict__ w2e, const float* __restrict__ b2e,
    const float* __restrict__ w2s, const float* __restrict__ b2s,
    const float* __restrict__ w2c, const float* __restrict__ b2c,
    const float* __restrict__ w2m, const float* __restrict__ b2m,
    float* __restrict__ out)
{
    int b = blockIdx.x;
    int t = threadIdx.x;
    __shared__ float comb[2 * HID];
    __shared__ float z[HID];
    comb[t] = g_pooled[b * HID + t];
    comb[HID + t] = sg_table[sgidx[b] * HID + t];
    __syncthreads();

    const float* w2arr[4] = { w2e, w2s, w2c, w2m };
    const float* b2arr[4] = { b2e, b2s, b2c, b2m };
    const int od[4] = { 1, 3, 7, 3 };
    const int off[4] = { 0, NB * 1, NB * 4, NB * 11 };

    for (int i = 0; i < 4; ++i) {
        float accz = hb1[i * HID + t];
        const float* W = hw1 + (size_t)i * 2 * HID * HID;
#pragma unroll 8
        for (int j = 0; j < 2 * HID; ++j) accz += comb[j] * W[j * HID + t];
        z[t] = fmaxf(accz, 0.f);
        __syncthreads();
        if (t < od[i]) {
            const float* w2 = w2arr[i];
            float acc = b2arr[i][t];
            for (int j = 0; j < HID; ++j) acc += z[j] * w2[j * od[i] + t];
            out[off[i] + b * od[i] + t] = acc;
        }
        __syncthreads();
    }
}

// ==================== host ====================
extern "C" void kernel_launch(void* const* d_in, const int* in_sizes, int n_in,
                              void* d_out, int out_size) {
    const float* x        = (const float*)d_in[0];
    const int*   ei       = (const int*)d_in[1];
    const float* ea       = (const float*)d_in[2];
    const int*   batch    = (const int*)d_in[3];
    const int*   sgidx    = (const int*)d_in[4];
    const float* node_w   = (const float*)d_in[5];
    const float* node_b   = (const float*)d_in[6];
    const float* sg_table = (const float*)d_in[7];
    const float* lin_w    = (const float*)d_in[8];
    const float* lin_b    = (const float*)d_in[9];
    const float* att_w    = (const float*)d_in[10];
    const float* att_b    = (const float*)d_in[11];
    const float* fk_w     = (const float*)d_in[12];
    const float* fk_b     = (const float*)d_in[13];
    const float* bn_g     = (const float*)d_in[14];
    const float* bn_b     = (const float*)d_in[15];
    const float* pool_w   = (const float*)d_in[16];
    const float* pool_b   = (const float*)d_in[17];
    const float* head_w1  = (const float*)d_in[18];
    const float* head_b1  = (const float*)d_in[19];
    const float* w2e = (const float*)d_in[20];
    const float* b2e = (const float*)d_in[21];
    const float* w2s = (const float*)d_in[22];
    const float* b2s = (const float*)d_in[23];
    const float* w2c = (const float*)d_in[24];
    const float* b2c = (const float*)d_in[25];
    const float* w2m = (const float*)d_in[26];
    const float* b2m = (const float*)d_in[27];
    float* out = (float*)d_out;

    cudaFuncSetAttribute(mma_gemm2_kernel, cudaFuncAttributeMaxDynamicSharedMemorySize,
                         GEMM_SMEM);
    cudaFuncSetAttribute(fk_gemm_kernel, cudaFuncAttributeMaxDynamicSharedMemorySize,
                         GEMM_SMEM);

    float *p_h, *p_hconv, *p_stats;
    bf16 *p_hhi, *p_hlo, *p_Wfk_hi, *p_Wfk_lo, *p_Wlin_hi, *p_Wlin_lo;
    int *p_count;
    cudaGetSymbolAddress((void**)&p_h, g_h);
    cudaGetSymbolAddress((void**)&p_hconv, g_hconv);
    cudaGetSymbolAddress((void**)&p_stats, g_stats);
    cudaGetSymbolAddress((void**)&p_hhi, g_hhi);
    cudaGetSymbolAddress((void**)&p_hlo, g_hlo);
    cudaGetSymbolAddress((void**)&p_Wfk_hi, g_Wfk_hi);
    cudaGetSymbolAddress((void**)&p_Wfk_lo, g_Wfk_lo);
    cudaGetSymbolAddress((void**)&p_Wlin_hi, g_Wlin_hi);
    cudaGetSymbolAddress((void**)&p_Wlin_lo, g_Wlin_lo);
    cudaGetSymbolAddress((void**)&p_count, g_count);
    float* p_p12;
    cudaGetSymbolAddress((void**)&p_p12, g_p12);

    const int warp_blocks = (NN + 7) / 8;             // 2500

    // CSR construction + payload gather (edge_index is layer-invariant)
    cudaMemsetAsync(p_count, 0, NN * sizeof(int), 0);
    hist_kernel<<<(NE + 255) / 256, 256>>>(ei);
    scan_kernel<<<1, 1024>>>();
    cudaMemsetAsync(p_count, 0, NN * sizeof(int), 0);
    scatter_kernel<<<(NE + 255) / 256, 256>>>(ei);
    csr_gather_kernel<<<(NE + 255) / 256, 256>>>(ei, ea);

    conv_fkw_kernel<<<(DEPTH * HID * HID + 255) / 256, 256>>>(fk_w);
    conv_linw_kernel<<<(DEPTH * 2 * HID * HID + 255) / 256, 256>>>(lin_w);

    pool_init_kernel<<<32, 256>>>();
    node_embed_q_kernel<<<warp_blocks, 256>>>(x, node_w, node_b, att_w);

    for (int l = 0; l < DEPTH; ++l) {
        const float* lw = lin_w + (size_t)l * 259 * HID;
        const float* lb = lin_b + (size_t)l * HID;
        const float* aw = att_w + (size_t)l * 259;
        const bf16* Wlin_hi = p_Wlin_hi + (size_t)l * 2 * HID * HID;
        const bf16* Wlin_lo = p_Wlin_lo + (size_t)l * 2 * HID * HID;

        mma_gemm2_kernel<<<2 * TILE_BLOCKS, 256, GEMM_SMEM>>>(
            p_hhi, p_hlo, Wlin_hi, Wlin_lo, p_p12, NN);
        edge_csr_kernel<<<warp_blocks, 256>>>(lw, lb, aw, att_b, l);
        fk_gemm_kernel<<<TILE_BLOCKS, 256, GEMM_SMEM>>>(
            p_h, p_Wfk_hi + (size_t)l * HID * KFK, p_Wfk_lo + (size_t)l * HID * KFK,
            fk_b + (size_t)l * HID, p_hconv, p_h, NN);
        cudaMemsetAsync(p_stats, 0, 2 * HID * sizeof(float), 0);
        bn_stat_kernel<<<160, 128>>>(p_h, (NN + 159) / 160);
        if (l < DEPTH - 1) {
            const float* awn = att_w + (size_t)(l + 1) * 259;
            bn_apply_q_kernel<<<warp_blocks, 256>>>(
                p_h, bn_g + (size_t)l * HID, bn_b + (size_t)l * HID,
                awn, awn + HID, nullptr);
        } else {
            bn_apply_q_kernel<<<warp_blocks, 256>>>(
                p_h, bn_g + (size_t)l * HID, bn_b + (size_t)l * HID,
                pool_w, nullptr, pool_b);
        }
    }

    pool_sumexp_kernel<<<80, 256>>>();
    pool_scatter_kernel<<<warp_blocks, 256>>>(p_h, batch);

    head_kernel<<<NB, 128>>>(sg_table, sgidx, head_w1, head_b1,
                             w2e, b2e, w2s, b2s, w2c, b2c, w2m, b2m, out);
}

// round 15
// speedup vs baseline: 2.7929x; 1.0158x over previous
#include <cuda_runtime.h>
#include <cuda_bf16.h>
#include <math.h>
#include <stdint.h>

#define NN 20000
#define MPAD 20096          // 314 * 64
#define NE 320000
#define NB 64
#define HID 128
#define DEPTH 4
#define NFREQ 8
#define KFK (NFREQ * HID)   // 1024
#define TWO_PI_F 6.283185307179586f
#define TILE_BLOCKS 313

typedef __nv_bfloat16 bf16;

// ==================== scratch (static device allocations) ====================
__device__ float g_h[MPAD * HID];
__device__ float g_p12[2 * NN * HID];             // p1 | p2
__device__ float g_hconv[NN * HID];
__device__ bf16 g_Wfk_hi[DEPTH * HID * KFK];      // [l][n][k = i*8+f]
__device__ bf16 g_Wfk_lo[DEPTH * HID * KFK];
__device__ bf16 g_Wlin_hi[DEPTH * 2 * HID * HID]; // [l][part][n][k]
__device__ bf16 g_Wlin_lo[DEPTH * 2 * HID * HID];
__device__ float g_q1[NN];
__device__ float g_q2[NN];
__device__ float g_logits[NN];
__device__ float g_stats[2 * HID];                // [0:128) sum, [128:256) sumsq
__device__ float g_pooled[NB * HID];
__device__ unsigned g_umax;
__device__ float g_sumexp;
// CSR (built once per launch)
__device__ int g_count[NN];
__device__ int g_rowstart[NN + 1];
__device__ int g_perm[NE];
__device__ int g_esrc[NE];
__device__ float4 g_eax[NE];

// ==================== mma.sync / cp.async helpers ====================
__device__ __forceinline__ uint32_t smem_to_u32(const void* p) {
    uint32_t a;
    asm("{ .reg .u64 t; cvta.to.shared.u64 t, %1; cvt.u32.u64 %0, t; }" : "=r"(a) : "l"(p));
    return a;
}

#define LDSM4(r, addr) \
    asm volatile("ldmatrix.sync.aligned.m8n8.x4.shared.b16 {%0,%1,%2,%3}, [%4];" \
        : "=r"((r)[0]), "=r"((r)[1]), "=r"((r)[2]), "=r"((r)[3]) : "r"(addr))

#define MMA_BF16(c, a, b0, b1) \
    asm volatile("mma.sync.aligned.m16n8k16.row.col.f32.bf16.bf16.f32 " \
        "{%0,%1,%2,%3}, {%4,%5,%6,%7}, {%8,%9}, {%0,%1,%2,%3};" \
        : "+f"((c)[0]), "+f"((c)[1]), "+f"((c)[2]), "+f"((c)[3]) \
        : "r"((a)[0]), "r"((a)[1]), "r"((a)[2]), "r"((a)[3]), "r"(b0), "r"(b1))

__device__ __forceinline__ void cp16(uint32_t dst, const void* src) {
    asm volatile("cp.async.cg.shared.global [%0], [%1], 16;" :: "r"(dst), "l"(src));
}
#define CP_COMMIT() asm volatile("cp.async.commit_group;" ::: "memory")
#define CP_WAIT(n)  asm volatile("cp.async.wait_group %0;" :: "n"(n) : "memory")

#define BKP 72
#define A_MAT_B (64 * BKP * 2)                  // 9216
#define B_MAT_B (128 * BKP * 2)                 // 18432
#define STAGE_BYTES (2 * A_MAT_B + 2 * B_MAT_B) // 55296
#define GEMM_SMEM (2 * STAGE_BYTES)             // 110592

// pack 2 floats -> bf16 hi pair + lo pair
__device__ __forceinline__ void split2(float a, float b, uint32_t& hp, uint32_t& lp) {
    bf16 h0 = __float2bfloat16(a);
    bf16 h1 = __float2bfloat16(b);
    bf16 l0 = __float2bfloat16(a - __bfloat162float(h0));
    bf16 l1 = __float2bfloat16(b - __bfloat162float(h1));
    hp = (uint32_t)__bfloat16_as_ushort(h0) | ((uint32_t)__bfloat16_as_ushort(h1) << 16);
    lp = (uint32_t)__bfloat16_as_ushort(l0) | ((uint32_t)__bfloat16_as_ushort(l1) << 16);
}

// ==================== shared MMA core ====================
struct AccT { float a[2][4][4]; };

__device__ __forceinline__ void mma_chunk(uint32_t sb, int lane, int warp_m, int warp_n,
                                          AccT& acc) {
    uint32_t uAhi = sb;
    uint32_t uAlo = sb + A_MAT_B;
    uint32_t uBhi = sb + 2 * A_MAT_B;
    uint32_t uBlo = sb + 2 * A_MAT_B + B_MAT_B;
#pragma unroll
    for (int ks = 0; ks < 4; ++ks) {
        uint32_t ahi[2][4], alo[2][4];
#pragma unroll
        for (int mt = 0; mt < 2; ++mt) {
            int r = warp_m * 32 + mt * 16 + (lane & 15);
            int cc = ks * 16 + ((lane >> 4) << 3);
            uint32_t off = (uint32_t)(r * BKP + cc) * 2;
            LDSM4(ahi[mt], uAhi + off);
            LDSM4(alo[mt], uAlo + off);
        }
#pragma unroll
        for (int np = 0; np < 2; ++np) {
            int j = lane >> 3;
            int rn = warp_n * 32 + np * 16 + ((j >> 1) << 3) + (lane & 7);
            int cn = ks * 16 + ((j & 1) << 3);
            uint32_t off = (uint32_t)(rn * BKP + cn) * 2;
            uint32_t bhi[4], blo[4];
            LDSM4(bhi, uBhi + off);
            LDSM4(blo, uBlo + off);
#pragma unroll
            for (int mt = 0; mt < 2; ++mt) {
                MMA_BF16(acc.a[mt][2 * np],     ahi[mt], bhi[0], bhi[1]);
                MMA_BF16(acc.a[mt][2 * np],     alo[mt], bhi[0], bhi[1]);
                MMA_BF16(acc.a[mt][2 * np],     ahi[mt], blo[0], blo[1]);
                MMA_BF16(acc.a[mt][2 * np + 1], ahi[mt], bhi[2], bhi[3]);
                MMA_BF16(acc.a[mt][2 * np + 1], alo[mt], bhi[2], bhi[3]);
                MMA_BF16(acc.a[mt][2 * np + 1], ahi[mt], blo[2], blo[3]);
            }
        }
    }
}

__device__ __forceinline__ void epilogue(const AccT& acc, int m0, int lane,
                                         int warp_m, int warp_n,
                                         const float* bias, const float* add,
                                         float* out, int M) {
#pragma unroll
    for (int mt = 0; mt < 2; ++mt) {
        int r0 = m0 + warp_m * 32 + mt * 16 + (lane >> 2);
        int r1 = r0 + 8;
#pragma unroll
        for (int nt = 0; nt < 4; ++nt) {
            int c = warp_n * 32 + nt * 8 + 2 * (lane & 3);
            float bx = 0.f, by = 0.f;
            if (bias) { float2 bv = *(const float2*)&bias[c]; bx = bv.x; by = bv.y; }
            if (r0 < M) {
                float vx = acc.a[mt][nt][0] + bx, vy = acc.a[mt][nt][1] + by;
                if (add) {
                    float2 av = *(const float2*)&add[(size_t)r0 * HID + c];
                    vx += av.x; vy += av.y;
                }
                float2 o; o.x = vx; o.y = vy;
                *(float2*)&out[(size_t)r0 * HID + c] = o;
            }
            if (r1 < M) {
                float vx = acc.a[mt][nt][2] + bx, vy = acc.a[mt][nt][3] + by;
                if (add) {
                    float2 av = *(const float2*)&add[(size_t)r1 * HID + c];
                    vx += av.x; vy += av.y;
                }
                float2 o; o.x = vx; o.y = vy;
                *(float2*)&out[(size_t)r1 * HID + c] = o;
            }
        }
    }
}

// ==================== merged p1/p2 GEMM (A = fp32 h, split inline) ============
__global__ __launch_bounds__(256, 2) void mma_gemm2_kernel(
    const float* __restrict__ h,
    const bf16* __restrict__ Bhi0, const bf16* __restrict__ Blo0,
    float* __restrict__ out0, int M)
{
    extern __shared__ __align__(16) char sm[];
    uint32_t smem_base = smem_to_u32(sm);
    int tid = threadIdx.x, lane = tid & 31, wid = tid >> 5;
    int warp_m = wid & 1;
    int warp_n = wid >> 1;
    int sel = (blockIdx.x >= TILE_BLOCKS) ? 1 : 0;
    int m0 = (blockIdx.x - sel * TILE_BLOCKS) * 64;
    const bf16* Bhi = Bhi0 + (size_t)sel * HID * HID;
    const bf16* Blo = Blo0 + (size_t)sel * HID * HID;
    float* out = out0 + (size_t)sel * NN * HID;
    const int K = HID;

    AccT acc;
#pragma unroll
    for (int mt = 0; mt < 2; ++mt)
#pragma unroll
        for (int nt = 0; nt < 4; ++nt)
#pragma unroll
            for (int j = 0; j < 4; ++j) acc.a[mt][nt][j] = 0.f;

    auto load_B = [&](int stage, int k0) {
        uint32_t sbase = smem_base + stage * STAGE_BYTES + 2 * A_MAT_B;
#pragma unroll
        for (int it = 0; it < 8; ++it) {
            int idx = tid + it * 256;
            int bmat = idx >> 10;
            int rem = idx & 1023;
            int row = rem >> 3, seg = rem & 7;
            const bf16* src = (bmat ? Blo : Bhi) + (size_t)row * K + k0 + seg * 8;
            uint32_t dst = sbase + bmat * B_MAT_B + (uint32_t)(row * BKP + seg * 8) * 2;
            cp16(dst, src);
        }
    };

    // A: read fp32 h, split hi/lo inline. 64 rows x 16 float4 per chunk.
    auto load_A = [&](int stage, int k0) {
        uint32_t aHi = smem_base + stage * STAGE_BYTES;
        uint32_t aLo = aHi + A_MAT_B;
#pragma unroll
        for (int it = 0; it < 4; ++it) {
            int idx = tid + it * 256;
            int row = idx >> 4, s4 = idx & 15;
            float4 hv = *(const float4*)&h[(size_t)(m0 + row) * HID + k0 + s4 * 4];
            uint32_t hp0, lp0, hp1, lp1;
            split2(hv.x, hv.y, hp0, lp0);
            split2(hv.z, hv.w, hp1, lp1);
            uint32_t off = (uint32_t)(row * BKP + s4 * 4) * 2;
            asm volatile("st.shared.v2.b32 [%0], {%1,%2};" :: "r"(aHi + off), "r"(hp0), "r"(hp1));
            asm volatile("st.shared.v2.b32 [%0], {%1,%2};" :: "r"(aLo + off), "r"(lp0), "r"(lp1));
        }
    };

    load_B(0, 0);
    CP_COMMIT();
    load_A(0, 0);
    for (int c = 0; c < 2; ++c) {
        if (c == 0) {
            load_B(1, 64);
            CP_COMMIT();
            load_A(1, 64);
            CP_WAIT(1);
        } else {
            CP_WAIT(0);
        }
        __syncthreads();
        mma_chunk(smem_base + (c & 1) * STAGE_BYTES, lane, warp_m, warp_n, acc);
        __syncthreads();
    }
    epilogue(acc, m0, lane, warp_m, warp_n, nullptr, nullptr, out, M);
}

// ==================== FK GEMM: Fourier features in-kernel + BN stats in epilogue ====
__global__ __launch_bounds__(256, 2) void fk_gemm_kernel(
    const float* __restrict__ h,
    const bf16* __restrict__ Bhi, const bf16* __restrict__ Blo,
    const float* __restrict__ bias, const float* __restrict__ add,
    float* __restrict__ out, int M)
{
    extern __shared__ __align__(16) char sm[];
    uint32_t smem_base = smem_to_u32(sm);
    int tid = threadIdx.x, lane = tid & 31, wid = tid >> 5;
    int warp_m = wid & 1;
    int warp_n = wid >> 1;
    int m0 = blockIdx.x * 64;
    const int K = KFK;

    AccT acc;
#pragma unroll
    for (int mt = 0; mt < 2; ++mt)
#pragma unroll
        for (int nt = 0; nt < 4; ++nt)
#pragma unroll
            for (int j = 0; j < 4; ++j) acc.a[mt][nt][j] = 0.f;

    auto load_B = [&](int stage, int k0) {
        uint32_t sbase = smem_base + stage * STAGE_BYTES + 2 * A_MAT_B;
#pragma unroll
        for (int it = 0; it < 8; ++it) {
            int idx = tid + it * 256;
            int bmat = idx >> 10;
            int rem = idx & 1023;
            int row = rem >> 3, seg = rem & 7;
            const bf16* src = (bmat ? Blo : Bhi) + (size_t)row * K + k0 + seg * 8;
            uint32_t dst = sbase + bmat * B_MAT_B + (uint32_t)(row * BKP + seg * 8) * 2;
            cp16(dst, src);
        }
    };

    auto compute_A = [&](int stage, int c) {
        uint32_t aHi = smem_base + stage * STAGE_BYTES;
        uint32_t aLo = aHi + A_MAT_B;
        int i0 = c << 3;
#pragma unroll
        for (int half = 0; half < 2; ++half) {
            int p = tid + half * 256;
            int row = p >> 3, il = p & 7;
            float hv = h[(size_t)(m0 + row) * HID + i0 + il];
            float th = TWO_PI_F * hv;
            float s1, c1;
            __sincosf(th, &s1, &c1);
            float s = s1, cc = c1;
            uint32_t hi4[4], lo4[4];
#pragma unroll
            for (int fp = 0; fp < 4; ++fp) {
                float v0 = s + cc;
                float s2 = s * c1 + cc * s1;
                float c2 = cc * c1 - s * s1;
                s = s2; cc = c2;
                float v1 = s + cc;
                s2 = s * c1 + cc * s1;
                c2 = cc * c1 - s * s1;
                s = s2; cc = c2;
                split2(v0, v1, hi4[fp], lo4[fp]);
            }
            uint32_t off = (uint32_t)(row * BKP + il * 8) * 2;
            asm volatile("st.shared.v4.b32 [%0], {%1,%2,%3,%4};"
                :: "r"(aHi + off), "r"(hi4[0]), "r"(hi4[1]), "r"(hi4[2]), "r"(hi4[3]));
            asm volatile("st.shared.v4.b32 [%0], {%1,%2,%3,%4};"
                :: "r"(aLo + off), "r"(lo4[0]), "r"(lo4[1]), "r"(lo4[2]), "r"(lo4[3]));
        }
    };

    const int nchunks = K >> 6;   // 16
    compute_A(0, 0);
    load_B(0, 0);
    CP_COMMIT();

    for (int c = 0; c < nchunks; ++c) {
        if (c + 1 < nchunks) {
            load_B((c + 1) & 1, (c + 1) << 6);
            CP_COMMIT();
            compute_A((c + 1) & 1, c + 1);
            CP_WAIT(1);
        } else {
            CP_WAIT(0);
        }
        __syncthreads();
        mma_chunk(smem_base + (c & 1) * STAGE_BYTES, lane, warp_m, warp_n, acc);
        __syncthreads();
    }

    // ---- epilogue with BN-stats accumulation (reuse stage smem as reduction) ----
    float* red = (float*)sm;           // red[0:128) sum, red[128:256) sumsq
    red[tid & 255] = 0.f;              // 256 threads cover 256 floats
    __syncthreads();

    float colsum[8], colssq[8];
#pragma unroll
    for (int q = 0; q < 8; ++q) { colsum[q] = 0.f; colssq[q] = 0.f; }

#pragma unroll
    for (int mt = 0; mt < 2; ++mt) {
        int r0 = m0 + warp_m * 32 + mt * 16 + (lane >> 2);
        int r1 = r0 + 8;
#pragma unroll
        for (int nt = 0; nt < 4; ++nt) {
            int c = warp_n * 32 + nt * 8 + 2 * (lane & 3);
            float2 bv = *(const float2*)&bias[c];
            if (r0 < M) {
                float vx = acc.a[mt][nt][0] + bv.x, vy = acc.a[mt][nt][1] + bv.y;
                float2 av = *(const float2*)&add[(size_t)r0 * HID + c];
                vx += av.x; vy += av.y;
                float2 o; o.x = vx; o.y = vy;
                *(float2*)&out[(size_t)r0 * HID + c] = o;
                colsum[nt * 2] += vx; colssq[nt * 2] += vx * vx;
                colsum[nt * 2 + 1] += vy; colssq[nt * 2 + 1] += vy * vy;
            }
            if (r1 < M) {
                float vx = acc.a[mt][nt][2] + bv.x, vy = acc.a[mt][nt][3] + bv.y;
                float2 av = *(const float2*)&add[(size_t)r1 * HID + c];
                vx += av.x; vy += av.y;
                float2 o; o.x = vx; o.y = vy;
                *(float2*)&out[(size_t)r1 * HID + c] = o;
                colsum[nt * 2] += vx; colssq[nt * 2] += vx * vx;
                colsum[nt * 2 + 1] += vy; colssq[nt * 2 + 1] += vy * vy;
            }
        }
    }
#pragma unroll
    for (int nt = 0; nt < 4; ++nt) {
#pragma unroll
        for (int k = 0; k < 2; ++k) {
            int c = warp_n * 32 + nt * 8 + 2 * (lane & 3) + k;
            atomicAdd(&red[c], colsum[nt * 2 + k]);
            atomicAdd(&red[128 + c], colssq[nt * 2 + k]);
        }
    }
    __syncthreads();
    if (tid < 256) atomicAdd(&g_stats[tid], red[tid]);
}

// ==================== CSR construction ====================
__global__ void hist_kernel(const int* __restrict__ ei) {
    int e = blockIdx.x * blockDim.x + threadIdx.x;
    if (e < NE) atomicAdd(&g_count[ei[NE + e]], 1);
}

#define SCH 20
__global__ __launch_bounds__(1024) void scan_kernel() {
    int t = threadIdx.x;
    int base = t * SCH;
    int loc[SCH];
    int s = 0;
#pragma unroll
    for (int i = 0; i < SCH; ++i) {
        int n = base + i;
        int v = (n < NN) ? g_count[n] : 0;
        loc[i] = s;
        s += v;
    }
    int lane = t & 31, w = t >> 5;
    int ps = s;
#pragma unroll
    for (int o = 1; o < 32; o <<= 1) {
        int x = __shfl_up_sync(0xffffffffu, ps, o);
        if (lane >= o) ps += x;
    }
    __shared__ int wsum[32];
    if (lane == 31) wsum[w] = ps;
    __syncthreads();
    if (w == 0) {
        int x = wsum[lane];
#pragma unroll
        for (int o = 1; o < 32; o <<= 1) {
            int y = __shfl_up_sync(0xffffffffu, x, o);
            if (lane >= o) x += y;
        }
        wsum[lane] = x;
    }
    __syncthreads();
    int off = ps - s + (w > 0 ? wsum[w - 1] : 0);
#pragma unroll
    for (int i = 0; i < SCH; ++i) {
        int n = base + i;
        if (n < NN) g_rowstart[n] = off + loc[i];
    }
    if (t == 0) g_rowstart[NN] = NE;
}

__global__ void scatter_kernel(const int* __restrict__ ei) {
    int e = blockIdx.x * blockDim.x + threadIdx.x;
    if (e < NE) {
        int dst = ei[NE + e];
        int pos = g_rowstart[dst] + atomicAdd(&g_count[dst], 1);
        g_perm[pos] = e;
    }
}

__global__ void csr_gather_kernel(const int* __restrict__ ei, const float* __restrict__ ea) {
    int j = blockIdx.x * blockDim.x + threadIdx.x;
    if (j < NE) {
        int e = g_perm[j];
        g_esrc[j] = ei[e];
        float4 v;
        v.x = ea[3 * e + 0]; v.y = ea[3 * e + 1]; v.z = ea[3 * e + 2]; v.w = 0.f;
        g_eax[j] = v;
    }
}

// ==================== edge conv (CSR order, warp per dst) ====================
__global__ __launch_bounds__(256) void edge_csr_kernel(
    const float* __restrict__ linw, const float* __restrict__ linb,
    const float* __restrict__ attw, const float* __restrict__ attb_p, int l)
{
    __shared__ float s_w0[HID], s_w1[HID], s_w2[HID], s_lb[HID];
    __shared__ float s_awe[3];
    __shared__ float s_attb;
    int tid = threadIdx.x;
    if (tid < HID) {
        s_w0[tid] = linw[256 * HID + tid];
        s_w1[tid] = linw[257 * HID + tid];
        s_w2[tid] = linw[258 * HID + tid];
        s_lb[tid] = linb[tid];
    }
    if (tid < 3) s_awe[tid] = attw[256 + tid];
    if (tid == 3) s_attb = attb_p[l];
    __syncthreads();

    int node = blockIdx.x * 8 + (tid >> 5);
    int lane = tid & 31;
    int start = g_rowstart[node], end = g_rowstart[node + 1];
    float q1d = g_q1[node];
    float aw0 = s_awe[0], aw1 = s_awe[1], aw2 = s_awe[2], ab = s_attb;

    float a0 = 0.f, a1 = 0.f, a2 = 0.f, a3 = 0.f;
    float sa = 0.f, se0 = 0.f, se1 = 0.f, se2 = 0.f;
    int j = start;
    for (; j + 1 < end; j += 2) {
        int sA = g_esrc[j], sB = g_esrc[j + 1];
        float4 eA = g_eax[j], eB = g_eax[j + 1];
        float qA = g_q2[sA], qB = g_q2[sB];
        float4 vA = *(const float4*)&g_p12[(size_t)(NN + sA) * HID + lane * 4];
        float4 vB = *(const float4*)&g_p12[(size_t)(NN + sB) * HID + lane * 4];
        float lgA = q1d + qA + eA.x * aw0 + eA.y * aw1 + eA.z * aw2 + ab;
        float lgB = q1d + qB + eB.x * aw0 + eB.y * aw1 + eB.z * aw2 + ab;
        float alA = 1.f / (1.f + __expf(-lgA));
        float alB = 1.f / (1.f + __expf(-lgB));
        a0 += alA * vA.x + alB * vB.x;
        a1 += alA * vA.y + alB * vB.y;
        a2 += alA * vA.z + alB * vB.z;
        a3 += alA * vA.w + alB * vB.w;
        sa += alA + alB;
        se0 += alA * eA.x + alB * eB.x;
        se1 += alA * eA.y + alB * eB.y;
        se2 += alA * eA.z + alB * eB.z;
    }
    if (j < end) {
        int src = g_esrc[j];
        float4 e4 = g_eax[j];
        float lg = q1d + g_q2[src] + e4.x * aw0 + e4.y * aw1 + e4.z * aw2 + ab;
        float al = 1.f / (1.f + __expf(-lg));
        float4 v2 = *(const float4*)&g_p12[(size_t)(NN + src) * HID + lane * 4];
        a0 += al * v2.x; a1 += al * v2.y; a2 += al * v2.z; a3 += al * v2.w;
        sa += al; se0 += al * e4.x; se1 += al * e4.y; se2 += al * e4.z;
    }
    int c = lane * 4;
    float4 p1v = *(const float4*)&g_p12[(size_t)node * HID + c];
    float4 r;
    r.x = a0 + se0 * s_w0[c + 0] + se1 * s_w1[c + 0] + se2 * s_w2[c + 0] + sa * (p1v.x + s_lb[c + 0]);
    r.y = a1 + se0 * s_w0[c + 1] + se1 * s_w1[c + 1] + se2 * s_w2[c + 1] + sa * (p1v.y + s_lb[c + 1]);
    r.z = a2 + se0 * s_w0[c + 2] + se1 * s_w1[c + 2] + se2 * s_w2[c + 2] + sa * (p1v.z + s_lb[c + 2]);
    r.w = a3 + se0 * s_w0[c + 3] + se1 * s_w1[c + 3] + se2 * s_w2[c + 3] + sa * (p1v.w + s_lb[c + 3]);
    *(float4*)&g_hconv[(size_t)node * HID + c] = r;
}

// ==================== init / embed ====================
__global__ void pool_init_kernel() {
    int i = blockIdx.x * blockDim.x + threadIdx.x;
    int stride = gridDim.x * blockDim.x;
    for (int j = i; j < NB * HID; j += stride) g_pooled[j] = 0.f;
    if (i == 0) { g_umax = 0u; g_sumexp = 0.f; }
}

// warp per row: h = x@node_w + node_b, and q for layer 0
__global__ __launch_bounds__(256) void node_embed_q_kernel(
    const float* __restrict__ x, const float* __restrict__ w,
    const float* __restrict__ b, const float* __restrict__ attw) {
    int row = (blockIdx.x * blockDim.x + threadIdx.x) >> 5;
    int lane = threadIdx.x & 31;
    if (row >= NN) return;
    int c = lane * 4;
    float4 xv = *(const float4*)&x[row * 4];
    float v[4];
#pragma unroll
    for (int jj = 0; jj < 4; ++jj) {
        int cc = c + jj;
        v[jj] = b[cc] + xv.x * w[cc] + xv.y * w[HID + cc]
              + xv.z * w[2 * HID + cc] + xv.w * w[3 * HID + cc];
    }
    size_t o = (size_t)row * HID + c;
    *(float4*)&g_h[o] = make_float4(v[0], v[1], v[2], v[3]);
    float s1 = v[0] * attw[c] + v[1] * attw[c + 1] + v[2] * attw[c + 2] + v[3] * attw[c + 3];
    float s2 = v[0] * attw[HID + c] + v[1] * attw[HID + c + 1]
             + v[2] * attw[HID + c + 2] + v[3] * attw[HID + c + 3];
#pragma unroll
    for (int o2 = 16; o2 > 0; o2 >>= 1) {
        s1 += __shfl_xor_sync(0xffffffffu, s1, o2);
        s2 += __shfl_xor_sync(0xffffffffu, s2, o2);
    }
    if (lane == 0) { g_q1[row] = s1; g_q2[row] = s2; }
}

// ==================== weight conversions ====================
__global__ void conv_fkw_kernel(const float* __restrict__ fkw) {
    int idx = blockIdx.x * blockDim.x + threadIdx.x;
    if (idx >= DEPTH * HID * HID) return;
    int l = idx >> 14;
    int rem = idx & 16383;
    int n = rem >> 7, i = rem & 127;
    uint32_t hi4[4], lo4[4];
#pragma unroll
    for (int fp = 0; fp < 4; ++fp) {
        float w0 = fkw[(((size_t)l * NFREQ + 2 * fp) * HID + i) * HID + n];
        float w1 = fkw[(((size_t)l * NFREQ + 2 * fp + 1) * HID + i) * HID + n];
        split2(w0, w1, hi4[fp], lo4[fp]);
    }
    size_t o = ((size_t)l * HID + n) * KFK + i * 8;
    *(uint4*)&g_Wfk_hi[o] = make_uint4(hi4[0], hi4[1], hi4[2], hi4[3]);
    *(uint4*)&g_Wfk_lo[o] = make_uint4(lo4[0], lo4[1], lo4[2], lo4[3]);
}

__global__ void conv_linw_kernel(const float* __restrict__ linw) {
    int idx = blockIdx.x * blockDim.x + threadIdx.x;
    if (idx >= DEPTH * 2 * HID * HID) return;
    int l = idx / (2 * HID * HID);
    int rem = idx - l * (2 * HID * HID);
    int p = rem >> 14;
    int nk = rem & 16383;
    int n = nk >> 7, k = nk & 127;
    float w = linw[((size_t)l * 259 + p * 128 + k) * HID + n];
    bf16 hi = __float2bfloat16(w);
    bf16 lo = __float2bfloat16(w - __bfloat162float(hi));
    size_t o = (((size_t)l * 2 + p) * HID + n) * HID + k;
    g_Wlin_hi[o] = hi;
    g_Wlin_lo[o] = lo;
}

// ==================== BN apply + q / pool-logit (warp per row) ====================
__device__ __forceinline__ unsigned float_key(float f) {
    unsigned u = __float_as_uint(f);
    return (u & 0x80000000u) ? ~u : (u | 0x80000000u);
}

__global__ __launch_bounds__(256) void bn_apply_q_kernel(
    float* __restrict__ h, const float* __restrict__ g, const float* __restrict__ b,
    const float* __restrict__ wa, const float* __restrict__ wb,
    const float* __restrict__ pb) {
    int row = (blockIdx.x * blockDim.x + threadIdx.x) >> 5;
    int lane = threadIdx.x & 31;
    if (row >= NN) return;
    int c = lane * 4;
    size_t o = (size_t)row * HID + c;
    float4 hv = *(const float4*)&h[o];
    float v[4] = { hv.x, hv.y, hv.z, hv.w };
    const float invN = 1.f / (float)NN;
#pragma unroll
    for (int jj = 0; jj < 4; ++jj) {
        int cc = c + jj;
        float mu = g_stats[cc] * invN;
        float var = g_stats[HID + cc] * invN - mu * mu;
        float rstd = rsqrtf(var + 1e-5f);
        v[jj] = fmaxf((v[jj] - mu) * rstd * g[cc] + b[cc], 0.f);
    }
    *(float4*)&h[o] = make_float4(v[0], v[1], v[2], v[3]);

    float s1 = v[0] * wa[c] + v[1] * wa[c + 1] + v[2] * wa[c + 2] + v[3] * wa[c + 3];
    if (wb) {
        float s2 = v[0] * wb[c] + v[1] * wb[c + 1] + v[2] * wb[c + 2] + v[3] * wb[c + 3];
#pragma unroll
        for (int o2 = 16; o2 > 0; o2 >>= 1) {
            s1 += __shfl_xor_sync(0xffffffffu, s1, o2);
            s2 += __shfl_xor_sync(0xffffffffu, s2, o2);
        }
        if (lane == 0) { g_q1[row] = s1; g_q2[row] = s2; }
    } else {
#pragma unroll
        for (int o2 = 16; o2 > 0; o2 >>= 1)
            s1 += __shfl_xor_sync(0xffffffffu, s1, o2);
        if (lane == 0) {
            s1 += pb[0];
            g_logits[row] = s1;
            atomicMax(&g_umax, float_key(s1));
        }
    }
}

// ==================== attention pooling tail ====================
__global__ void pool_sumexp_kernel() {
    unsigned k = g_umax;
    float maxv = (k & 0x80000000u) ? __uint_as_float(k ^ 0x80000000u)
                                   : __uint_as_float(~k);
    int i = blockIdx.x * blockDim.x + threadIdx.x;
    int stride = gridDim.x * blockDim.x;
    float local = 0.f;
    for (; i < NN; i += stride) local += __expf(g_logits[i] - maxv);
#pragma unroll
    for (int o = 16; o > 0; o >>= 1) local += __shfl_xor_sync(0xffffffffu, local, o);
    __shared__ float ws[8];
    int lane = threadIdx.x & 31, wid = threadIdx.x >> 5;
    if (lane == 0) ws[wid] = local;
    __syncthreads();
    if (wid == 0) {
        float v = (lane < (blockDim.x >> 5)) ? ws[lane] : 0.f;
#pragma unroll
        for (int o = 16; o > 0; o >>= 1) v += __shfl_xor_sync(0xffffffffu, v, o);
        if (lane == 0) atomicAdd(&g_sumexp, v);
    }
}

__global__ void pool_scatter_kernel(const float* __restrict__ h,
                                    const int* __restrict__ batch) {
    int gwarp = (blockIdx.x * blockDim.x + threadIdx.x) >> 5;
    int lane = threadIdx.x & 31;
    if (gwarp >= NN) return;
    unsigned k = g_umax;
    float maxv = (k & 0x80000000u) ? __uint_as_float(k ^ 0x80000000u)
                                   : __uint_as_float(~k);
    float w = __expf(g_logits[gwarp] - maxv) / g_sumexp;
    int b = batch[gwarp];
    int c = lane * 4;
    float4 hv = *(const float4*)&h[(size_t)gwarp * HID + c];
    float* outp = &g_pooled[b * HID + c];
    atomicAdd(outp + 0, w * hv.x);
    atomicAdd(outp + 1, w * hv.y);
    atomicAdd(outp + 2, w * hv.z);
    atomicAdd(outp + 3, w * hv.w);
}

// ==================== heads ====================
__global__ __launch_bounds__(128) void head_kernel(
    const float* __restrict__ sg_table, const int* __restrict__ sgidx,
    const float* __restrict__ hw1, const float* __restrict__ hb1,
    const float* __restrict__ w2e, const float* __restrict__ b2e,
    const float* __restrict__ w2s, const float* __restrict__ b2s,
    const float* __restrict__ w2c, const float* __restrict__ b2c,
    const float* __restrict__ w2m, const float* __restrict__ b2m,
    float* __restrict__ out)
{
    int b = blockIdx.x;
    int t = threadIdx.x;
    __shared__ float comb[2 * HID];
    __shared__ float z[HID];
    comb[t] = g_pooled[b * HID + t];
    comb[HID + t] = sg_table[sgidx[b] * HID + t];
    __syncthreads();

    const float* w2arr[4] = { w2e, w2s, w2c, w2m };
    const float* b2arr[4] = { b2e, b2s, b2c, b2m };
    const int od[4] = { 1, 3, 7, 3 };
    const int off[4] = { 0, NB * 1, NB * 4, NB * 11 };

    for (int i = 0; i < 4; ++i) {
        float accz = hb1[i * HID + t];
        const float* W = hw1 + (size_t)i * 2 * HID * HID;
#pragma unroll 8
        for (int j = 0; j < 2 * HID; ++j) accz += comb[j] * W[j * HID + t];
        z[t] = fmaxf(accz, 0.f);
        __syncthreads();
        if (t < od[i]) {
            const float* w2 = w2arr[i];
            float acc = b2arr[i][t];
            for (int j = 0; j < HID; ++j) acc += z[j] * w2[j * od[i] + t];
            out[off[i] + b * od[i] + t] = acc;
        }
        __syncthreads();
    }
}

// ==================== host ====================
extern "C" void kernel_launch(void* const* d_in, const int* in_sizes, int n_in,
                              void* d_out, int out_size) {
    const float* x        = (const float*)d_in[0];
    const int*   ei       = (const int*)d_in[1];
    const float* ea       = (const float*)d_in[2];
    const int*   batch    = (const int*)d_in[3];
    const int*   sgidx    = (const int*)d_in[4];
    const float* node_w   = (const float*)d_in[5];
    const float* node_b   = (const float*)d_in[6];
    const float* sg_table = (const float*)d_in[7];
    const float* lin_w    = (const float*)d_in[8];
    const float* lin_b    = (const float*)d_in[9];
    const float* att_w    = (const float*)d_in[10];
    const float* att_b    = (const float*)d_in[11];
    const float* fk_w     = (const float*)d_in[12];
    const float* fk_b     = (const float*)d_in[13];
    const float* bn_g     = (const float*)d_in[14];
    const float* bn_b     = (const float*)d_in[15];
    const float* pool_w   = (const float*)d_in[16];
    const float* pool_b   = (const float*)d_in[17];
    const float* head_w1  = (const float*)d_in[18];
    const float* head_b1  = (const float*)d_in[19];
    const float* w2e = (const float*)d_in[20];
    const float* b2e = (const float*)d_in[21];
    const float* w2s = (const float*)d_in[22];
    const float* b2s = (const float*)d_in[23];
    const float* w2c = (const float*)d_in[24];
    const float* b2c = (const float*)d_in[25];
    const float* w2m = (const float*)d_in[26];
    const float* b2m = (const float*)d_in[27];
    float* out = (float*)d_out;

    cudaFuncSetAttribute(mma_gemm2_kernel, cudaFuncAttributeMaxDynamicSharedMemorySize,
                         GEMM_SMEM);
    cudaFuncSetAttribute(fk_gemm_kernel, cudaFuncAttributeMaxDynamicSharedMemorySize,
                         GEMM_SMEM);

    float *p_h, *p_hconv, *p_stats, *p_p12;
    bf16 *p_Wfk_hi, *p_Wfk_lo, *p_Wlin_hi, *p_Wlin_lo;
    int *p_count;
    cudaGetSymbolAddress((void**)&p_h, g_h);
    cudaGetSymbolAddress((void**)&p_hconv, g_hconv);
    cudaGetSymbolAddress((void**)&p_stats, g_stats);
    cudaGetSymbolAddress((void**)&p_Wfk_hi, g_Wfk_hi);
    cudaGetSymbolAddress((void**)&p_Wfk_lo, g_Wfk_lo);
    cudaGetSymbolAddress((void**)&p_Wlin_hi, g_Wlin_hi);
    cudaGetSymbolAddress((void**)&p_Wlin_lo, g_Wlin_lo);
    cudaGetSymbolAddress((void**)&p_count, g_count);
    cudaGetSymbolAddress((void**)&p_p12, g_p12);

    const int warp_blocks = (NN + 7) / 8;             // 2500

    // CSR construction + payload gather (edge_index is layer-invariant)
    cudaMemsetAsync(p_count, 0, NN * sizeof(int), 0);
    hist_kernel<<<(NE + 255) / 256, 256>>>(ei);
    scan_kernel<<<1, 1024>>>();
    cudaMemsetAsync(p_count, 0, NN * sizeof(int), 0);
    scatter_kernel<<<(NE + 255) / 256, 256>>>(ei);
    csr_gather_kernel<<<(NE + 255) / 256, 256>>>(ei, ea);

    conv_fkw_kernel<<<(DEPTH * HID * HID + 255) / 256, 256>>>(fk_w);
    conv_linw_kernel<<<(DEPTH * 2 * HID * HID + 255) / 256, 256>>>(lin_w);

    pool_init_kernel<<<32, 256>>>();
    node_embed_q_kernel<<<warp_blocks, 256>>>(x, node_w, node_b, att_w);

    for (int l = 0; l < DEPTH; ++l) {
        const float* lw = lin_w + (size_t)l * 259 * HID;
        const float* lb = lin_b + (size_t)l * HID;
        const float* aw = att_w + (size_t)l * 259;
        const bf16* Wlin_hi = p_Wlin_hi + (size_t)l * 2 * HID * HID;
        const bf16* Wlin_lo = p_Wlin_lo + (size_t)l * 2 * HID * HID;

        mma_gemm2_kernel<<<2 * TILE_BLOCKS, 256, GEMM_SMEM>>>(
            p_h, Wlin_hi, Wlin_lo, p_p12, NN);
        edge_csr_kernel<<<warp_blocks, 256>>>(lw, lb, aw, att_b, l);
        cudaMemsetAsync(p_stats, 0, 2 * HID * sizeof(float), 0);
        // FK GEMM: Fourier features in-kernel, out aliases h, BN stats in epilogue
        fk_gemm_kernel<<<TILE_BLOCKS, 256, GEMM_SMEM>>>(
            p_h, p_Wfk_hi + (size_t)l * HID * KFK, p_Wfk_lo + (size_t)l * HID * KFK,
            fk_b + (size_t)l * HID, p_hconv, p_h, NN);
        if (l < DEPTH - 1) {
            const float* awn = att_w + (size_t)(l + 1) * 259;
            bn_apply_q_kernel<<<warp_blocks, 256>>>(
                p_h, bn_g + (size_t)l * HID, bn_b + (size_t)l * HID,
                awn, awn + HID, nullptr);
        } else {
            bn_apply_q_kernel<<<warp_blocks, 256>>>(
                p_h, bn_g + (size_t)l * HID, bn_b + (size_t)l * HID,
                pool_w, nullptr, pool_b);
        }
    }

    pool_sumexp_kernel<<<80, 256>>>();
    pool_scatter_kernel<<<warp_blocks, 256>>>(p_h, batch);

    head_kernel<<<NB, 128>>>(sg_table, sgidx, head_w1, head_b1,
                             w2e, b2e, w2s, b2s, w2c, b2c, w2m, b2m, out);
}